// round 1
// baseline (speedup 1.0000x reference)
#include <cuda_runtime.h>

#define N_NODES 50000
#define IN_DIM  512
#define HID_DIM 256
#define OUT_DIM 64

// ---- scratch (no allocations allowed) ----
__device__ float g_deg[N_NODES];
__device__ float g_dinv[N_NODES];
__device__ float g_h1[(size_t)N_NODES * HID_DIM];    // x @ W1
__device__ float g_agg1[(size_t)N_NODES * HID_DIM];  // aggregated layer-1
__device__ float g_h2[(size_t)N_NODES * OUT_DIM];    // agg1 @ W2

// ------------------------------------------------------------------
// zero: deg, agg1, and d_out (used as agg2 accumulator)
// ------------------------------------------------------------------
__global__ void zero_kernel(float* __restrict__ out) {
    const long long total = (long long)N_NODES * HID_DIM;
    const long long outn  = (long long)N_NODES * OUT_DIM;
    for (long long i = (long long)blockIdx.x * blockDim.x + threadIdx.x;
         i < total; i += (long long)gridDim.x * blockDim.x) {
        g_agg1[i] = 0.f;
        if (i < N_NODES) g_deg[i] = 0.f;
        if (i < outn)    out[i] = 0.f;
    }
}

// ------------------------------------------------------------------
// degree (on dst, self-loop added in dinv)
// ------------------------------------------------------------------
__global__ void deg_kernel(const int* __restrict__ dst, int E) {
    int i = blockIdx.x * blockDim.x + threadIdx.x;
    if (i < E) atomicAdd(&g_deg[dst[i]], 1.f);
}

__global__ void dinv_kernel() {
    int i = blockIdx.x * blockDim.x + threadIdx.x;
    if (i < N_NODES) g_dinv[i] = rsqrtf(g_deg[i] + 1.f);
}

// ------------------------------------------------------------------
// SGEMM: C[M,N] = A[M,K] @ B[K,N], fp32.
// 64x64 tile, BK=16, 256 threads, 4x4 per thread, float4 smem loads.
// Requires N % 64 == 0, K % 16 == 0 (true for both GEMMs here).
// ------------------------------------------------------------------
__global__ void sgemm64(const float* __restrict__ A, const float* __restrict__ B,
                        float* __restrict__ C, int M, int N, int K) {
    __shared__ float As[16][64];   // [k][m] (transposed)
    __shared__ float Bs[16][64];   // [k][n]

    const int tid = threadIdx.x;
    const int tx = tid & 15;        // 0..15 -> N
    const int ty = tid >> 4;        // 0..15 -> M
    const int row0 = blockIdx.y * 64;
    const int col0 = blockIdx.x * 64;

    // A-tile load mapping: 64 rows x 16 cols -> one float4 per thread
    const int ar = tid >> 2;            // 0..63
    const int ac = (tid & 3) * 4;       // 0,4,8,12
    // B-tile load mapping: 16 rows x 64 cols -> one float4 per thread
    const int br = tid >> 4;            // 0..15
    const int bc = (tid & 15) * 4;      // 0..60

    float acc[4][4] = {};

    for (int k0 = 0; k0 < K; k0 += 16) {
        float4 av = make_float4(0.f, 0.f, 0.f, 0.f);
        int gm = row0 + ar;
        if (gm < M) av = *(const float4*)(A + (size_t)gm * K + k0 + ac);
        As[ac + 0][ar] = av.x;
        As[ac + 1][ar] = av.y;
        As[ac + 2][ar] = av.z;
        As[ac + 3][ar] = av.w;

        float4 bv = *(const float4*)(B + (size_t)(k0 + br) * N + col0 + bc);
        *(float4*)&Bs[br][bc] = bv;

        __syncthreads();
#pragma unroll
        for (int k = 0; k < 16; k++) {
            float4 a = *(const float4*)&As[k][ty * 4];
            float4 b = *(const float4*)&Bs[k][tx * 4];
            float am[4] = {a.x, a.y, a.z, a.w};
            float bn[4] = {b.x, b.y, b.z, b.w};
#pragma unroll
            for (int i = 0; i < 4; i++)
#pragma unroll
                for (int j = 0; j < 4; j++)
                    acc[i][j] += am[i] * bn[j];
        }
        __syncthreads();
    }

#pragma unroll
    for (int i = 0; i < 4; i++) {
        int gm = row0 + ty * 4 + i;
        if (gm < M) {
            float4 v = make_float4(acc[i][0], acc[i][1], acc[i][2], acc[i][3]);
            *(float4*)(C + (size_t)gm * N + col0 + tx * 4) = v;
        }
    }
}

// ------------------------------------------------------------------
// Edge aggregation, F=256: one warp per edge, float4 gather + scalar atomics
// ------------------------------------------------------------------
__global__ void agg_kernel256(const float* __restrict__ h, float* __restrict__ out,
                              const int* __restrict__ src, const int* __restrict__ dst,
                              int E) {
    int e = (blockIdx.x * blockDim.x + threadIdx.x) >> 5;
    int lane = threadIdx.x & 31;
    if (e >= E) return;
    int s = __ldg(src + e);
    int d = __ldg(dst + e);
    float norm = g_dinv[s] * g_dinv[d];
    const float4* hr = (const float4*)(h + (size_t)s * HID_DIM);
    float* orow = out + (size_t)d * HID_DIM;
#pragma unroll
    for (int f4 = lane; f4 < HID_DIM / 4; f4 += 32) {
        float4 v = hr[f4];
        atomicAdd(orow + f4 * 4 + 0, v.x * norm);
        atomicAdd(orow + f4 * 4 + 1, v.y * norm);
        atomicAdd(orow + f4 * 4 + 2, v.z * norm);
        atomicAdd(orow + f4 * 4 + 3, v.w * norm);
    }
}

// F=64: 16 threads per edge (one float4 each)
__global__ void agg_kernel64(const float* __restrict__ h, float* __restrict__ out,
                             const int* __restrict__ src, const int* __restrict__ dst,
                             int E) {
    long long t = (long long)blockIdx.x * blockDim.x + threadIdx.x;
    int e = (int)(t >> 4);
    int q = (int)(t & 15);
    if (e >= E) return;
    int s = __ldg(src + e);
    int d = __ldg(dst + e);
    float norm = g_dinv[s] * g_dinv[d];
    float4 v = ((const float4*)(h + (size_t)s * OUT_DIM))[q];
    float* orow = out + (size_t)d * OUT_DIM + q * 4;
    atomicAdd(orow + 0, v.x * norm);
    atomicAdd(orow + 1, v.y * norm);
    atomicAdd(orow + 2, v.z * norm);
    atomicAdd(orow + 3, v.w * norm);
}

// ------------------------------------------------------------------
// layer-1 epilogue: agg1 = relu(agg1 + h1 * dinv^2 + b1)
// ------------------------------------------------------------------
__global__ void finalize_relu(const float* __restrict__ b1) {
    long long i = (long long)blockIdx.x * blockDim.x + threadIdx.x;
    if (i >= (long long)N_NODES * HID_DIM) return;
    int row = (int)(i >> 8);       // /256
    int f = (int)(i & 255);
    float di = g_dinv[row];
    float v = g_agg1[i] + g_h1[i] * di * di + b1[f];
    g_agg1[i] = fmaxf(v, 0.f);
}

// ------------------------------------------------------------------
// layer-2 epilogue: out = log_softmax(out + h2 * dinv^2 + b2), warp per row
// ------------------------------------------------------------------
__global__ void finalize_softmax(float* __restrict__ out, const float* __restrict__ b2) {
    int row = (blockIdx.x * blockDim.x + threadIdx.x) >> 5;
    int lane = threadIdx.x & 31;
    if (row >= N_NODES) return;
    float di = g_dinv[row];
    float self = di * di;
    size_t base = (size_t)row * OUT_DIM;
    float v0 = out[base + lane]      + g_h2[base + lane]      * self + b2[lane];
    float v1 = out[base + 32 + lane] + g_h2[base + 32 + lane] * self + b2[32 + lane];

    float m = fmaxf(v0, v1);
#pragma unroll
    for (int o = 16; o; o >>= 1) m = fmaxf(m, __shfl_xor_sync(0xFFFFFFFFu, m, o));
    float s = expf(v0 - m) + expf(v1 - m);
#pragma unroll
    for (int o = 16; o; o >>= 1) s += __shfl_xor_sync(0xFFFFFFFFu, s, o);
    float ls = m + logf(s);

    out[base + lane]      = v0 - ls;
    out[base + 32 + lane] = v1 - ls;
}

// ------------------------------------------------------------------
extern "C" void kernel_launch(void* const* d_in, const int* in_sizes, int n_in,
                              void* d_out, int out_size) {
    const float* x  = (const float*)d_in[0];
    const float* W1 = (const float*)d_in[1];
    const float* b1 = (const float*)d_in[2];
    const float* W2 = (const float*)d_in[3];
    const float* b2 = (const float*)d_in[4];
    const int* ei   = (const int*)d_in[5];
    const int E = in_sizes[5] / 2;
    const int* src = ei;
    const int* dst = ei + E;
    float* out = (float*)d_out;

    float *h1, *agg1, *h2;
    cudaGetSymbolAddress((void**)&h1,   g_h1);
    cudaGetSymbolAddress((void**)&agg1, g_agg1);
    cudaGetSymbolAddress((void**)&h2,   g_h2);

    // 1. zero accumulators
    zero_kernel<<<8192, 256>>>(out);
    // 2. degree + dinv
    deg_kernel<<<(E + 255) / 256, 256>>>(dst, E);
    dinv_kernel<<<(N_NODES + 255) / 256, 256>>>();
    // 3. h1 = x @ W1
    sgemm64<<<dim3(HID_DIM / 64, (N_NODES + 63) / 64), 256>>>(x, W1, h1, N_NODES, HID_DIM, IN_DIM);
    // 4. agg1 += h1[src] * norm  (scatter)
    {
        long long threads = (long long)E * 32;
        agg_kernel256<<<(unsigned)((threads + 255) / 256), 256>>>(h1, agg1, src, dst, E);
    }
    // 5. relu(agg1 + self + b1)
    finalize_relu<<<(N_NODES * HID_DIM + 255) / 256, 256>>>(b1);
    // 6. h2 = agg1 @ W2
    sgemm64<<<dim3(OUT_DIM / 64, (N_NODES + 63) / 64), 256>>>(agg1, W2, h2, N_NODES, OUT_DIM, HID_DIM);
    // 7. out += h2[src] * norm (scatter)
    {
        long long threads = (long long)E * 16;
        agg_kernel64<<<(unsigned)((threads + 255) / 256), 256>>>(h2, out, src, dst, E);
    }
    // 8. log_softmax(out + self + b2)
    finalize_softmax<<<((long long)N_NODES * 32 + 255) / 256, 256>>>(out, b2);
}

// round 2
// speedup vs baseline: 2.1278x; 2.1278x over previous
#include <cuda_runtime.h>

#define N_NODES 50000
#define IN_DIM  512
#define HID_DIM 256
#define OUT_DIM 64
#define EDGE_CAP 1700000

// ---- scratch (no allocations allowed) ----
__device__ int   g_cnt[N_NODES];          // per-dst edge counts
__device__ int   g_rowptr[N_NODES + 1];   // CSR row pointers (by dst)
__device__ int   g_fill[N_NODES];         // fill cursors
__device__ int   g_esrc[EDGE_CAP];        // src node id per CSR slot
__device__ float g_dinv[N_NODES];
__device__ float g_h1[(size_t)N_NODES * HID_DIM];
__device__ float g_a1[(size_t)N_NODES * HID_DIM];
__device__ float g_h2[(size_t)N_NODES * OUT_DIM];

// ------------------------------------------------------------------
// CSR build
// ------------------------------------------------------------------
__global__ void zero_cnt_kernel() {
    int i = blockIdx.x * blockDim.x + threadIdx.x;
    if (i < N_NODES) g_cnt[i] = 0;
}

__global__ void count_kernel(const int* __restrict__ dst, int E) {
    int i = blockIdx.x * blockDim.x + threadIdx.x;
    if (i < E) atomicAdd(&g_cnt[dst[i]], 1);
}

__global__ void dinv_kernel() {
    int i = blockIdx.x * blockDim.x + threadIdx.x;
    if (i < N_NODES) g_dinv[i] = rsqrtf((float)g_cnt[i] + 1.0f);
}

// single-block exclusive scan over g_cnt -> g_rowptr / g_fill
__global__ void scan_kernel() {
    __shared__ int s[1024];
    const int t = threadIdx.x;
    const int C = (N_NODES + 1023) / 1024;   // 49
    const int base = t * C;

    int sum = 0;
    for (int i = 0; i < C; i++) {
        int idx = base + i;
        if (idx < N_NODES) sum += g_cnt[idx];
    }
    s[t] = sum;
    __syncthreads();
    // inclusive scan over 1024 partials
    for (int off = 1; off < 1024; off <<= 1) {
        int v = 0;
        if (t >= off) v = s[t - off];
        __syncthreads();
        if (t >= off) s[t] += v;
        __syncthreads();
    }
    int run = (t == 0) ? 0 : s[t - 1];
    for (int i = 0; i < C; i++) {
        int idx = base + i;
        if (idx < N_NODES) {
            g_rowptr[idx] = run;
            g_fill[idx]   = run;
            run += g_cnt[idx];
        }
    }
    if (t == 1023) g_rowptr[N_NODES] = s[1023];
}

__global__ void fill_kernel(const int* __restrict__ src, const int* __restrict__ dst, int E) {
    int i = blockIdx.x * blockDim.x + threadIdx.x;
    if (i < E) {
        int d = dst[i];
        int pos = atomicAdd(&g_fill[d], 1);
        g_esrc[pos] = src[i];
    }
}

// ------------------------------------------------------------------
// SGEMM 128x128 tile, BK=8, 256 threads, 8x8 microtile (for GEMM1)
// N must be divisible by 128; M guarded; K divisible by 8.
// ------------------------------------------------------------------
__global__ void __launch_bounds__(256, 2)
sgemm128(const float* __restrict__ A, const float* __restrict__ B,
         float* __restrict__ C, int M, int N, int K) {
    __shared__ float As[8][128];
    __shared__ float Bs[8][128];

    const int tid = threadIdx.x;
    const int row0 = blockIdx.y * 128;
    const int col0 = blockIdx.x * 128;

    const int ar = tid >> 1;            // 0..127
    const int ac = (tid & 1) * 4;       // 0 or 4
    const int br = tid >> 5;            // 0..7
    const int bc = (tid & 31) * 4;      // 0..124

    const int tx = tid & 15;            // col microtile
    const int ty = tid >> 4;            // row microtile

    float acc[8][8] = {};

    for (int k0 = 0; k0 < K; k0 += 8) {
        float4 av = make_float4(0.f, 0.f, 0.f, 0.f);
        int gm = row0 + ar;
        if (gm < M) av = *(const float4*)(A + (size_t)gm * K + k0 + ac);
        As[ac + 0][ar] = av.x;
        As[ac + 1][ar] = av.y;
        As[ac + 2][ar] = av.z;
        As[ac + 3][ar] = av.w;

        float4 bv = *(const float4*)(B + (size_t)(k0 + br) * N + col0 + bc);
        *(float4*)&Bs[br][bc] = bv;

        __syncthreads();
#pragma unroll
        for (int k = 0; k < 8; k++) {
            float a[8], b[8];
            *(float4*)(a)     = *(const float4*)&As[k][ty * 8];
            *(float4*)(a + 4) = *(const float4*)&As[k][ty * 8 + 4];
            *(float4*)(b)     = *(const float4*)&Bs[k][tx * 8];
            *(float4*)(b + 4) = *(const float4*)&Bs[k][tx * 8 + 4];
#pragma unroll
            for (int i = 0; i < 8; i++)
#pragma unroll
                for (int j = 0; j < 8; j++)
                    acc[i][j] += a[i] * b[j];
        }
        __syncthreads();
    }

#pragma unroll
    for (int i = 0; i < 8; i++) {
        int gm = row0 + ty * 8 + i;
        if (gm < M) {
            float* cr = C + (size_t)gm * N + col0 + tx * 8;
            *(float4*)(cr)     = make_float4(acc[i][0], acc[i][1], acc[i][2], acc[i][3]);
            *(float4*)(cr + 4) = make_float4(acc[i][4], acc[i][5], acc[i][6], acc[i][7]);
        }
    }
}

// ------------------------------------------------------------------
// SGEMM 64x64 tile (for GEMM2, N=64)
// ------------------------------------------------------------------
__global__ void sgemm64(const float* __restrict__ A, const float* __restrict__ B,
                        float* __restrict__ C, int M, int N, int K) {
    __shared__ float As[16][64];
    __shared__ float Bs[16][64];

    const int tid = threadIdx.x;
    const int tx = tid & 15;
    const int ty = tid >> 4;
    const int row0 = blockIdx.y * 64;
    const int col0 = blockIdx.x * 64;

    const int ar = tid >> 2;
    const int ac = (tid & 3) * 4;
    const int br = tid >> 4;
    const int bc = (tid & 15) * 4;

    float acc[4][4] = {};

    for (int k0 = 0; k0 < K; k0 += 16) {
        float4 av = make_float4(0.f, 0.f, 0.f, 0.f);
        int gm = row0 + ar;
        if (gm < M) av = *(const float4*)(A + (size_t)gm * K + k0 + ac);
        As[ac + 0][ar] = av.x;
        As[ac + 1][ar] = av.y;
        As[ac + 2][ar] = av.z;
        As[ac + 3][ar] = av.w;

        float4 bv = *(const float4*)(B + (size_t)(k0 + br) * N + col0 + bc);
        *(float4*)&Bs[br][bc] = bv;

        __syncthreads();
#pragma unroll
        for (int k = 0; k < 16; k++) {
            float4 a = *(const float4*)&As[k][ty * 4];
            float4 b = *(const float4*)&Bs[k][tx * 4];
            float am[4] = {a.x, a.y, a.z, a.w};
            float bn[4] = {b.x, b.y, b.z, b.w};
#pragma unroll
            for (int i = 0; i < 4; i++)
#pragma unroll
                for (int j = 0; j < 4; j++)
                    acc[i][j] += am[i] * bn[j];
        }
        __syncthreads();
    }

#pragma unroll
    for (int i = 0; i < 4; i++) {
        int gm = row0 + ty * 4 + i;
        if (gm < M) {
            *(float4*)(C + (size_t)gm * N + col0 + tx * 4) =
                make_float4(acc[i][0], acc[i][1], acc[i][2], acc[i][3]);
        }
    }
}

// ------------------------------------------------------------------
// Layer-1 aggregation (CSR gather, no atomics), fused self+bias+relu:
//   a1[d,f] = relu( dinv[d] * sum_e dinv[src]*h1[src,f] + dinv[d]^2*h1[d,f] + b1[f] )
// One block of 256 threads per destination node; thread = feature.
// ------------------------------------------------------------------
__global__ void spmm_relu256(const float* __restrict__ h, float* __restrict__ out,
                             const float* __restrict__ b1) {
    const int d = blockIdx.x;
    const int f = threadIdx.x;
    const int beg = g_rowptr[d];
    const int end = g_rowptr[d + 1];

    float acc = 0.f;
    int e = beg;
    for (; e + 1 < end; e += 2) {
        int s0 = __ldg(&g_esrc[e]);
        int s1 = __ldg(&g_esrc[e + 1]);
        float w0 = __ldg(&g_dinv[s0]);
        float w1 = __ldg(&g_dinv[s1]);
        float v0 = __ldg(h + (size_t)s0 * HID_DIM + f);
        float v1 = __ldg(h + (size_t)s1 * HID_DIM + f);
        acc += w0 * v0 + w1 * v1;
    }
    if (e < end) {
        int s0 = __ldg(&g_esrc[e]);
        acc += __ldg(&g_dinv[s0]) * __ldg(h + (size_t)s0 * HID_DIM + f);
    }

    float di = g_dinv[d];
    float self = __ldg(h + (size_t)d * HID_DIM + f);
    float v = di * acc + di * di * self + b1[f];
    out[(size_t)d * HID_DIM + f] = fmaxf(v, 0.f);
}

// ------------------------------------------------------------------
// Layer-2 aggregation + bias + log_softmax, warp per destination node.
// Lane handles features lane and lane+32.
// ------------------------------------------------------------------
__global__ void spmm_softmax64(const float* __restrict__ h, float* __restrict__ out,
                               const float* __restrict__ b2) {
    const int node = (blockIdx.x * blockDim.x + threadIdx.x) >> 5;
    const int lane = threadIdx.x & 31;
    if (node >= N_NODES) return;

    const int beg = g_rowptr[node];
    const int end = g_rowptr[node + 1];

    float a0 = 0.f, a1 = 0.f;
    int e = beg;
    for (; e + 1 < end; e += 2) {
        int s0 = __ldg(&g_esrc[e]);
        int s1 = __ldg(&g_esrc[e + 1]);
        float w0 = __ldg(&g_dinv[s0]);
        float w1 = __ldg(&g_dinv[s1]);
        const float* r0 = h + (size_t)s0 * OUT_DIM;
        const float* r1 = h + (size_t)s1 * OUT_DIM;
        a0 += w0 * __ldg(r0 + lane)      + w1 * __ldg(r1 + lane);
        a1 += w0 * __ldg(r0 + 32 + lane) + w1 * __ldg(r1 + 32 + lane);
    }
    if (e < end) {
        int s0 = __ldg(&g_esrc[e]);
        float w0 = __ldg(&g_dinv[s0]);
        const float* r0 = h + (size_t)s0 * OUT_DIM;
        a0 += w0 * __ldg(r0 + lane);
        a1 += w0 * __ldg(r0 + 32 + lane);
    }

    float di = g_dinv[node];
    float self = di * di;
    const float* hr = h + (size_t)node * OUT_DIM;
    float v0 = di * a0 + self * __ldg(hr + lane)      + b2[lane];
    float v1 = di * a1 + self * __ldg(hr + 32 + lane) + b2[32 + lane];

    float m = fmaxf(v0, v1);
#pragma unroll
    for (int o = 16; o; o >>= 1) m = fmaxf(m, __shfl_xor_sync(0xFFFFFFFFu, m, o));
    float s = expf(v0 - m) + expf(v1 - m);
#pragma unroll
    for (int o = 16; o; o >>= 1) s += __shfl_xor_sync(0xFFFFFFFFu, s, o);
    float ls = m + logf(s);

    out[(size_t)node * OUT_DIM + lane]      = v0 - ls;
    out[(size_t)node * OUT_DIM + 32 + lane] = v1 - ls;
}

// ------------------------------------------------------------------
extern "C" void kernel_launch(void* const* d_in, const int* in_sizes, int n_in,
                              void* d_out, int out_size) {
    const float* x  = (const float*)d_in[0];
    const float* W1 = (const float*)d_in[1];
    const float* b1 = (const float*)d_in[2];
    const float* W2 = (const float*)d_in[3];
    const float* b2 = (const float*)d_in[4];
    const int* ei   = (const int*)d_in[5];
    const int E = in_sizes[5] / 2;
    const int* src = ei;
    const int* dst = ei + E;
    float* out = (float*)d_out;

    float *h1, *a1, *h2;
    cudaGetSymbolAddress((void**)&h1, g_h1);
    cudaGetSymbolAddress((void**)&a1, g_a1);
    cudaGetSymbolAddress((void**)&h2, g_h2);

    const int TB = 256;

    // ---- CSR build (by dst) ----
    zero_cnt_kernel<<<(N_NODES + TB - 1) / TB, TB>>>();
    count_kernel<<<(E + TB - 1) / TB, TB>>>(dst, E);
    dinv_kernel<<<(N_NODES + TB - 1) / TB, TB>>>();
    scan_kernel<<<1, 1024>>>();
    fill_kernel<<<(E + TB - 1) / TB, TB>>>(src, dst, E);

    // ---- layer 1 ----
    sgemm128<<<dim3(HID_DIM / 128, (N_NODES + 127) / 128), 256>>>(x, W1, h1, N_NODES, HID_DIM, IN_DIM);
    spmm_relu256<<<N_NODES, HID_DIM>>>(h1, a1, b1);

    // ---- layer 2 ----
    sgemm64<<<dim3(OUT_DIM / 64, (N_NODES + 63) / 64), 256>>>(a1, W2, h2, N_NODES, OUT_DIM, HID_DIM);
    spmm_softmax64<<<(N_NODES * 32 + TB - 1) / TB, TB>>>(h2, out, b2);
}

// round 4
// speedup vs baseline: 2.5343x; 1.1910x over previous
#include <cuda_runtime.h>

#define N_NODES 50000
#define IN_DIM  512
#define HID_DIM 256
#define OUT_DIM 64
#define EDGE_CAP 1700000

#define SCAN_TB 256
#define SCAN_NBLK ((N_NODES + SCAN_TB - 1) / SCAN_TB)   // 196

// ---- scratch (no allocations allowed) ----
__device__ int   g_cnt[N_NODES];
__device__ int   g_rowptr[N_NODES + 1];
__device__ int   g_fill[N_NODES];
__device__ int   g_esrc[EDGE_CAP];
__device__ int   g_part[SCAN_NBLK];
__device__ float g_dinv[N_NODES];
__device__ float g_h1[(size_t)N_NODES * HID_DIM];
__device__ float g_a1[(size_t)N_NODES * HID_DIM];
__device__ float g_h2[(size_t)N_NODES * OUT_DIM];

// ------------------------------------------------------------------
// CSR build
// ------------------------------------------------------------------
__global__ void zero_cnt_kernel() {
    int i = blockIdx.x * blockDim.x + threadIdx.x;
    if (i < N_NODES) g_cnt[i] = 0;
}

__global__ void count_kernel(const int* __restrict__ dst, int E) {
    int i = blockIdx.x * blockDim.x + threadIdx.x;
    if (i < E) atomicAdd(&g_cnt[dst[i]], 1);
}

__global__ void dinv_kernel() {
    int i = blockIdx.x * blockDim.x + threadIdx.x;
    if (i < N_NODES) g_dinv[i] = rsqrtf((float)g_cnt[i] + 1.0f);
}

// scan stage 1: per-block sums
__global__ void scan1_kernel() {
    __shared__ int s[SCAN_TB];
    int t = threadIdx.x;
    int i = blockIdx.x * SCAN_TB + t;
    int v = (i < N_NODES) ? g_cnt[i] : 0;
    s[t] = v;
    __syncthreads();
    for (int off = SCAN_TB / 2; off > 0; off >>= 1) {
        if (t < off) s[t] += s[t + off];
        __syncthreads();
    }
    if (t == 0) g_part[blockIdx.x] = s[0];
}

// scan stage 2: exclusive scan of 196 partials (one block)
__global__ void scan2_kernel() {
    __shared__ int s[SCAN_TB];
    int t = threadIdx.x;
    int v = (t < SCAN_NBLK) ? g_part[t] : 0;
    s[t] = v;
    __syncthreads();
    for (int off = 1; off < SCAN_TB; off <<= 1) {
        int u = (t >= off) ? s[t - off] : 0;
        __syncthreads();
        s[t] += u;
        __syncthreads();
    }
    if (t < SCAN_NBLK) g_part[t] = s[t] - v;   // exclusive
    if (t == SCAN_TB - 1) g_rowptr[N_NODES] = s[SCAN_TB - 1];
}

// scan stage 3: per-block exclusive scan + offset -> rowptr / fill
__global__ void scan3_kernel() {
    __shared__ int s[SCAN_TB];
    int t = threadIdx.x;
    int i = blockIdx.x * SCAN_TB + t;
    int v = (i < N_NODES) ? g_cnt[i] : 0;
    s[t] = v;
    __syncthreads();
    for (int off = 1; off < SCAN_TB; off <<= 1) {
        int u = (t >= off) ? s[t - off] : 0;
        __syncthreads();
        s[t] += u;
        __syncthreads();
    }
    if (i < N_NODES) {
        int excl = g_part[blockIdx.x] + s[t] - v;
        g_rowptr[i] = excl;
        g_fill[i]   = excl;
    }
}

__global__ void fill_kernel(const int* __restrict__ src, const int* __restrict__ dst, int E) {
    int i = blockIdx.x * blockDim.x + threadIdx.x;
    if (i < E) {
        int d = dst[i];
        int pos = atomicAdd(&g_fill[d], 1);
        g_esrc[pos] = src[i];
    }
}

// ------------------------------------------------------------------
// SGEMM 128x128, BK=8, 256 threads, 8x8 microtile (split 4+4),
// double-buffered smem with register prefetch.
// ------------------------------------------------------------------
__global__ void __launch_bounds__(256, 2)
sgemm128(const float* __restrict__ A, const float* __restrict__ B,
         float* __restrict__ C, int M, int N, int K) {
    __shared__ float As[2][8][128];
    __shared__ float Bs[2][8][128];

    const int tid = threadIdx.x;
    const int row0 = blockIdx.y * 128;
    const int col0 = blockIdx.x * 128;

    const int ar = tid >> 1;            // 0..127
    const int ac = (tid & 1) * 4;       // 0 or 4
    const int br = tid >> 5;            // 0..7
    const int bc = (tid & 31) * 4;      // 0..124

    const int tx = tid & 15;            // col group
    const int ty = tid >> 4;            // row group

    float acc[8][8] = {};

    // initial tile -> buffer 0
    const int gm0 = row0 + ar;
    float4 pa = make_float4(0.f, 0.f, 0.f, 0.f);
    if (gm0 < M) pa = *(const float4*)(A + (size_t)gm0 * K + ac);
    As[0][ac + 0][ar] = pa.x;
    As[0][ac + 1][ar] = pa.y;
    As[0][ac + 2][ar] = pa.z;
    As[0][ac + 3][ar] = pa.w;
    float4 pb = *(const float4*)(B + (size_t)br * N + col0 + bc);
    *(float4*)&Bs[0][br][bc] = pb;
    __syncthreads();

    int buf = 0;
    for (int k0 = 0; k0 < K; k0 += 8) {
        const bool has_next = (k0 + 8) < K;
        if (has_next) {
            pa = make_float4(0.f, 0.f, 0.f, 0.f);
            if (gm0 < M) pa = *(const float4*)(A + (size_t)gm0 * K + k0 + 8 + ac);
            pb = *(const float4*)(B + (size_t)(k0 + 8 + br) * N + col0 + bc);
        }

#pragma unroll
        for (int k = 0; k < 8; k++) {
            float a[8], b[8];
            *(float4*)(a)     = *(const float4*)&As[buf][k][ty * 4];
            *(float4*)(a + 4) = *(const float4*)&As[buf][k][64 + ty * 4];
            *(float4*)(b)     = *(const float4*)&Bs[buf][k][tx * 4];
            *(float4*)(b + 4) = *(const float4*)&Bs[buf][k][64 + tx * 4];
#pragma unroll
            for (int i = 0; i < 8; i++)
#pragma unroll
                for (int j = 0; j < 8; j++)
                    acc[i][j] += a[i] * b[j];
        }

        if (has_next) {
            const int nb = buf ^ 1;
            As[nb][ac + 0][ar] = pa.x;
            As[nb][ac + 1][ar] = pa.y;
            As[nb][ac + 2][ar] = pa.z;
            As[nb][ac + 3][ar] = pa.w;
            *(float4*)&Bs[nb][br][bc] = pb;
            __syncthreads();
            buf = nb;
        }
    }

#pragma unroll
    for (int half = 0; half < 2; half++) {
#pragma unroll
        for (int i = 0; i < 4; i++) {
            int gm = row0 + half * 64 + ty * 4 + i;
            if (gm < M) {
                float* cr = C + (size_t)gm * N + col0;
                *(float4*)(cr + tx * 4) =
                    make_float4(acc[half * 4 + i][0], acc[half * 4 + i][1],
                                acc[half * 4 + i][2], acc[half * 4 + i][3]);
                *(float4*)(cr + 64 + tx * 4) =
                    make_float4(acc[half * 4 + i][4], acc[half * 4 + i][5],
                                acc[half * 4 + i][6], acc[half * 4 + i][7]);
            }
        }
    }
}

// ------------------------------------------------------------------
// SGEMM 64x64 tile (GEMM2, N=64)
// ------------------------------------------------------------------
__global__ void sgemm64(const float* __restrict__ A, const float* __restrict__ B,
                        float* __restrict__ C, int M, int N, int K) {
    __shared__ float As[16][64];
    __shared__ float Bs[16][64];

    const int tid = threadIdx.x;
    const int tx = tid & 15;
    const int ty = tid >> 4;
    const int row0 = blockIdx.y * 64;
    const int col0 = blockIdx.x * 64;

    const int ar = tid >> 2;
    const int ac = (tid & 3) * 4;
    const int br = tid >> 4;
    const int bc = (tid & 15) * 4;

    float acc[4][4] = {};

    for (int k0 = 0; k0 < K; k0 += 16) {
        float4 av = make_float4(0.f, 0.f, 0.f, 0.f);
        int gm = row0 + ar;
        if (gm < M) av = *(const float4*)(A + (size_t)gm * K + k0 + ac);
        As[ac + 0][ar] = av.x;
        As[ac + 1][ar] = av.y;
        As[ac + 2][ar] = av.z;
        As[ac + 3][ar] = av.w;

        float4 bv = *(const float4*)(B + (size_t)(k0 + br) * N + col0 + bc);
        *(float4*)&Bs[br][bc] = bv;

        __syncthreads();
#pragma unroll
        for (int k = 0; k < 16; k++) {
            float4 a = *(const float4*)&As[k][ty * 4];
            float4 b = *(const float4*)&Bs[k][tx * 4];
            float am[4] = {a.x, a.y, a.z, a.w};
            float bn[4] = {b.x, b.y, b.z, b.w};
#pragma unroll
            for (int i = 0; i < 4; i++)
#pragma unroll
                for (int j = 0; j < 4; j++)
                    acc[i][j] += am[i] * bn[j];
        }
        __syncthreads();
    }

#pragma unroll
    for (int i = 0; i < 4; i++) {
        int gm = row0 + ty * 4 + i;
        if (gm < M) {
            *(float4*)(C + (size_t)gm * N + col0 + tx * 4) =
                make_float4(acc[i][0], acc[i][1], acc[i][2], acc[i][3]);
        }
    }
}

// ------------------------------------------------------------------
// Layer-1 aggregation (CSR gather) + self + bias + relu
// ------------------------------------------------------------------
__global__ void spmm_relu256(const float* __restrict__ h, float* __restrict__ out,
                             const float* __restrict__ b1) {
    const int d = blockIdx.x;
    const int f = threadIdx.x;
    const int beg = g_rowptr[d];
    const int end = g_rowptr[d + 1];

    float acc = 0.f;
    int e = beg;
    for (; e + 1 < end; e += 2) {
        int s0 = __ldg(&g_esrc[e]);
        int s1 = __ldg(&g_esrc[e + 1]);
        float w0 = __ldg(&g_dinv[s0]);
        float w1 = __ldg(&g_dinv[s1]);
        float v0 = __ldg(h + (size_t)s0 * HID_DIM + f);
        float v1 = __ldg(h + (size_t)s1 * HID_DIM + f);
        acc += w0 * v0 + w1 * v1;
    }
    if (e < end) {
        int s0 = __ldg(&g_esrc[e]);
        acc += __ldg(&g_dinv[s0]) * __ldg(h + (size_t)s0 * HID_DIM + f);
    }

    float di = g_dinv[d];
    float self = __ldg(h + (size_t)d * HID_DIM + f);
    float v = di * acc + di * di * self + b1[f];
    out[(size_t)d * HID_DIM + f] = fmaxf(v, 0.f);
}

// ------------------------------------------------------------------
// Layer-2 aggregation + bias + log_softmax (warp per node)
// ------------------------------------------------------------------
__global__ void spmm_softmax64(const float* __restrict__ h, float* __restrict__ out,
                               const float* __restrict__ b2) {
    const int node = (blockIdx.x * blockDim.x + threadIdx.x) >> 5;
    const int lane = threadIdx.x & 31;
    if (node >= N_NODES) return;

    const int beg = g_rowptr[node];
    const int end = g_rowptr[node + 1];

    float a0 = 0.f, a1 = 0.f;
    int e = beg;
    for (; e + 1 < end; e += 2) {
        int s0 = __ldg(&g_esrc[e]);
        int s1 = __ldg(&g_esrc[e + 1]);
        float w0 = __ldg(&g_dinv[s0]);
        float w1 = __ldg(&g_dinv[s1]);
        const float* r0 = h + (size_t)s0 * OUT_DIM;
        const float* r1 = h + (size_t)s1 * OUT_DIM;
        a0 += w0 * __ldg(r0 + lane)      + w1 * __ldg(r1 + lane);
        a1 += w0 * __ldg(r0 + 32 + lane) + w1 * __ldg(r1 + 32 + lane);
    }
    if (e < end) {
        int s0 = __ldg(&g_esrc[e]);
        float w0 = __ldg(&g_dinv[s0]);
        const float* r0 = h + (size_t)s0 * OUT_DIM;
        a0 += w0 * __ldg(r0 + lane);
        a1 += w0 * __ldg(r0 + 32 + lane);
    }

    float di = g_dinv[node];
    float self = di * di;
    const float* hr = h + (size_t)node * OUT_DIM;
    float v0 = di * a0 + self * __ldg(hr + lane)      + b2[lane];
    float v1 = di * a1 + self * __ldg(hr + 32 + lane) + b2[32 + lane];

    float m = fmaxf(v0, v1);
#pragma unroll
    for (int o = 16; o; o >>= 1) m = fmaxf(m, __shfl_xor_sync(0xFFFFFFFFu, m, o));
    float s = expf(v0 - m) + expf(v1 - m);
#pragma unroll
    for (int o = 16; o; o >>= 1) s += __shfl_xor_sync(0xFFFFFFFFu, s, o);
    float ls = m + logf(s);

    out[(size_t)node * OUT_DIM + lane]      = v0 - ls;
    out[(size_t)node * OUT_DIM + 32 + lane] = v1 - ls;
}

// ------------------------------------------------------------------
extern "C" void kernel_launch(void* const* d_in, const int* in_sizes, int n_in,
                              void* d_out, int out_size) {
    const float* x  = (const float*)d_in[0];
    const float* W1 = (const float*)d_in[1];
    const float* b1 = (const float*)d_in[2];
    const float* W2 = (const float*)d_in[3];
    const float* b2 = (const float*)d_in[4];
    const int* ei   = (const int*)d_in[5];
    const int E = in_sizes[5] / 2;
    const int* src = ei;
    const int* dst = ei + E;
    float* out = (float*)d_out;

    float *h1, *a1, *h2;
    cudaGetSymbolAddress((void**)&h1, g_h1);
    cudaGetSymbolAddress((void**)&a1, g_a1);
    cudaGetSymbolAddress((void**)&h2, g_h2);

    const int TB = 256;

    // ---- CSR build ----
    zero_cnt_kernel<<<(N_NODES + TB - 1) / TB, TB>>>();
    count_kernel<<<(E + TB - 1) / TB, TB>>>(dst, E);
    dinv_kernel<<<(N_NODES + TB - 1) / TB, TB>>>();
    scan1_kernel<<<SCAN_NBLK, SCAN_TB>>>();
    scan2_kernel<<<1, SCAN_TB>>>();
    scan3_kernel<<<SCAN_NBLK, SCAN_TB>>>();
    fill_kernel<<<(E + TB - 1) / TB, TB>>>(src, dst, E);

    // ---- layer 1 ----
    sgemm128<<<dim3(HID_DIM / 128, (N_NODES + 127) / 128), 256>>>(x, W1, h1, N_NODES, HID_DIM, IN_DIM);
    spmm_relu256<<<N_NODES, HID_DIM>>>(h1, a1, b1);

    // ---- layer 2 ----
    sgemm64<<<dim3(OUT_DIM / 64, (N_NODES + 63) / 64), 256>>>(a1, W2, h2, N_NODES, OUT_DIM, HID_DIM);
    spmm_softmax64<<<(N_NODES * 32 + TB - 1) / TB, TB>>>(h2, out, b2);
}

// round 6
// speedup vs baseline: 3.2198x; 1.2705x over previous
#include <cuda_runtime.h>
#include <cstdint>

#define N_NODES 50000
#define IN_DIM  512
#define HID_DIM 256
#define OUT_DIM 64
#define EDGE_CAP 1700000

#define SCAN_TB 256
#define SCAN_NBLK ((N_NODES + SCAN_TB - 1) / SCAN_TB)   // 196

// ---- scratch (no allocations allowed) ----
__device__ int   g_cnt[N_NODES];
__device__ int   g_rowptr[N_NODES + 1];
__device__ int   g_fill[N_NODES];
__device__ int   g_esrc[EDGE_CAP];
__device__ int   g_part[SCAN_NBLK];
__device__ float g_dinv[N_NODES];
__device__ float g_h1[(size_t)N_NODES * HID_DIM];
__device__ float g_a1[(size_t)N_NODES * HID_DIM];
__device__ float g_h2[(size_t)N_NODES * OUT_DIM];

// ------------------------------------------------------------------
// CSR build
// ------------------------------------------------------------------
__global__ void zero_cnt_kernel() {
    int i = blockIdx.x * blockDim.x + threadIdx.x;
    if (i < N_NODES) g_cnt[i] = 0;
}

__global__ void count_kernel(const int* __restrict__ dst, int E) {
    int i = blockIdx.x * blockDim.x + threadIdx.x;
    if (i < E) atomicAdd(&g_cnt[dst[i]], 1);
}

__global__ void dinv_kernel() {
    int i = blockIdx.x * blockDim.x + threadIdx.x;
    if (i < N_NODES) g_dinv[i] = rsqrtf((float)g_cnt[i] + 1.0f);
}

__global__ void scan1_kernel() {
    __shared__ int s[SCAN_TB];
    int t = threadIdx.x;
    int i = blockIdx.x * SCAN_TB + t;
    int v = (i < N_NODES) ? g_cnt[i] : 0;
    s[t] = v;
    __syncthreads();
    for (int off = SCAN_TB / 2; off > 0; off >>= 1) {
        if (t < off) s[t] += s[t + off];
        __syncthreads();
    }
    if (t == 0) g_part[blockIdx.x] = s[0];
}

__global__ void scan2_kernel() {
    __shared__ int s[SCAN_TB];
    int t = threadIdx.x;
    int v = (t < SCAN_NBLK) ? g_part[t] : 0;
    s[t] = v;
    __syncthreads();
    for (int off = 1; off < SCAN_TB; off <<= 1) {
        int u = (t >= off) ? s[t - off] : 0;
        __syncthreads();
        s[t] += u;
        __syncthreads();
    }
    if (t < SCAN_NBLK) g_part[t] = s[t] - v;   // exclusive
    if (t == SCAN_TB - 1) g_rowptr[N_NODES] = s[SCAN_TB - 1];
}

__global__ void scan3_kernel() {
    __shared__ int s[SCAN_TB];
    int t = threadIdx.x;
    int i = blockIdx.x * SCAN_TB + t;
    int v = (i < N_NODES) ? g_cnt[i] : 0;
    s[t] = v;
    __syncthreads();
    for (int off = 1; off < SCAN_TB; off <<= 1) {
        int u = (t >= off) ? s[t - off] : 0;
        __syncthreads();
        s[t] += u;
        __syncthreads();
    }
    if (i < N_NODES) {
        int excl = g_part[blockIdx.x] + s[t] - v;
        g_rowptr[i] = excl;
        g_fill[i]   = excl;
    }
}

__global__ void fill_kernel(const int* __restrict__ src, const int* __restrict__ dst, int E) {
    int i = blockIdx.x * blockDim.x + threadIdx.x;
    if (i < E) {
        int d = dst[i];
        int pos = atomicAdd(&g_fill[d], 1);
        g_esrc[pos] = src[i];
    }
}

// ------------------------------------------------------------------
// tf32 mma.sync GEMM:  C[M,N] = A[M,K] @ B[K,N]
// CTA 128x128, BK=16, 256 threads, 8 warps (4x2), warp tile 32x64.
// Requires N % 128 == 0, K % 16 == 0. (GEMM1: N=256, K=512)
// ------------------------------------------------------------------
static __device__ __forceinline__ uint32_t f2tf32(float x) {
    uint32_t u;
    asm("cvt.rna.tf32.f32 %0, %1;" : "=r"(u) : "f"(x));
    return u;
}

#define ASTRIDE 20   // 16 + 4 pad
#define BSTRIDE 132  // 128 + 4 pad

__global__ void __launch_bounds__(256, 2)
gemm_tf32_mma(const float* __restrict__ A, const float* __restrict__ B,
              float* __restrict__ C, int M, int N, int K) {
    __shared__ float As[128][ASTRIDE];   // [m][k], tf32 bits
    __shared__ float Bs[16][BSTRIDE];    // [k][n], tf32 bits

    const int tid  = threadIdx.x;
    const int lane = tid & 31;
    const int w    = tid >> 5;           // 0..7
    const int wm   = w >> 1;             // 0..3  (M dir)
    const int wn   = w & 1;              // 0..1  (N dir)
    const int g    = lane >> 2;          // groupID 0..7
    const int t4   = lane & 3;           // 0..3

    const int row0 = blockIdx.y * 128;
    const int col0 = blockIdx.x * 128;

    // A load mapping: 128 rows x 16 k, 8 floats/thread
    const int ar = tid >> 1;
    const int ak = (tid & 1) * 8;
    // B load mapping: 16 k x 128 n, 8 floats/thread
    const int bk = tid >> 4;
    const int bn = (tid & 15) * 8;

    float c[2][8][4];
#pragma unroll
    for (int mt = 0; mt < 2; mt++)
#pragma unroll
        for (int nt = 0; nt < 8; nt++)
#pragma unroll
            for (int q = 0; q < 4; q++) c[mt][nt][q] = 0.f;

    for (int k0 = 0; k0 < K; k0 += 16) {
        // stage A
        {
            int gm = row0 + ar;
            float4 v0 = make_float4(0.f, 0.f, 0.f, 0.f);
            float4 v1 = make_float4(0.f, 0.f, 0.f, 0.f);
            if (gm < M) {
                const float* ap = A + (size_t)gm * K + k0 + ak;
                v0 = *(const float4*)(ap);
                v1 = *(const float4*)(ap + 4);
            }
            As[ar][ak + 0] = __uint_as_float(f2tf32(v0.x));
            As[ar][ak + 1] = __uint_as_float(f2tf32(v0.y));
            As[ar][ak + 2] = __uint_as_float(f2tf32(v0.z));
            As[ar][ak + 3] = __uint_as_float(f2tf32(v0.w));
            As[ar][ak + 4] = __uint_as_float(f2tf32(v1.x));
            As[ar][ak + 5] = __uint_as_float(f2tf32(v1.y));
            As[ar][ak + 6] = __uint_as_float(f2tf32(v1.z));
            As[ar][ak + 7] = __uint_as_float(f2tf32(v1.w));
        }
        // stage B
        {
            const float* bp = B + (size_t)(k0 + bk) * N + col0 + bn;
            float4 v0 = *(const float4*)(bp);
            float4 v1 = *(const float4*)(bp + 4);
            Bs[bk][bn + 0] = __uint_as_float(f2tf32(v0.x));
            Bs[bk][bn + 1] = __uint_as_float(f2tf32(v0.y));
            Bs[bk][bn + 2] = __uint_as_float(f2tf32(v0.z));
            Bs[bk][bn + 3] = __uint_as_float(f2tf32(v0.w));
            Bs[bk][bn + 4] = __uint_as_float(f2tf32(v1.x));
            Bs[bk][bn + 5] = __uint_as_float(f2tf32(v1.y));
            Bs[bk][bn + 6] = __uint_as_float(f2tf32(v1.z));
            Bs[bk][bn + 7] = __uint_as_float(f2tf32(v1.w));
        }
        __syncthreads();

#pragma unroll
        for (int kk = 0; kk < 16; kk += 8) {
            // A fragments for 2 m-tiles
            uint32_t af[2][4];
#pragma unroll
            for (int mt = 0; mt < 2; mt++) {
                int rm = wm * 32 + mt * 16;
                af[mt][0] = __float_as_uint(As[rm + g][kk + t4]);
                af[mt][1] = __float_as_uint(As[rm + 8 + g][kk + t4]);
                af[mt][2] = __float_as_uint(As[rm + g][kk + 4 + t4]);
                af[mt][3] = __float_as_uint(As[rm + 8 + g][kk + 4 + t4]);
            }
#pragma unroll
            for (int nt = 0; nt < 8; nt++) {
                int nb = wn * 64 + nt * 8;
                uint32_t b0 = __float_as_uint(Bs[kk + t4][nb + g]);
                uint32_t b1 = __float_as_uint(Bs[kk + 4 + t4][nb + g]);
#pragma unroll
                for (int mt = 0; mt < 2; mt++) {
                    asm volatile(
                        "mma.sync.aligned.m16n8k8.row.col.f32.tf32.tf32.f32 "
                        "{%0,%1,%2,%3}, {%4,%5,%6,%7}, {%8,%9}, {%0,%1,%2,%3};"
                        : "+f"(c[mt][nt][0]), "+f"(c[mt][nt][1]),
                          "+f"(c[mt][nt][2]), "+f"(c[mt][nt][3])
                        : "r"(af[mt][0]), "r"(af[mt][1]), "r"(af[mt][2]), "r"(af[mt][3]),
                          "r"(b0), "r"(b1));
                }
            }
        }
        __syncthreads();
    }

    // epilogue
#pragma unroll
    for (int mt = 0; mt < 2; mt++) {
#pragma unroll
        for (int nt = 0; nt < 8; nt++) {
            int rbase = row0 + wm * 32 + mt * 16 + g;
            int cbase = col0 + wn * 64 + nt * 8 + 2 * t4;
            if (rbase < M)
                *(float2*)(C + (size_t)rbase * N + cbase) =
                    make_float2(c[mt][nt][0], c[mt][nt][1]);
            if (rbase + 8 < M)
                *(float2*)(C + (size_t)(rbase + 8) * N + cbase) =
                    make_float2(c[mt][nt][2], c[mt][nt][3]);
        }
    }
}

// ------------------------------------------------------------------
// SGEMM 64x64 tile (GEMM2, N=64, fp32)
// ------------------------------------------------------------------
__global__ void sgemm64(const float* __restrict__ A, const float* __restrict__ B,
                        float* __restrict__ C, int M, int N, int K) {
    __shared__ float As[16][64];
    __shared__ float Bs[16][64];

    const int tid = threadIdx.x;
    const int tx = tid & 15;
    const int ty = tid >> 4;
    const int row0 = blockIdx.y * 64;
    const int col0 = blockIdx.x * 64;

    const int ar = tid >> 2;
    const int ac = (tid & 3) * 4;
    const int br = tid >> 4;
    const int bc = (tid & 15) * 4;

    float acc[4][4] = {};

    for (int k0 = 0; k0 < K; k0 += 16) {
        float4 av = make_float4(0.f, 0.f, 0.f, 0.f);
        int gm = row0 + ar;
        if (gm < M) av = *(const float4*)(A + (size_t)gm * K + k0 + ac);
        As[ac + 0][ar] = av.x;
        As[ac + 1][ar] = av.y;
        As[ac + 2][ar] = av.z;
        As[ac + 3][ar] = av.w;

        float4 bv = *(const float4*)(B + (size_t)(k0 + br) * N + col0 + bc);
        *(float4*)&Bs[br][bc] = bv;

        __syncthreads();
#pragma unroll
        for (int k = 0; k < 16; k++) {
            float4 a = *(const float4*)&As[k][ty * 4];
            float4 b = *(const float4*)&Bs[k][tx * 4];
            float am[4] = {a.x, a.y, a.z, a.w};
            float bn[4] = {b.x, b.y, b.z, b.w};
#pragma unroll
            for (int i = 0; i < 4; i++)
#pragma unroll
                for (int j = 0; j < 4; j++)
                    acc[i][j] += am[i] * bn[j];
        }
        __syncthreads();
    }

#pragma unroll
    for (int i = 0; i < 4; i++) {
        int gm = row0 + ty * 4 + i;
        if (gm < M) {
            *(float4*)(C + (size_t)gm * N + col0 + tx * 4) =
                make_float4(acc[i][0], acc[i][1], acc[i][2], acc[i][3]);
        }
    }
}

// ------------------------------------------------------------------
// Layer-1 aggregation (CSR gather) + self + bias + relu
// ------------------------------------------------------------------
__global__ void spmm_relu256(const float* __restrict__ h, float* __restrict__ out,
                             const float* __restrict__ b1) {
    const int d = blockIdx.x;
    const int f = threadIdx.x;
    const int beg = g_rowptr[d];
    const int end = g_rowptr[d + 1];

    float acc = 0.f;
    int e = beg;
    for (; e + 1 < end; e += 2) {
        int s0 = __ldg(&g_esrc[e]);
        int s1 = __ldg(&g_esrc[e + 1]);
        float w0 = __ldg(&g_dinv[s0]);
        float w1 = __ldg(&g_dinv[s1]);
        float v0 = __ldg(h + (size_t)s0 * HID_DIM + f);
        float v1 = __ldg(h + (size_t)s1 * HID_DIM + f);
        acc += w0 * v0 + w1 * v1;
    }
    if (e < end) {
        int s0 = __ldg(&g_esrc[e]);
        acc += __ldg(&g_dinv[s0]) * __ldg(h + (size_t)s0 * HID_DIM + f);
    }

    float di = g_dinv[d];
    float self = __ldg(h + (size_t)d * HID_DIM + f);
    float v = di * acc + di * di * self + b1[f];
    out[(size_t)d * HID_DIM + f] = fmaxf(v, 0.f);
}

// ------------------------------------------------------------------
// Layer-2 aggregation + bias + log_softmax (warp per node)
// ------------------------------------------------------------------
__global__ void spmm_softmax64(const float* __restrict__ h, float* __restrict__ out,
                               const float* __restrict__ b2) {
    const int node = (blockIdx.x * blockDim.x + threadIdx.x) >> 5;
    const int lane = threadIdx.x & 31;
    if (node >= N_NODES) return;

    const int beg = g_rowptr[node];
    const int end = g_rowptr[node + 1];

    float a0 = 0.f, a1 = 0.f;
    int e = beg;
    for (; e + 1 < end; e += 2) {
        int s0 = __ldg(&g_esrc[e]);
        int s1 = __ldg(&g_esrc[e + 1]);
        float w0 = __ldg(&g_dinv[s0]);
        float w1 = __ldg(&g_dinv[s1]);
        const float* r0 = h + (size_t)s0 * OUT_DIM;
        const float* r1 = h + (size_t)s1 * OUT_DIM;
        a0 += w0 * __ldg(r0 + lane)      + w1 * __ldg(r1 + lane);
        a1 += w0 * __ldg(r0 + 32 + lane) + w1 * __ldg(r1 + 32 + lane);
    }
    if (e < end) {
        int s0 = __ldg(&g_esrc[e]);
        float w0 = __ldg(&g_dinv[s0]);
        const float* r0 = h + (size_t)s0 * OUT_DIM;
        a0 += w0 * __ldg(r0 + lane);
        a1 += w0 * __ldg(r0 + 32 + lane);
    }

    float di = g_dinv[node];
    float self = di * di;
    const float* hr = h + (size_t)node * OUT_DIM;
    float v0 = di * a0 + self * __ldg(hr + lane)      + b2[lane];
    float v1 = di * a1 + self * __ldg(hr + 32 + lane) + b2[32 + lane];

    float m = fmaxf(v0, v1);
#pragma unroll
    for (int o = 16; o; o >>= 1) m = fmaxf(m, __shfl_xor_sync(0xFFFFFFFFu, m, o));
    float s = expf(v0 - m) + expf(v1 - m);
#pragma unroll
    for (int o = 16; o; o >>= 1) s += __shfl_xor_sync(0xFFFFFFFFu, s, o);
    float ls = m + logf(s);

    out[(size_t)node * OUT_DIM + lane]      = v0 - ls;
    out[(size_t)node * OUT_DIM + 32 + lane] = v1 - ls;
}

// ------------------------------------------------------------------
extern "C" void kernel_launch(void* const* d_in, const int* in_sizes, int n_in,
                              void* d_out, int out_size) {
    const float* x  = (const float*)d_in[0];
    const float* W1 = (const float*)d_in[1];
    const float* b1 = (const float*)d_in[2];
    const float* W2 = (const float*)d_in[3];
    const float* b2 = (const float*)d_in[4];
    const int* ei   = (const int*)d_in[5];
    const int E = in_sizes[5] / 2;
    const int* src = ei;
    const int* dst = ei + E;
    float* out = (float*)d_out;

    float *h1, *a1, *h2;
    cudaGetSymbolAddress((void**)&h1, g_h1);
    cudaGetSymbolAddress((void**)&a1, g_a1);
    cudaGetSymbolAddress((void**)&h2, g_h2);

    const int TB = 256;

    // ---- CSR build ----
    zero_cnt_kernel<<<(N_NODES + TB - 1) / TB, TB>>>();
    count_kernel<<<(E + TB - 1) / TB, TB>>>(dst, E);
    dinv_kernel<<<(N_NODES + TB - 1) / TB, TB>>>();
    scan1_kernel<<<SCAN_NBLK, SCAN_TB>>>();
    scan2_kernel<<<1, SCAN_TB>>>();
    scan3_kernel<<<SCAN_NBLK, SCAN_TB>>>();
    fill_kernel<<<(E + TB - 1) / TB, TB>>>(src, dst, E);

    // ---- layer 1: tf32 mma.sync GEMM ----
    gemm_tf32_mma<<<dim3(HID_DIM / 128, (N_NODES + 127) / 128), 256>>>(
        x, W1, h1, N_NODES, HID_DIM, IN_DIM);
    spmm_relu256<<<N_NODES, HID_DIM>>>(h1, a1, b1);

    // ---- layer 2 ----
    sgemm64<<<dim3(OUT_DIM / 64, (N_NODES + 63) / 64), 256>>>(a1, W2, h2, N_NODES, OUT_DIM, HID_DIM);
    spmm_softmax64<<<(N_NODES * 32 + TB - 1) / TB, TB>>>(h2, out, b2);
}

// round 7
// speedup vs baseline: 4.2688x; 1.3258x over previous
#include <cuda_runtime.h>
#include <cstdint>

#define N_NODES 50000
#define IN_DIM  512
#define HID_DIM 256
#define OUT_DIM 64
#define EDGE_CAP 1700000

#define SCAN_TB 256
#define SCAN_NBLK ((N_NODES + SCAN_TB - 1) / SCAN_TB)   // 196

// ---- scratch (no allocations allowed) ----
__device__ int   g_cnt[N_NODES];
__device__ int   g_rowptr[N_NODES + 1];
__device__ int   g_fill[N_NODES];
__device__ int   g_esrc[EDGE_CAP];
__device__ int   g_part[SCAN_NBLK];
__device__ float g_dinv[N_NODES];
__device__ float g_h1[(size_t)N_NODES * HID_DIM];
__device__ float g_a1[(size_t)N_NODES * HID_DIM];
__device__ float g_h2[(size_t)N_NODES * OUT_DIM];

// ------------------------------------------------------------------
// CSR build
// ------------------------------------------------------------------
__global__ void zero_cnt_kernel() {
    int i = blockIdx.x * blockDim.x + threadIdx.x;
    if (i < N_NODES) g_cnt[i] = 0;
}

__global__ void count_kernel(const int* __restrict__ dst, int E) {
    int i = blockIdx.x * blockDim.x + threadIdx.x;
    if (i < E) atomicAdd(&g_cnt[dst[i]], 1);
}

__global__ void dinv_kernel() {
    int i = blockIdx.x * blockDim.x + threadIdx.x;
    if (i < N_NODES) g_dinv[i] = rsqrtf((float)g_cnt[i] + 1.0f);
}

__global__ void scan1_kernel() {
    __shared__ int s[SCAN_TB];
    int t = threadIdx.x;
    int i = blockIdx.x * SCAN_TB + t;
    int v = (i < N_NODES) ? g_cnt[i] : 0;
    s[t] = v;
    __syncthreads();
    for (int off = SCAN_TB / 2; off > 0; off >>= 1) {
        if (t < off) s[t] += s[t + off];
        __syncthreads();
    }
    if (t == 0) g_part[blockIdx.x] = s[0];
}

__global__ void scan2_kernel() {
    __shared__ int s[SCAN_TB];
    int t = threadIdx.x;
    int v = (t < SCAN_NBLK) ? g_part[t] : 0;
    s[t] = v;
    __syncthreads();
    for (int off = 1; off < SCAN_TB; off <<= 1) {
        int u = (t >= off) ? s[t - off] : 0;
        __syncthreads();
        s[t] += u;
        __syncthreads();
    }
    if (t < SCAN_NBLK) g_part[t] = s[t] - v;   // exclusive
    if (t == SCAN_TB - 1) g_rowptr[N_NODES] = s[SCAN_TB - 1];
}

__global__ void scan3_kernel() {
    __shared__ int s[SCAN_TB];
    int t = threadIdx.x;
    int i = blockIdx.x * SCAN_TB + t;
    int v = (i < N_NODES) ? g_cnt[i] : 0;
    s[t] = v;
    __syncthreads();
    for (int off = 1; off < SCAN_TB; off <<= 1) {
        int u = (t >= off) ? s[t - off] : 0;
        __syncthreads();
        s[t] += u;
        __syncthreads();
    }
    if (i < N_NODES) {
        int excl = g_part[blockIdx.x] + s[t] - v;
        g_rowptr[i] = excl;
        g_fill[i]   = excl;
    }
}

__global__ void fill_kernel(const int* __restrict__ src, const int* __restrict__ dst, int E) {
    int i = blockIdx.x * blockDim.x + threadIdx.x;
    if (i < E) {
        int d = dst[i];
        int pos = atomicAdd(&g_fill[d], 1);
        g_esrc[pos] = src[i];
    }
}

// ------------------------------------------------------------------
// tf32 helpers / fragments
// ------------------------------------------------------------------
static __device__ __forceinline__ uint32_t f2tf32(float x) {
    uint32_t u;
    asm("cvt.rna.tf32.f32 %0, %1;" : "=r"(u) : "f"(x));
    return u;
}

#define ASTRIDE 20   // 16 + 4 pad

// ------------------------------------------------------------------
// GEMM1: tf32 mma.sync, CTA 128x128, BK=16, warp tile 32x64 (N=256,K=512)
// ------------------------------------------------------------------
#define BSTRIDE 132  // 128 + 4 pad

__global__ void __launch_bounds__(256, 2)
gemm_tf32_mma(const float* __restrict__ A, const float* __restrict__ B,
              float* __restrict__ C, int M, int N, int K) {
    __shared__ float As[128][ASTRIDE];   // [m][k], tf32 bits
    __shared__ float Bs[16][BSTRIDE];    // [k][n], tf32 bits

    const int tid  = threadIdx.x;
    const int lane = tid & 31;
    const int w    = tid >> 5;
    const int wm   = w >> 1;             // 0..3
    const int wn   = w & 1;              // 0..1
    const int g    = lane >> 2;
    const int t4   = lane & 3;

    const int row0 = blockIdx.y * 128;
    const int col0 = blockIdx.x * 128;

    const int ar = tid >> 1;
    const int ak = (tid & 1) * 8;
    const int bk = tid >> 4;
    const int bn = (tid & 15) * 8;

    float c[2][8][4];
#pragma unroll
    for (int mt = 0; mt < 2; mt++)
#pragma unroll
        for (int nt = 0; nt < 8; nt++)
#pragma unroll
            for (int q = 0; q < 4; q++) c[mt][nt][q] = 0.f;

    for (int k0 = 0; k0 < K; k0 += 16) {
        {
            int gm = row0 + ar;
            float4 v0 = make_float4(0.f, 0.f, 0.f, 0.f);
            float4 v1 = make_float4(0.f, 0.f, 0.f, 0.f);
            if (gm < M) {
                const float* ap = A + (size_t)gm * K + k0 + ak;
                v0 = *(const float4*)(ap);
                v1 = *(const float4*)(ap + 4);
            }
            As[ar][ak + 0] = __uint_as_float(f2tf32(v0.x));
            As[ar][ak + 1] = __uint_as_float(f2tf32(v0.y));
            As[ar][ak + 2] = __uint_as_float(f2tf32(v0.z));
            As[ar][ak + 3] = __uint_as_float(f2tf32(v0.w));
            As[ar][ak + 4] = __uint_as_float(f2tf32(v1.x));
            As[ar][ak + 5] = __uint_as_float(f2tf32(v1.y));
            As[ar][ak + 6] = __uint_as_float(f2tf32(v1.z));
            As[ar][ak + 7] = __uint_as_float(f2tf32(v1.w));
        }
        {
            const float* bp = B + (size_t)(k0 + bk) * N + col0 + bn;
            float4 v0 = *(const float4*)(bp);
            float4 v1 = *(const float4*)(bp + 4);
            Bs[bk][bn + 0] = __uint_as_float(f2tf32(v0.x));
            Bs[bk][bn + 1] = __uint_as_float(f2tf32(v0.y));
            Bs[bk][bn + 2] = __uint_as_float(f2tf32(v0.z));
            Bs[bk][bn + 3] = __uint_as_float(f2tf32(v0.w));
            Bs[bk][bn + 4] = __uint_as_float(f2tf32(v1.x));
            Bs[bk][bn + 5] = __uint_as_float(f2tf32(v1.y));
            Bs[bk][bn + 6] = __uint_as_float(f2tf32(v1.z));
            Bs[bk][bn + 7] = __uint_as_float(f2tf32(v1.w));
        }
        __syncthreads();

#pragma unroll
        for (int kk = 0; kk < 16; kk += 8) {
            uint32_t af[2][4];
#pragma unroll
            for (int mt = 0; mt < 2; mt++) {
                int rm = wm * 32 + mt * 16;
                af[mt][0] = __float_as_uint(As[rm + g][kk + t4]);
                af[mt][1] = __float_as_uint(As[rm + 8 + g][kk + t4]);
                af[mt][2] = __float_as_uint(As[rm + g][kk + 4 + t4]);
                af[mt][3] = __float_as_uint(As[rm + 8 + g][kk + 4 + t4]);
            }
#pragma unroll
            for (int nt = 0; nt < 8; nt++) {
                int nb = wn * 64 + nt * 8;
                uint32_t b0 = __float_as_uint(Bs[kk + t4][nb + g]);
                uint32_t b1 = __float_as_uint(Bs[kk + 4 + t4][nb + g]);
#pragma unroll
                for (int mt = 0; mt < 2; mt++) {
                    asm volatile(
                        "mma.sync.aligned.m16n8k8.row.col.f32.tf32.tf32.f32 "
                        "{%0,%1,%2,%3}, {%4,%5,%6,%7}, {%8,%9}, {%0,%1,%2,%3};"
                        : "+f"(c[mt][nt][0]), "+f"(c[mt][nt][1]),
                          "+f"(c[mt][nt][2]), "+f"(c[mt][nt][3])
                        : "r"(af[mt][0]), "r"(af[mt][1]), "r"(af[mt][2]), "r"(af[mt][3]),
                          "r"(b0), "r"(b1));
                }
            }
        }
        __syncthreads();
    }

#pragma unroll
    for (int mt = 0; mt < 2; mt++) {
#pragma unroll
        for (int nt = 0; nt < 8; nt++) {
            int rbase = row0 + wm * 32 + mt * 16 + g;
            int cbase = col0 + wn * 64 + nt * 8 + 2 * t4;
            if (rbase < M)
                *(float2*)(C + (size_t)rbase * N + cbase) =
                    make_float2(c[mt][nt][0], c[mt][nt][1]);
            if (rbase + 8 < M)
                *(float2*)(C + (size_t)(rbase + 8) * N + cbase) =
                    make_float2(c[mt][nt][2], c[mt][nt][3]);
        }
    }
}

// ------------------------------------------------------------------
// GEMM2: tf32 mma.sync, CTA 128x64, BK=16, warp tile 32x32 (N=64,K=256)
// ------------------------------------------------------------------
#define B2STRIDE 68  // 64 + 4 pad

__global__ void __launch_bounds__(256, 2)
gemm2_tf32_mma(const float* __restrict__ A, const float* __restrict__ B,
               float* __restrict__ C, int M) {
    const int N = OUT_DIM, K = HID_DIM;
    __shared__ float As[128][ASTRIDE];
    __shared__ float Bs[16][B2STRIDE];

    const int tid  = threadIdx.x;
    const int lane = tid & 31;
    const int w    = tid >> 5;
    const int wm   = w >> 1;             // 0..3
    const int wn   = w & 1;              // 0..1
    const int g    = lane >> 2;
    const int t4   = lane & 3;

    const int row0 = blockIdx.x * 128;

    const int ar = tid >> 1;
    const int ak = (tid & 1) * 8;
    const int bk = tid >> 4;             // 0..15
    const int bn = (tid & 15) * 4;       // 0..60

    float c[2][4][4];
#pragma unroll
    for (int mt = 0; mt < 2; mt++)
#pragma unroll
        for (int nt = 0; nt < 4; nt++)
#pragma unroll
            for (int q = 0; q < 4; q++) c[mt][nt][q] = 0.f;

    for (int k0 = 0; k0 < K; k0 += 16) {
        {
            int gm = row0 + ar;
            float4 v0 = make_float4(0.f, 0.f, 0.f, 0.f);
            float4 v1 = make_float4(0.f, 0.f, 0.f, 0.f);
            if (gm < M) {
                const float* ap = A + (size_t)gm * K + k0 + ak;
                v0 = *(const float4*)(ap);
                v1 = *(const float4*)(ap + 4);
            }
            As[ar][ak + 0] = __uint_as_float(f2tf32(v0.x));
            As[ar][ak + 1] = __uint_as_float(f2tf32(v0.y));
            As[ar][ak + 2] = __uint_as_float(f2tf32(v0.z));
            As[ar][ak + 3] = __uint_as_float(f2tf32(v0.w));
            As[ar][ak + 4] = __uint_as_float(f2tf32(v1.x));
            As[ar][ak + 5] = __uint_as_float(f2tf32(v1.y));
            As[ar][ak + 6] = __uint_as_float(f2tf32(v1.z));
            As[ar][ak + 7] = __uint_as_float(f2tf32(v1.w));
        }
        {
            const float* bp = B + (size_t)(k0 + bk) * N + bn;
            float4 v0 = *(const float4*)(bp);
            Bs[bk][bn + 0] = __uint_as_float(f2tf32(v0.x));
            Bs[bk][bn + 1] = __uint_as_float(f2tf32(v0.y));
            Bs[bk][bn + 2] = __uint_as_float(f2tf32(v0.z));
            Bs[bk][bn + 3] = __uint_as_float(f2tf32(v0.w));
        }
        __syncthreads();

#pragma unroll
        for (int kk = 0; kk < 16; kk += 8) {
            uint32_t af[2][4];
#pragma unroll
            for (int mt = 0; mt < 2; mt++) {
                int rm = wm * 32 + mt * 16;
                af[mt][0] = __float_as_uint(As[rm + g][kk + t4]);
                af[mt][1] = __float_as_uint(As[rm + 8 + g][kk + t4]);
                af[mt][2] = __float_as_uint(As[rm + g][kk + 4 + t4]);
                af[mt][3] = __float_as_uint(As[rm + 8 + g][kk + 4 + t4]);
            }
#pragma unroll
            for (int nt = 0; nt < 4; nt++) {
                int nb = wn * 32 + nt * 8;
                uint32_t b0 = __float_as_uint(Bs[kk + t4][nb + g]);
                uint32_t b1 = __float_as_uint(Bs[kk + 4 + t4][nb + g]);
#pragma unroll
                for (int mt = 0; mt < 2; mt++) {
                    asm volatile(
                        "mma.sync.aligned.m16n8k8.row.col.f32.tf32.tf32.f32 "
                        "{%0,%1,%2,%3}, {%4,%5,%6,%7}, {%8,%9}, {%0,%1,%2,%3};"
                        : "+f"(c[mt][nt][0]), "+f"(c[mt][nt][1]),
                          "+f"(c[mt][nt][2]), "+f"(c[mt][nt][3])
                        : "r"(af[mt][0]), "r"(af[mt][1]), "r"(af[mt][2]), "r"(af[mt][3]),
                          "r"(b0), "r"(b1));
                }
            }
        }
        __syncthreads();
    }

#pragma unroll
    for (int mt = 0; mt < 2; mt++) {
#pragma unroll
        for (int nt = 0; nt < 4; nt++) {
            int rbase = row0 + wm * 32 + mt * 16 + g;
            int cbase = wn * 32 + nt * 8 + 2 * t4;
            if (rbase < M)
                *(float2*)(C + (size_t)rbase * N + cbase) =
                    make_float2(c[mt][nt][0], c[mt][nt][1]);
            if (rbase + 8 < M)
                *(float2*)(C + (size_t)(rbase + 8) * N + cbase) =
                    make_float2(c[mt][nt][2], c[mt][nt][3]);
        }
    }
}

// ------------------------------------------------------------------
// Layer-1 aggregation (CSR gather) + self + bias + relu
// 4 nodes per 256-thread block; 64 threads/node, float4 per thread.
// ------------------------------------------------------------------
__global__ void spmm_relu256(const float* __restrict__ h, float* __restrict__ out,
                             const float* __restrict__ b1) {
    const int d = blockIdx.x * 4 + (threadIdx.x >> 6);
    const int q = threadIdx.x & 63;            // float4 slot (feature q*4)
    if (d >= N_NODES) return;
    const int beg = g_rowptr[d];
    const int end = g_rowptr[d + 1];

    float4 acc = make_float4(0.f, 0.f, 0.f, 0.f);
    int e = beg;
    for (; e + 1 < end; e += 2) {
        int s0 = __ldg(&g_esrc[e]);
        int s1 = __ldg(&g_esrc[e + 1]);
        float w0 = __ldg(&g_dinv[s0]);
        float w1 = __ldg(&g_dinv[s1]);
        float4 v0 = __ldg((const float4*)(h + (size_t)s0 * HID_DIM) + q);
        float4 v1 = __ldg((const float4*)(h + (size_t)s1 * HID_DIM) + q);
        acc.x += w0 * v0.x + w1 * v1.x;
        acc.y += w0 * v0.y + w1 * v1.y;
        acc.z += w0 * v0.z + w1 * v1.z;
        acc.w += w0 * v0.w + w1 * v1.w;
    }
    if (e < end) {
        int s0 = __ldg(&g_esrc[e]);
        float w0 = __ldg(&g_dinv[s0]);
        float4 v0 = __ldg((const float4*)(h + (size_t)s0 * HID_DIM) + q);
        acc.x += w0 * v0.x;
        acc.y += w0 * v0.y;
        acc.z += w0 * v0.z;
        acc.w += w0 * v0.w;
    }

    float di = g_dinv[d];
    float sw = di * di;
    float4 self = __ldg((const float4*)(h + (size_t)d * HID_DIM) + q);
    float4 bias = __ldg((const float4*)b1 + q);
    float4 r;
    r.x = fmaxf(di * acc.x + sw * self.x + bias.x, 0.f);
    r.y = fmaxf(di * acc.y + sw * self.y + bias.y, 0.f);
    r.z = fmaxf(di * acc.z + sw * self.z + bias.z, 0.f);
    r.w = fmaxf(di * acc.w + sw * self.w + bias.w, 0.f);
    ((float4*)(out + (size_t)d * HID_DIM))[q] = r;
}

// ------------------------------------------------------------------
// Layer-2 aggregation + bias + log_softmax (warp per node, float2 lanes)
// ------------------------------------------------------------------
__global__ void spmm_softmax64(const float* __restrict__ h, float* __restrict__ out,
                               const float* __restrict__ b2) {
    const int node = (blockIdx.x * blockDim.x + threadIdx.x) >> 5;
    const int lane = threadIdx.x & 31;
    if (node >= N_NODES) return;

    const int beg = g_rowptr[node];
    const int end = g_rowptr[node + 1];

    float a0 = 0.f, a1 = 0.f;
    int e = beg;
    for (; e + 1 < end; e += 2) {
        int s0 = __ldg(&g_esrc[e]);
        int s1 = __ldg(&g_esrc[e + 1]);
        float w0 = __ldg(&g_dinv[s0]);
        float w1 = __ldg(&g_dinv[s1]);
        float2 v0 = __ldg((const float2*)(h + (size_t)s0 * OUT_DIM) + lane);
        float2 v1 = __ldg((const float2*)(h + (size_t)s1 * OUT_DIM) + lane);
        a0 += w0 * v0.x + w1 * v1.x;
        a1 += w0 * v0.y + w1 * v1.y;
    }
    if (e < end) {
        int s0 = __ldg(&g_esrc[e]);
        float w0 = __ldg(&g_dinv[s0]);
        float2 v0 = __ldg((const float2*)(h + (size_t)s0 * OUT_DIM) + lane);
        a0 += w0 * v0.x;
        a1 += w0 * v0.y;
    }

    float di = g_dinv[node];
    float sw = di * di;
    float2 self = __ldg((const float2*)(h + (size_t)node * OUT_DIM) + lane);
    float2 bias = __ldg((const float2*)b2 + lane);
    float v0 = di * a0 + sw * self.x + bias.x;
    float v1 = di * a1 + sw * self.y + bias.y;

    float m = fmaxf(v0, v1);
#pragma unroll
    for (int o = 16; o; o >>= 1) m = fmaxf(m, __shfl_xor_sync(0xFFFFFFFFu, m, o));
    float s = expf(v0 - m) + expf(v1 - m);
#pragma unroll
    for (int o = 16; o; o >>= 1) s += __shfl_xor_sync(0xFFFFFFFFu, s, o);
    float ls = m + logf(s);

    ((float2*)(out + (size_t)node * OUT_DIM))[lane] = make_float2(v0 - ls, v1 - ls);
}

// ------------------------------------------------------------------
extern "C" void kernel_launch(void* const* d_in, const int* in_sizes, int n_in,
                              void* d_out, int out_size) {
    const float* x  = (const float*)d_in[0];
    const float* W1 = (const float*)d_in[1];
    const float* b1 = (const float*)d_in[2];
    const float* W2 = (const float*)d_in[3];
    const float* b2 = (const float*)d_in[4];
    const int* ei   = (const int*)d_in[5];
    const int E = in_sizes[5] / 2;
    const int* src = ei;
    const int* dst = ei + E;
    float* out = (float*)d_out;

    float *h1, *a1, *h2;
    cudaGetSymbolAddress((void**)&h1, g_h1);
    cudaGetSymbolAddress((void**)&a1, g_a1);
    cudaGetSymbolAddress((void**)&h2, g_h2);

    const int TB = 256;

    // ---- CSR build ----
    zero_cnt_kernel<<<(N_NODES + TB - 1) / TB, TB>>>();
    count_kernel<<<(E + TB - 1) / TB, TB>>>(dst, E);
    dinv_kernel<<<(N_NODES + TB - 1) / TB, TB>>>();
    scan1_kernel<<<SCAN_NBLK, SCAN_TB>>>();
    scan2_kernel<<<1, SCAN_TB>>>();
    scan3_kernel<<<SCAN_NBLK, SCAN_TB>>>();
    fill_kernel<<<(E + TB - 1) / TB, TB>>>(src, dst, E);

    // ---- layer 1 ----
    gemm_tf32_mma<<<dim3(HID_DIM / 128, (N_NODES + 127) / 128), 256>>>(
        x, W1, h1, N_NODES, HID_DIM, IN_DIM);
    spmm_relu256<<<(N_NODES + 3) / 4, 256>>>(h1, a1, b1);

    // ---- layer 2 ----
    gemm2_tf32_mma<<<(N_NODES + 127) / 128, 256>>>(a1, W2, h2, N_NODES);
    spmm_softmax64<<<(N_NODES * 32 + TB - 1) / TB, TB>>>(h2, out, b2);
}

// round 8
// speedup vs baseline: 4.5627x; 1.0689x over previous
#include <cuda_runtime.h>
#include <cstdint>

#define N_NODES 50000
#define IN_DIM  512
#define HID_DIM 256
#define OUT_DIM 64
#define EDGE_CAP 1700000

#define SCAN_TB 256
#define SCAN_NBLK ((N_NODES + SCAN_TB - 1) / SCAN_TB)   // 196

// ---- scratch (no allocations allowed) ----
__device__ int   g_cnt[N_NODES];
__device__ int   g_rowptr[N_NODES + 1];
__device__ int   g_fill[N_NODES];
__device__ int   g_esrc[EDGE_CAP];
__device__ int   g_part[SCAN_NBLK];
__device__ float g_dinv[N_NODES];
__device__ float g_h1[(size_t)N_NODES * HID_DIM];
__device__ float g_a1[(size_t)N_NODES * HID_DIM];
__device__ float g_h2[(size_t)N_NODES * OUT_DIM];

// ------------------------------------------------------------------
// CSR build
// ------------------------------------------------------------------
__global__ void count_kernel(const int* __restrict__ dst, int E) {
    int i = blockIdx.x * blockDim.x + threadIdx.x;
    if (i < E) atomicAdd(&g_cnt[dst[i]], 1);
}

// per-block sums + dinv (fused)
__global__ void scan1_kernel() {
    __shared__ int s[SCAN_TB];
    int t = threadIdx.x;
    int i = blockIdx.x * SCAN_TB + t;
    int v = 0;
    if (i < N_NODES) {
        v = g_cnt[i];
        g_dinv[i] = rsqrtf((float)v + 1.0f);
    }
    s[t] = v;
    __syncthreads();
    for (int off = SCAN_TB / 2; off > 0; off >>= 1) {
        if (t < off) s[t] += s[t + off];
        __syncthreads();
    }
    if (t == 0) g_part[blockIdx.x] = s[0];
}

__global__ void scan2_kernel() {
    __shared__ int s[SCAN_TB];
    int t = threadIdx.x;
    int v = (t < SCAN_NBLK) ? g_part[t] : 0;
    s[t] = v;
    __syncthreads();
    for (int off = 1; off < SCAN_TB; off <<= 1) {
        int u = (t >= off) ? s[t - off] : 0;
        __syncthreads();
        s[t] += u;
        __syncthreads();
    }
    if (t < SCAN_NBLK) g_part[t] = s[t] - v;   // exclusive
    if (t == SCAN_TB - 1) g_rowptr[N_NODES] = s[SCAN_TB - 1];
}

__global__ void scan3_kernel() {
    __shared__ int s[SCAN_TB];
    int t = threadIdx.x;
    int i = blockIdx.x * SCAN_TB + t;
    int v = (i < N_NODES) ? g_cnt[i] : 0;
    s[t] = v;
    __syncthreads();
    for (int off = 1; off < SCAN_TB; off <<= 1) {
        int u = (t >= off) ? s[t - off] : 0;
        __syncthreads();
        s[t] += u;
        __syncthreads();
    }
    if (i < N_NODES) {
        int excl = g_part[blockIdx.x] + s[t] - v;
        g_rowptr[i] = excl;
        g_fill[i]   = excl;
    }
}

__global__ void fill_kernel(const int* __restrict__ src, const int* __restrict__ dst, int E) {
    int i = blockIdx.x * blockDim.x + threadIdx.x;
    if (i < E) {
        int d = dst[i];
        int pos = atomicAdd(&g_fill[d], 1);
        g_esrc[pos] = src[i];
    }
}

// ------------------------------------------------------------------
// tf32 helpers
// ------------------------------------------------------------------
static __device__ __forceinline__ uint32_t f2tf32(float x) {
    uint32_t u;
    asm("cvt.rna.tf32.f32 %0, %1;" : "=r"(u) : "f"(x));
    return u;
}

#define ASTRIDE 20   // 16 + 4 pad
#define BSTRIDE 132  // 128 + 4 pad

// ------------------------------------------------------------------
// GEMM1: tf32 mma.sync, CTA 128x128, BK=16, warp tile 32x64,
// double-buffered smem with register prefetch. (N=256, K=512)
// ------------------------------------------------------------------
__global__ void __launch_bounds__(256, 2)
gemm_tf32_mma(const float* __restrict__ A, const float* __restrict__ B,
              float* __restrict__ C, int M, int N, int K) {
    __shared__ float As[2][128][ASTRIDE];
    __shared__ float Bs[2][16][BSTRIDE];

    const int tid  = threadIdx.x;
    const int lane = tid & 31;
    const int w    = tid >> 5;
    const int wm   = w >> 1;             // 0..3
    const int wn   = w & 1;              // 0..1
    const int g    = lane >> 2;
    const int t4   = lane & 3;

    const int row0 = blockIdx.y * 128;
    const int col0 = blockIdx.x * 128;

    const int ar = tid >> 1;
    const int ak = (tid & 1) * 8;
    const int bk = tid >> 4;
    const int bn = (tid & 15) * 8;

    const int gm = row0 + ar;
    const float* aptr = A + (size_t)gm * K + ak;
    const float* bptr = B + (size_t)bk * N + col0 + bn;

    float c[2][8][4];
#pragma unroll
    for (int mt = 0; mt < 2; mt++)
#pragma unroll
        for (int nt = 0; nt < 8; nt++)
#pragma unroll
            for (int q = 0; q < 4; q++) c[mt][nt][q] = 0.f;

    // prime buffer 0
    float4 pa0 = make_float4(0.f, 0.f, 0.f, 0.f), pa1 = pa0;
    if (gm < M) { pa0 = *(const float4*)(aptr); pa1 = *(const float4*)(aptr + 4); }
    float4 pb0 = *(const float4*)(bptr);
    float4 pb1 = *(const float4*)(bptr + 4);
    {
        float* as = &As[0][ar][ak];
        as[0] = __uint_as_float(f2tf32(pa0.x)); as[1] = __uint_as_float(f2tf32(pa0.y));
        as[2] = __uint_as_float(f2tf32(pa0.z)); as[3] = __uint_as_float(f2tf32(pa0.w));
        as[4] = __uint_as_float(f2tf32(pa1.x)); as[5] = __uint_as_float(f2tf32(pa1.y));
        as[6] = __uint_as_float(f2tf32(pa1.z)); as[7] = __uint_as_float(f2tf32(pa1.w));
        float* bs = &Bs[0][bk][bn];
        bs[0] = __uint_as_float(f2tf32(pb0.x)); bs[1] = __uint_as_float(f2tf32(pb0.y));
        bs[2] = __uint_as_float(f2tf32(pb0.z)); bs[3] = __uint_as_float(f2tf32(pb0.w));
        bs[4] = __uint_as_float(f2tf32(pb1.x)); bs[5] = __uint_as_float(f2tf32(pb1.y));
        bs[6] = __uint_as_float(f2tf32(pb1.z)); bs[7] = __uint_as_float(f2tf32(pb1.w));
    }
    __syncthreads();

    int buf = 0;
    for (int k0 = 0; k0 < K; k0 += 16) {
        const bool has_next = (k0 + 16) < K;
        if (has_next) {
            if (gm < M) {
                pa0 = *(const float4*)(aptr + k0 + 16);
                pa1 = *(const float4*)(aptr + k0 + 16 + 4);
            }
            pb0 = *(const float4*)(bptr + (size_t)(k0 + 16) * N);
            pb1 = *(const float4*)(bptr + (size_t)(k0 + 16) * N + 4);
        }

#pragma unroll
        for (int kk = 0; kk < 16; kk += 8) {
            uint32_t af[2][4];
#pragma unroll
            for (int mt = 0; mt < 2; mt++) {
                int rm = wm * 32 + mt * 16;
                af[mt][0] = __float_as_uint(As[buf][rm + g][kk + t4]);
                af[mt][1] = __float_as_uint(As[buf][rm + 8 + g][kk + t4]);
                af[mt][2] = __float_as_uint(As[buf][rm + g][kk + 4 + t4]);
                af[mt][3] = __float_as_uint(As[buf][rm + 8 + g][kk + 4 + t4]);
            }
#pragma unroll
            for (int nt = 0; nt < 8; nt++) {
                int nb = wn * 64 + nt * 8;
                uint32_t b0 = __float_as_uint(Bs[buf][kk + t4][nb + g]);
                uint32_t b1 = __float_as_uint(Bs[buf][kk + 4 + t4][nb + g]);
#pragma unroll
                for (int mt = 0; mt < 2; mt++) {
                    asm volatile(
                        "mma.sync.aligned.m16n8k8.row.col.f32.tf32.tf32.f32 "
                        "{%0,%1,%2,%3}, {%4,%5,%6,%7}, {%8,%9}, {%0,%1,%2,%3};"
                        : "+f"(c[mt][nt][0]), "+f"(c[mt][nt][1]),
                          "+f"(c[mt][nt][2]), "+f"(c[mt][nt][3])
                        : "r"(af[mt][0]), "r"(af[mt][1]), "r"(af[mt][2]), "r"(af[mt][3]),
                          "r"(b0), "r"(b1));
                }
            }
        }

        if (has_next) {
            const int nb = buf ^ 1;
            float* as = &As[nb][ar][ak];
            as[0] = __uint_as_float(f2tf32(pa0.x)); as[1] = __uint_as_float(f2tf32(pa0.y));
            as[2] = __uint_as_float(f2tf32(pa0.z)); as[3] = __uint_as_float(f2tf32(pa0.w));
            as[4] = __uint_as_float(f2tf32(pa1.x)); as[5] = __uint_as_float(f2tf32(pa1.y));
            as[6] = __uint_as_float(f2tf32(pa1.z)); as[7] = __uint_as_float(f2tf32(pa1.w));
            float* bs = &Bs[nb][bk][bn];
            bs[0] = __uint_as_float(f2tf32(pb0.x)); bs[1] = __uint_as_float(f2tf32(pb0.y));
            bs[2] = __uint_as_float(f2tf32(pb0.z)); bs[3] = __uint_as_float(f2tf32(pb0.w));
            bs[4] = __uint_as_float(f2tf32(pb1.x)); bs[5] = __uint_as_float(f2tf32(pb1.y));
            bs[6] = __uint_as_float(f2tf32(pb1.z)); bs[7] = __uint_as_float(f2tf32(pb1.w));
            __syncthreads();
            buf = nb;
        }
    }

#pragma unroll
    for (int mt = 0; mt < 2; mt++) {
#pragma unroll
        for (int nt = 0; nt < 8; nt++) {
            int rbase = row0 + wm * 32 + mt * 16 + g;
            int cbase = col0 + wn * 64 + nt * 8 + 2 * t4;
            if (rbase < M)
                *(float2*)(C + (size_t)rbase * N + cbase) =
                    make_float2(c[mt][nt][0], c[mt][nt][1]);
            if (rbase + 8 < M)
                *(float2*)(C + (size_t)(rbase + 8) * N + cbase) =
                    make_float2(c[mt][nt][2], c[mt][nt][3]);
        }
    }
}

// ------------------------------------------------------------------
// GEMM2: tf32 mma.sync, CTA 128x64, BK=16, warp tile 32x32 (N=64,K=256)
// ------------------------------------------------------------------
#define B2STRIDE 68  // 64 + 4 pad

__global__ void __launch_bounds__(256, 2)
gemm2_tf32_mma(const float* __restrict__ A, const float* __restrict__ B,
               float* __restrict__ C, int M) {
    const int N = OUT_DIM, K = HID_DIM;
    __shared__ float As[128][ASTRIDE];
    __shared__ float Bs[16][B2STRIDE];

    const int tid  = threadIdx.x;
    const int lane = tid & 31;
    const int w    = tid >> 5;
    const int wm   = w >> 1;
    const int wn   = w & 1;
    const int g    = lane >> 2;
    const int t4   = lane & 3;

    const int row0 = blockIdx.x * 128;

    const int ar = tid >> 1;
    const int ak = (tid & 1) * 8;
    const int bk = tid >> 4;
    const int bn = (tid & 15) * 4;

    float c[2][4][4];
#pragma unroll
    for (int mt = 0; mt < 2; mt++)
#pragma unroll
        for (int nt = 0; nt < 4; nt++)
#pragma unroll
            for (int q = 0; q < 4; q++) c[mt][nt][q] = 0.f;

    for (int k0 = 0; k0 < K; k0 += 16) {
        {
            int gm = row0 + ar;
            float4 v0 = make_float4(0.f, 0.f, 0.f, 0.f);
            float4 v1 = make_float4(0.f, 0.f, 0.f, 0.f);
            if (gm < M) {
                const float* ap = A + (size_t)gm * K + k0 + ak;
                v0 = *(const float4*)(ap);
                v1 = *(const float4*)(ap + 4);
            }
            As[ar][ak + 0] = __uint_as_float(f2tf32(v0.x));
            As[ar][ak + 1] = __uint_as_float(f2tf32(v0.y));
            As[ar][ak + 2] = __uint_as_float(f2tf32(v0.z));
            As[ar][ak + 3] = __uint_as_float(f2tf32(v0.w));
            As[ar][ak + 4] = __uint_as_float(f2tf32(v1.x));
            As[ar][ak + 5] = __uint_as_float(f2tf32(v1.y));
            As[ar][ak + 6] = __uint_as_float(f2tf32(v1.z));
            As[ar][ak + 7] = __uint_as_float(f2tf32(v1.w));
        }
        {
            const float* bp = B + (size_t)(k0 + bk) * N + bn;
            float4 v0 = *(const float4*)(bp);
            Bs[bk][bn + 0] = __uint_as_float(f2tf32(v0.x));
            Bs[bk][bn + 1] = __uint_as_float(f2tf32(v0.y));
            Bs[bk][bn + 2] = __uint_as_float(f2tf32(v0.z));
            Bs[bk][bn + 3] = __uint_as_float(f2tf32(v0.w));
        }
        __syncthreads();

#pragma unroll
        for (int kk = 0; kk < 16; kk += 8) {
            uint32_t af[2][4];
#pragma unroll
            for (int mt = 0; mt < 2; mt++) {
                int rm = wm * 32 + mt * 16;
                af[mt][0] = __float_as_uint(As[rm + g][kk + t4]);
                af[mt][1] = __float_as_uint(As[rm + 8 + g][kk + t4]);
                af[mt][2] = __float_as_uint(As[rm + g][kk + 4 + t4]);
                af[mt][3] = __float_as_uint(As[rm + 8 + g][kk + 4 + t4]);
            }
#pragma unroll
            for (int nt = 0; nt < 4; nt++) {
                int nb = wn * 32 + nt * 8;
                uint32_t b0 = __float_as_uint(Bs[kk + t4][nb + g]);
                uint32_t b1 = __float_as_uint(Bs[kk + 4 + t4][nb + g]);
#pragma unroll
                for (int mt = 0; mt < 2; mt++) {
                    asm volatile(
                        "mma.sync.aligned.m16n8k8.row.col.f32.tf32.tf32.f32 "
                        "{%0,%1,%2,%3}, {%4,%5,%6,%7}, {%8,%9}, {%0,%1,%2,%3};"
                        : "+f"(c[mt][nt][0]), "+f"(c[mt][nt][1]),
                          "+f"(c[mt][nt][2]), "+f"(c[mt][nt][3])
                        : "r"(af[mt][0]), "r"(af[mt][1]), "r"(af[mt][2]), "r"(af[mt][3]),
                          "r"(b0), "r"(b1));
                }
            }
        }
        __syncthreads();
    }

#pragma unroll
    for (int mt = 0; mt < 2; mt++) {
#pragma unroll
        for (int nt = 0; nt < 4; nt++) {
            int rbase = row0 + wm * 32 + mt * 16 + g;
            int cbase = wn * 32 + nt * 8 + 2 * t4;
            if (rbase < M)
                *(float2*)(C + (size_t)rbase * N + cbase) =
                    make_float2(c[mt][nt][0], c[mt][nt][1]);
            if (rbase + 8 < M)
                *(float2*)(C + (size_t)(rbase + 8) * N + cbase) =
                    make_float2(c[mt][nt][2], c[mt][nt][3]);
        }
    }
}

// ------------------------------------------------------------------
// Layer-1 aggregation (CSR gather) + self + bias + relu
// 4 nodes per 256-thread block; 64 threads/node, float4 per thread.
// ------------------------------------------------------------------
__global__ void spmm_relu256(const float* __restrict__ h, float* __restrict__ out,
                             const float* __restrict__ b1) {
    const int d = blockIdx.x * 4 + (threadIdx.x >> 6);
    const int q = threadIdx.x & 63;
    if (d >= N_NODES) return;
    const int beg = g_rowptr[d];
    const int end = g_rowptr[d + 1];

    float4 acc = make_float4(0.f, 0.f, 0.f, 0.f);
    int e = beg;
    for (; e + 1 < end; e += 2) {
        int s0 = __ldg(&g_esrc[e]);
        int s1 = __ldg(&g_esrc[e + 1]);
        float w0 = __ldg(&g_dinv[s0]);
        float w1 = __ldg(&g_dinv[s1]);
        float4 v0 = __ldg((const float4*)(h + (size_t)s0 * HID_DIM) + q);
        float4 v1 = __ldg((const float4*)(h + (size_t)s1 * HID_DIM) + q);
        acc.x += w0 * v0.x + w1 * v1.x;
        acc.y += w0 * v0.y + w1 * v1.y;
        acc.z += w0 * v0.z + w1 * v1.z;
        acc.w += w0 * v0.w + w1 * v1.w;
    }
    if (e < end) {
        int s0 = __ldg(&g_esrc[e]);
        float w0 = __ldg(&g_dinv[s0]);
        float4 v0 = __ldg((const float4*)(h + (size_t)s0 * HID_DIM) + q);
        acc.x += w0 * v0.x;
        acc.y += w0 * v0.y;
        acc.z += w0 * v0.z;
        acc.w += w0 * v0.w;
    }

    float di = g_dinv[d];
    float sw = di * di;
    float4 self = __ldg((const float4*)(h + (size_t)d * HID_DIM) + q);
    float4 bias = __ldg((const float4*)b1 + q);
    float4 r;
    r.x = fmaxf(di * acc.x + sw * self.x + bias.x, 0.f);
    r.y = fmaxf(di * acc.y + sw * self.y + bias.y, 0.f);
    r.z = fmaxf(di * acc.z + sw * self.z + bias.z, 0.f);
    r.w = fmaxf(di * acc.w + sw * self.w + bias.w, 0.f);
    ((float4*)(out + (size_t)d * HID_DIM))[q] = r;
}

// ------------------------------------------------------------------
// Layer-2 aggregation + bias + log_softmax (warp per node, float2 lanes)
// ------------------------------------------------------------------
__global__ void spmm_softmax64(const float* __restrict__ h, float* __restrict__ out,
                               const float* __restrict__ b2) {
    const int node = (blockIdx.x * blockDim.x + threadIdx.x) >> 5;
    const int lane = threadIdx.x & 31;
    if (node >= N_NODES) return;

    const int beg = g_rowptr[node];
    const int end = g_rowptr[node + 1];

    float a0 = 0.f, a1 = 0.f;
    int e = beg;
    for (; e + 1 < end; e += 2) {
        int s0 = __ldg(&g_esrc[e]);
        int s1 = __ldg(&g_esrc[e + 1]);
        float w0 = __ldg(&g_dinv[s0]);
        float w1 = __ldg(&g_dinv[s1]);
        float2 v0 = __ldg((const float2*)(h + (size_t)s0 * OUT_DIM) + lane);
        float2 v1 = __ldg((const float2*)(h + (size_t)s1 * OUT_DIM) + lane);
        a0 += w0 * v0.x + w1 * v1.x;
        a1 += w0 * v0.y + w1 * v1.y;
    }
    if (e < end) {
        int s0 = __ldg(&g_esrc[e]);
        float w0 = __ldg(&g_dinv[s0]);
        float2 v0 = __ldg((const float2*)(h + (size_t)s0 * OUT_DIM) + lane);
        a0 += w0 * v0.x;
        a1 += w0 * v0.y;
    }

    float di = g_dinv[node];
    float sw = di * di;
    float2 self = __ldg((const float2*)(h + (size_t)node * OUT_DIM) + lane);
    float2 bias = __ldg((const float2*)b2 + lane);
    float v0 = di * a0 + sw * self.x + bias.x;
    float v1 = di * a1 + sw * self.y + bias.y;

    float m = fmaxf(v0, v1);
#pragma unroll
    for (int o = 16; o; o >>= 1) m = fmaxf(m, __shfl_xor_sync(0xFFFFFFFFu, m, o));
    float s = expf(v0 - m) + expf(v1 - m);
#pragma unroll
    for (int o = 16; o; o >>= 1) s += __shfl_xor_sync(0xFFFFFFFFu, s, o);
    float ls = m + logf(s);

    ((float2*)(out + (size_t)node * OUT_DIM))[lane] = make_float2(v0 - ls, v1 - ls);
}

// ------------------------------------------------------------------
extern "C" void kernel_launch(void* const* d_in, const int* in_sizes, int n_in,
                              void* d_out, int out_size) {
    const float* x  = (const float*)d_in[0];
    const float* W1 = (const float*)d_in[1];
    const float* b1 = (const float*)d_in[2];
    const float* W2 = (const float*)d_in[3];
    const float* b2 = (const float*)d_in[4];
    const int* ei   = (const int*)d_in[5];
    const int E = in_sizes[5] / 2;
    const int* src = ei;
    const int* dst = ei + E;
    float* out = (float*)d_out;

    float *h1, *a1, *h2;
    int* cntp;
    cudaGetSymbolAddress((void**)&h1, g_h1);
    cudaGetSymbolAddress((void**)&a1, g_a1);
    cudaGetSymbolAddress((void**)&h2, g_h2);
    cudaGetSymbolAddress((void**)&cntp, g_cnt);

    const int TB = 256;

    // ---- CSR build ----
    cudaMemsetAsync(cntp, 0, N_NODES * sizeof(int), 0);
    count_kernel<<<(E + TB - 1) / TB, TB>>>(dst, E);
    scan1_kernel<<<SCAN_NBLK, SCAN_TB>>>();       // also computes dinv
    scan2_kernel<<<1, SCAN_TB>>>();
    scan3_kernel<<<SCAN_NBLK, SCAN_TB>>>();
    fill_kernel<<<(E + TB - 1) / TB, TB>>>(src, dst, E);

    // ---- layer 1 ----
    gemm_tf32_mma<<<dim3(HID_DIM / 128, (N_NODES + 127) / 128), 256>>>(
        x, W1, h1, N_NODES, HID_DIM, IN_DIM);
    spmm_relu256<<<(N_NODES + 3) / 4, 256>>>(h1, a1, b1);

    // ---- layer 2 ----
    gemm2_tf32_mma<<<(N_NODES + 127) / 128, 256>>>(a1, W2, h2, N_NODES);
    spmm_softmax64<<<(N_NODES * 32 + TB - 1) / TB, TB>>>(h2, out, b2);
}

// round 9
// speedup vs baseline: 4.9942x; 1.0946x over previous
#include <cuda_runtime.h>
#include <cstdint>

#define N_NODES 50000
#define IN_DIM  512
#define HID_DIM 256
#define OUT_DIM 64
#define EDGE_CAP 1700000

#define SCAN_TB 256
#define SCAN_NBLK ((N_NODES + SCAN_TB - 1) / SCAN_TB)   // 196

// ---- scratch (no allocations allowed) ----
__device__ int      g_cnt[N_NODES];
__device__ int      g_rowptr[N_NODES + 1];
__device__ int      g_fill[N_NODES];
__device__ int      g_esrc[EDGE_CAP];
__device__ int      g_part[SCAN_NBLK];
__device__ float    g_dinv[N_NODES];
__device__ uint32_t g_h1b[(size_t)N_NODES * (HID_DIM / 2)];  // bf16x2 packed
__device__ float    g_a1[(size_t)N_NODES * HID_DIM];
__device__ uint32_t g_h2b[(size_t)N_NODES * (OUT_DIM / 2)];  // bf16x2 packed

// ------------------------------------------------------------------
// bf16 helpers
// ------------------------------------------------------------------
static __device__ __forceinline__ uint32_t pack_bf162(float lo, float hi) {
    uint32_t u;
    asm("cvt.rn.bf16x2.f32 %0, %1, %2;" : "=r"(u) : "f"(hi), "f"(lo));
    return u;
}
static __device__ __forceinline__ float bf_lo(uint32_t u) {
    return __uint_as_float(u << 16);
}
static __device__ __forceinline__ float bf_hi(uint32_t u) {
    return __uint_as_float(u & 0xFFFF0000u);
}

// ------------------------------------------------------------------
// CSR build
// ------------------------------------------------------------------
__global__ void count_kernel(const int* __restrict__ dst, int E) {
    int i = blockIdx.x * blockDim.x + threadIdx.x;
    if (i < E) atomicAdd(&g_cnt[dst[i]], 1);
}

__global__ void scan1_kernel() {   // block sums + dinv (fused)
    __shared__ int s[SCAN_TB];
    int t = threadIdx.x;
    int i = blockIdx.x * SCAN_TB + t;
    int v = 0;
    if (i < N_NODES) {
        v = g_cnt[i];
        g_dinv[i] = rsqrtf((float)v + 1.0f);
    }
    s[t] = v;
    __syncthreads();
    for (int off = SCAN_TB / 2; off > 0; off >>= 1) {
        if (t < off) s[t] += s[t + off];
        __syncthreads();
    }
    if (t == 0) g_part[blockIdx.x] = s[0];
}

__global__ void scan2_kernel() {
    __shared__ int s[SCAN_TB];
    int t = threadIdx.x;
    int v = (t < SCAN_NBLK) ? g_part[t] : 0;
    s[t] = v;
    __syncthreads();
    for (int off = 1; off < SCAN_TB; off <<= 1) {
        int u = (t >= off) ? s[t - off] : 0;
        __syncthreads();
        s[t] += u;
        __syncthreads();
    }
    if (t < SCAN_NBLK) g_part[t] = s[t] - v;
    if (t == SCAN_TB - 1) g_rowptr[N_NODES] = s[SCAN_TB - 1];
}

__global__ void scan3_kernel() {
    __shared__ int s[SCAN_TB];
    int t = threadIdx.x;
    int i = blockIdx.x * SCAN_TB + t;
    int v = (i < N_NODES) ? g_cnt[i] : 0;
    s[t] = v;
    __syncthreads();
    for (int off = 1; off < SCAN_TB; off <<= 1) {
        int u = (t >= off) ? s[t - off] : 0;
        __syncthreads();
        s[t] += u;
        __syncthreads();
    }
    if (i < N_NODES) {
        int excl = g_part[blockIdx.x] + s[t] - v;
        g_rowptr[i] = excl;
        g_fill[i]   = excl;
    }
}

__global__ void fill_kernel(const int* __restrict__ src, const int* __restrict__ dst, int E) {
    int i = blockIdx.x * blockDim.x + threadIdx.x;
    if (i < E) {
        int d = dst[i];
        int pos = atomicAdd(&g_fill[d], 1);
        g_esrc[pos] = src[i];
    }
}

// ------------------------------------------------------------------
// tf32 helpers
// ------------------------------------------------------------------
static __device__ __forceinline__ uint32_t f2tf32(float x) {
    uint32_t u;
    asm("cvt.rna.tf32.f32 %0, %1;" : "=r"(u) : "f"(x));
    return u;
}

#define ASTRIDE 20   // 16 + 4 pad
#define BSTRIDE 132  // 128 + 4 pad

// ------------------------------------------------------------------
// GEMM1: tf32 mma.sync, CTA 128x128, BK=16, warp tile 32x64,
// double-buffered. Output packed bf16x2. (N=256, K=512)
// ------------------------------------------------------------------
__global__ void __launch_bounds__(256, 2)
gemm_tf32_mma(const float* __restrict__ A, const float* __restrict__ B,
              uint32_t* __restrict__ Cb, int M, int N, int K) {
    __shared__ float As[2][128][ASTRIDE];
    __shared__ float Bs[2][16][BSTRIDE];

    const int tid  = threadIdx.x;
    const int lane = tid & 31;
    const int w    = tid >> 5;
    const int wm   = w >> 1;
    const int wn   = w & 1;
    const int g    = lane >> 2;
    const int t4   = lane & 3;

    const int row0 = blockIdx.y * 128;
    const int col0 = blockIdx.x * 128;

    const int ar = tid >> 1;
    const int ak = (tid & 1) * 8;
    const int bk = tid >> 4;
    const int bn = (tid & 15) * 8;

    const int gm = row0 + ar;
    const float* aptr = A + (size_t)gm * K + ak;
    const float* bptr = B + (size_t)bk * N + col0 + bn;

    float c[2][8][4];
#pragma unroll
    for (int mt = 0; mt < 2; mt++)
#pragma unroll
        for (int nt = 0; nt < 8; nt++)
#pragma unroll
            for (int q = 0; q < 4; q++) c[mt][nt][q] = 0.f;

    float4 pa0 = make_float4(0.f, 0.f, 0.f, 0.f), pa1 = pa0;
    if (gm < M) { pa0 = *(const float4*)(aptr); pa1 = *(const float4*)(aptr + 4); }
    float4 pb0 = *(const float4*)(bptr);
    float4 pb1 = *(const float4*)(bptr + 4);
    {
        float* as = &As[0][ar][ak];
        as[0] = __uint_as_float(f2tf32(pa0.x)); as[1] = __uint_as_float(f2tf32(pa0.y));
        as[2] = __uint_as_float(f2tf32(pa0.z)); as[3] = __uint_as_float(f2tf32(pa0.w));
        as[4] = __uint_as_float(f2tf32(pa1.x)); as[5] = __uint_as_float(f2tf32(pa1.y));
        as[6] = __uint_as_float(f2tf32(pa1.z)); as[7] = __uint_as_float(f2tf32(pa1.w));
        float* bs = &Bs[0][bk][bn];
        bs[0] = __uint_as_float(f2tf32(pb0.x)); bs[1] = __uint_as_float(f2tf32(pb0.y));
        bs[2] = __uint_as_float(f2tf32(pb0.z)); bs[3] = __uint_as_float(f2tf32(pb0.w));
        bs[4] = __uint_as_float(f2tf32(pb1.x)); bs[5] = __uint_as_float(f2tf32(pb1.y));
        bs[6] = __uint_as_float(f2tf32(pb1.z)); bs[7] = __uint_as_float(f2tf32(pb1.w));
    }
    __syncthreads();

    int buf = 0;
    for (int k0 = 0; k0 < K; k0 += 16) {
        const bool has_next = (k0 + 16) < K;
        if (has_next) {
            if (gm < M) {
                pa0 = *(const float4*)(aptr + k0 + 16);
                pa1 = *(const float4*)(aptr + k0 + 16 + 4);
            }
            pb0 = *(const float4*)(bptr + (size_t)(k0 + 16) * N);
            pb1 = *(const float4*)(bptr + (size_t)(k0 + 16) * N + 4);
        }

#pragma unroll
        for (int kk = 0; kk < 16; kk += 8) {
            uint32_t af[2][4];
#pragma unroll
            for (int mt = 0; mt < 2; mt++) {
                int rm = wm * 32 + mt * 16;
                af[mt][0] = __float_as_uint(As[buf][rm + g][kk + t4]);
                af[mt][1] = __float_as_uint(As[buf][rm + 8 + g][kk + t4]);
                af[mt][2] = __float_as_uint(As[buf][rm + g][kk + 4 + t4]);
                af[mt][3] = __float_as_uint(As[buf][rm + 8 + g][kk + 4 + t4]);
            }
#pragma unroll
            for (int nt = 0; nt < 8; nt++) {
                int nb = wn * 64 + nt * 8;
                uint32_t b0 = __float_as_uint(Bs[buf][kk + t4][nb + g]);
                uint32_t b1 = __float_as_uint(Bs[buf][kk + 4 + t4][nb + g]);
#pragma unroll
                for (int mt = 0; mt < 2; mt++) {
                    asm volatile(
                        "mma.sync.aligned.m16n8k8.row.col.f32.tf32.tf32.f32 "
                        "{%0,%1,%2,%3}, {%4,%5,%6,%7}, {%8,%9}, {%0,%1,%2,%3};"
                        : "+f"(c[mt][nt][0]), "+f"(c[mt][nt][1]),
                          "+f"(c[mt][nt][2]), "+f"(c[mt][nt][3])
                        : "r"(af[mt][0]), "r"(af[mt][1]), "r"(af[mt][2]), "r"(af[mt][3]),
                          "r"(b0), "r"(b1));
                }
            }
        }

        if (has_next) {
            const int nb = buf ^ 1;
            float* as = &As[nb][ar][ak];
            as[0] = __uint_as_float(f2tf32(pa0.x)); as[1] = __uint_as_float(f2tf32(pa0.y));
            as[2] = __uint_as_float(f2tf32(pa0.z)); as[3] = __uint_as_float(f2tf32(pa0.w));
            as[4] = __uint_as_float(f2tf32(pa1.x)); as[5] = __uint_as_float(f2tf32(pa1.y));
            as[6] = __uint_as_float(f2tf32(pa1.z)); as[7] = __uint_as_float(f2tf32(pa1.w));
            float* bs = &Bs[nb][bk][bn];
            bs[0] = __uint_as_float(f2tf32(pb0.x)); bs[1] = __uint_as_float(f2tf32(pb0.y));
            bs[2] = __uint_as_float(f2tf32(pb0.z)); bs[3] = __uint_as_float(f2tf32(pb0.w));
            bs[4] = __uint_as_float(f2tf32(pb1.x)); bs[5] = __uint_as_float(f2tf32(pb1.y));
            bs[6] = __uint_as_float(f2tf32(pb1.z)); bs[7] = __uint_as_float(f2tf32(pb1.w));
            __syncthreads();
            buf = nb;
        }
    }

    // epilogue: pack adjacent column pairs to bf16x2
#pragma unroll
    for (int mt = 0; mt < 2; mt++) {
#pragma unroll
        for (int nt = 0; nt < 8; nt++) {
            int rbase = row0 + wm * 32 + mt * 16 + g;
            int cpair = (col0 + wn * 64 + nt * 8 + 2 * t4) >> 1;
            if (rbase < M)
                Cb[(size_t)rbase * (N / 2) + cpair] = pack_bf162(c[mt][nt][0], c[mt][nt][1]);
            if (rbase + 8 < M)
                Cb[(size_t)(rbase + 8) * (N / 2) + cpair] = pack_bf162(c[mt][nt][2], c[mt][nt][3]);
        }
    }
}

// ------------------------------------------------------------------
// GEMM2: tf32 mma.sync, CTA 128x64, warp tile 32x32 (N=64,K=256)
// Output packed bf16x2.
// ------------------------------------------------------------------
#define B2STRIDE 68  // 64 + 4 pad

__global__ void __launch_bounds__(256, 2)
gemm2_tf32_mma(const float* __restrict__ A, const float* __restrict__ B,
               uint32_t* __restrict__ Cb, int M) {
    const int N = OUT_DIM, K = HID_DIM;
    __shared__ float As[128][ASTRIDE];
    __shared__ float Bs[16][B2STRIDE];

    const int tid  = threadIdx.x;
    const int lane = tid & 31;
    const int w    = tid >> 5;
    const int wm   = w >> 1;
    const int wn   = w & 1;
    const int g    = lane >> 2;
    const int t4   = lane & 3;

    const int row0 = blockIdx.x * 128;

    const int ar = tid >> 1;
    const int ak = (tid & 1) * 8;
    const int bk = tid >> 4;
    const int bn = (tid & 15) * 4;

    float c[2][4][4];
#pragma unroll
    for (int mt = 0; mt < 2; mt++)
#pragma unroll
        for (int nt = 0; nt < 4; nt++)
#pragma unroll
            for (int q = 0; q < 4; q++) c[mt][nt][q] = 0.f;

    for (int k0 = 0; k0 < K; k0 += 16) {
        {
            int gm = row0 + ar;
            float4 v0 = make_float4(0.f, 0.f, 0.f, 0.f);
            float4 v1 = make_float4(0.f, 0.f, 0.f, 0.f);
            if (gm < M) {
                const float* ap = A + (size_t)gm * K + k0 + ak;
                v0 = *(const float4*)(ap);
                v1 = *(const float4*)(ap + 4);
            }
            As[ar][ak + 0] = __uint_as_float(f2tf32(v0.x));
            As[ar][ak + 1] = __uint_as_float(f2tf32(v0.y));
            As[ar][ak + 2] = __uint_as_float(f2tf32(v0.z));
            As[ar][ak + 3] = __uint_as_float(f2tf32(v0.w));
            As[ar][ak + 4] = __uint_as_float(f2tf32(v1.x));
            As[ar][ak + 5] = __uint_as_float(f2tf32(v1.y));
            As[ar][ak + 6] = __uint_as_float(f2tf32(v1.z));
            As[ar][ak + 7] = __uint_as_float(f2tf32(v1.w));
        }
        {
            const float* bp = B + (size_t)(k0 + bk) * N + bn;
            float4 v0 = *(const float4*)(bp);
            Bs[bk][bn + 0] = __uint_as_float(f2tf32(v0.x));
            Bs[bk][bn + 1] = __uint_as_float(f2tf32(v0.y));
            Bs[bk][bn + 2] = __uint_as_float(f2tf32(v0.z));
            Bs[bk][bn + 3] = __uint_as_float(f2tf32(v0.w));
        }
        __syncthreads();

#pragma unroll
        for (int kk = 0; kk < 16; kk += 8) {
            uint32_t af[2][4];
#pragma unroll
            for (int mt = 0; mt < 2; mt++) {
                int rm = wm * 32 + mt * 16;
                af[mt][0] = __float_as_uint(As[rm + g][kk + t4]);
                af[mt][1] = __float_as_uint(As[rm + 8 + g][kk + t4]);
                af[mt][2] = __float_as_uint(As[rm + g][kk + 4 + t4]);
                af[mt][3] = __float_as_uint(As[rm + 8 + g][kk + 4 + t4]);
            }
#pragma unroll
            for (int nt = 0; nt < 4; nt++) {
                int nb = wn * 32 + nt * 8;
                uint32_t b0 = __float_as_uint(Bs[kk + t4][nb + g]);
                uint32_t b1 = __float_as_uint(Bs[kk + 4 + t4][nb + g]);
#pragma unroll
                for (int mt = 0; mt < 2; mt++) {
                    asm volatile(
                        "mma.sync.aligned.m16n8k8.row.col.f32.tf32.tf32.f32 "
                        "{%0,%1,%2,%3}, {%4,%5,%6,%7}, {%8,%9}, {%0,%1,%2,%3};"
                        : "+f"(c[mt][nt][0]), "+f"(c[mt][nt][1]),
                          "+f"(c[mt][nt][2]), "+f"(c[mt][nt][3])
                        : "r"(af[mt][0]), "r"(af[mt][1]), "r"(af[mt][2]), "r"(af[mt][3]),
                          "r"(b0), "r"(b1));
                }
            }
        }
        __syncthreads();
    }

#pragma unroll
    for (int mt = 0; mt < 2; mt++) {
#pragma unroll
        for (int nt = 0; nt < 4; nt++) {
            int rbase = row0 + wm * 32 + mt * 16 + g;
            int cpair = (wn * 32 + nt * 8 + 2 * t4) >> 1;
            if (rbase < M)
                Cb[(size_t)rbase * (N / 2) + cpair] = pack_bf162(c[mt][nt][0], c[mt][nt][1]);
            if (rbase + 8 < M)
                Cb[(size_t)(rbase + 8) * (N / 2) + cpair] = pack_bf162(c[mt][nt][2], c[mt][nt][3]);
        }
    }
}

// ------------------------------------------------------------------
// Layer-1 aggregation (bf16 gather) + self + bias + relu -> fp32 a1
// Warp per node; lane handles 8 features (one uint4 = 4 bf16x2).
// ------------------------------------------------------------------
__global__ void spmm_relu_bf16(const uint32_t* __restrict__ h, float* __restrict__ out,
                               const float* __restrict__ b1) {
    const int node = (blockIdx.x * blockDim.x + threadIdx.x) >> 5;
    const int lane = threadIdx.x & 31;
    if (node >= N_NODES) return;
    const int beg = g_rowptr[node];
    const int end = g_rowptr[node + 1];

    float acc[8] = {};
    int e = beg;
    for (; e + 1 < end; e += 2) {
        int s0 = __ldg(&g_esrc[e]);
        int s1 = __ldg(&g_esrc[e + 1]);
        float w0 = __ldg(&g_dinv[s0]);
        float w1 = __ldg(&g_dinv[s1]);
        uint4 v0 = __ldg((const uint4*)(h + (size_t)s0 * (HID_DIM / 2)) + lane);
        uint4 v1 = __ldg((const uint4*)(h + (size_t)s1 * (HID_DIM / 2)) + lane);
        acc[0] += w0 * bf_lo(v0.x) + w1 * bf_lo(v1.x);
        acc[1] += w0 * bf_hi(v0.x) + w1 * bf_hi(v1.x);
        acc[2] += w0 * bf_lo(v0.y) + w1 * bf_lo(v1.y);
        acc[3] += w0 * bf_hi(v0.y) + w1 * bf_hi(v1.y);
        acc[4] += w0 * bf_lo(v0.z) + w1 * bf_lo(v1.z);
        acc[5] += w0 * bf_hi(v0.z) + w1 * bf_hi(v1.z);
        acc[6] += w0 * bf_lo(v0.w) + w1 * bf_lo(v1.w);
        acc[7] += w0 * bf_hi(v0.w) + w1 * bf_hi(v1.w);
    }
    if (e < end) {
        int s0 = __ldg(&g_esrc[e]);
        float w0 = __ldg(&g_dinv[s0]);
        uint4 v0 = __ldg((const uint4*)(h + (size_t)s0 * (HID_DIM / 2)) + lane);
        acc[0] += w0 * bf_lo(v0.x); acc[1] += w0 * bf_hi(v0.x);
        acc[2] += w0 * bf_lo(v0.y); acc[3] += w0 * bf_hi(v0.y);
        acc[4] += w0 * bf_lo(v0.z); acc[5] += w0 * bf_hi(v0.z);
        acc[6] += w0 * bf_lo(v0.w); acc[7] += w0 * bf_hi(v0.w);
    }

    float di = g_dinv[node];
    float sw = di * di;
    uint4 sv = __ldg((const uint4*)(h + (size_t)node * (HID_DIM / 2)) + lane);
    float4 bia0 = __ldg((const float4*)b1 + 2 * lane);
    float4 bia1 = __ldg((const float4*)b1 + 2 * lane + 1);

    float4 r0, r1;
    r0.x = fmaxf(di * acc[0] + sw * bf_lo(sv.x) + bia0.x, 0.f);
    r0.y = fmaxf(di * acc[1] + sw * bf_hi(sv.x) + bia0.y, 0.f);
    r0.z = fmaxf(di * acc[2] + sw * bf_lo(sv.y) + bia0.z, 0.f);
    r0.w = fmaxf(di * acc[3] + sw * bf_hi(sv.y) + bia0.w, 0.f);
    r1.x = fmaxf(di * acc[4] + sw * bf_lo(sv.z) + bia1.x, 0.f);
    r1.y = fmaxf(di * acc[5] + sw * bf_hi(sv.z) + bia1.y, 0.f);
    r1.z = fmaxf(di * acc[6] + sw * bf_lo(sv.w) + bia1.z, 0.f);
    r1.w = fmaxf(di * acc[7] + sw * bf_hi(sv.w) + bia1.w, 0.f);

    float4* op = (float4*)(out + (size_t)node * HID_DIM) + 2 * lane;
    op[0] = r0;
    op[1] = r1;
}

// ------------------------------------------------------------------
// Layer-2 aggregation (bf16 gather) + bias + log_softmax
// Warp per node; lane handles cols 2*lane, 2*lane+1 (one uint32).
// ------------------------------------------------------------------
__global__ void spmm_softmax_bf16(const uint32_t* __restrict__ h, float* __restrict__ out,
                                  const float* __restrict__ b2) {
    const int node = (blockIdx.x * blockDim.x + threadIdx.x) >> 5;
    const int lane = threadIdx.x & 31;
    if (node >= N_NODES) return;

    const int beg = g_rowptr[node];
    const int end = g_rowptr[node + 1];

    float a0 = 0.f, a1 = 0.f;
    int e = beg;
    for (; e + 1 < end; e += 2) {
        int s0 = __ldg(&g_esrc[e]);
        int s1 = __ldg(&g_esrc[e + 1]);
        float w0 = __ldg(&g_dinv[s0]);
        float w1 = __ldg(&g_dinv[s1]);
        uint32_t v0 = __ldg(h + (size_t)s0 * (OUT_DIM / 2) + lane);
        uint32_t v1 = __ldg(h + (size_t)s1 * (OUT_DIM / 2) + lane);
        a0 += w0 * bf_lo(v0) + w1 * bf_lo(v1);
        a1 += w0 * bf_hi(v0) + w1 * bf_hi(v1);
    }
    if (e < end) {
        int s0 = __ldg(&g_esrc[e]);
        float w0 = __ldg(&g_dinv[s0]);
        uint32_t v0 = __ldg(h + (size_t)s0 * (OUT_DIM / 2) + lane);
        a0 += w0 * bf_lo(v0);
        a1 += w0 * bf_hi(v0);
    }

    float di = g_dinv[node];
    float sw = di * di;
    uint32_t sv = __ldg(h + (size_t)node * (OUT_DIM / 2) + lane);
    float2 bias = __ldg((const float2*)b2 + lane);
    float v0 = di * a0 + sw * bf_lo(sv) + bias.x;
    float v1 = di * a1 + sw * bf_hi(sv) + bias.y;

    float m = fmaxf(v0, v1);
#pragma unroll
    for (int o = 16; o; o >>= 1) m = fmaxf(m, __shfl_xor_sync(0xFFFFFFFFu, m, o));
    float s = expf(v0 - m) + expf(v1 - m);
#pragma unroll
    for (int o = 16; o; o >>= 1) s += __shfl_xor_sync(0xFFFFFFFFu, s, o);
    float ls = m + logf(s);

    ((float2*)(out + (size_t)node * OUT_DIM))[lane] = make_float2(v0 - ls, v1 - ls);
}

// ------------------------------------------------------------------
extern "C" void kernel_launch(void* const* d_in, const int* in_sizes, int n_in,
                              void* d_out, int out_size) {
    const float* x  = (const float*)d_in[0];
    const float* W1 = (const float*)d_in[1];
    const float* b1 = (const float*)d_in[2];
    const float* W2 = (const float*)d_in[3];
    const float* b2 = (const float*)d_in[4];
    const int* ei   = (const int*)d_in[5];
    const int E = in_sizes[5] / 2;
    const int* src = ei;
    const int* dst = ei + E;
    float* out = (float*)d_out;

    uint32_t *h1b, *h2b;
    float* a1;
    int* cntp;
    cudaGetSymbolAddress((void**)&h1b, g_h1b);
    cudaGetSymbolAddress((void**)&a1, g_a1);
    cudaGetSymbolAddress((void**)&h2b, g_h2b);
    cudaGetSymbolAddress((void**)&cntp, g_cnt);

    const int TB = 256;

    // ---- CSR build ----
    cudaMemsetAsync(cntp, 0, N_NODES * sizeof(int), 0);
    count_kernel<<<(E + TB - 1) / TB, TB>>>(dst, E);
    scan1_kernel<<<SCAN_NBLK, SCAN_TB>>>();       // also computes dinv
    scan2_kernel<<<1, SCAN_TB>>>();
    scan3_kernel<<<SCAN_NBLK, SCAN_TB>>>();
    fill_kernel<<<(E + TB - 1) / TB, TB>>>(src, dst, E);

    // ---- layer 1 ----
    gemm_tf32_mma<<<dim3(HID_DIM / 128, (N_NODES + 127) / 128), 256>>>(
        x, W1, h1b, N_NODES, HID_DIM, IN_DIM);
    spmm_relu_bf16<<<(N_NODES * 32 + TB - 1) / TB, TB>>>(h1b, a1, b1);

    // ---- layer 2 ----
    gemm2_tf32_mma<<<(N_NODES + 127) / 128, 256>>>(a1, W2, h2b, N_NODES);
    spmm_softmax_bf16<<<(N_NODES * 32 + TB - 1) / TB, TB>>>(h2b, out, b2);
}

// round 10
// speedup vs baseline: 5.1455x; 1.0303x over previous
#include <cuda_runtime.h>
#include <cstdint>

#define N_NODES 50000
#define IN_DIM  512
#define HID_DIM 256
#define OUT_DIM 64
#define EDGE_CAP 1700000

#define SCAN_TB 256
#define SCAN_NBLK ((N_NODES + SCAN_TB - 1) / SCAN_TB)   // 196

// ---- scratch (no allocations allowed) ----
__device__ int      g_cnt[N_NODES];
__device__ int      g_rowptr[N_NODES + 1];
__device__ int      g_fill[N_NODES];
__device__ int      g_esrc[EDGE_CAP];
__device__ int      g_part[SCAN_NBLK];
__device__ float    g_dinv[N_NODES];
__device__ uint32_t g_h1b[(size_t)N_NODES * (HID_DIM / 2)];  // bf16x2 packed
__device__ float    g_a1[(size_t)N_NODES * HID_DIM];
__device__ uint32_t g_h2b[(size_t)N_NODES * (OUT_DIM / 2)];  // bf16x2 packed

// ------------------------------------------------------------------
// helpers
// ------------------------------------------------------------------
static __device__ __forceinline__ uint32_t pack_bf162(float lo, float hi) {
    uint32_t u;
    asm("cvt.rn.bf16x2.f32 %0, %1, %2;" : "=r"(u) : "f"(hi), "f"(lo));
    return u;
}
static __device__ __forceinline__ float bf_lo(uint32_t u) {
    return __uint_as_float(u << 16);
}
static __device__ __forceinline__ float bf_hi(uint32_t u) {
    return __uint_as_float(u & 0xFFFF0000u);
}
static __device__ __forceinline__ uint32_t f2tf32(float x) {
    uint32_t u;
    asm("cvt.rna.tf32.f32 %0, %1;" : "=r"(u) : "f"(x));
    return u;
}
static __device__ __forceinline__ uint32_t smem_u32(const void* p) {
    return (uint32_t)__cvta_generic_to_shared(p);
}
static __device__ __forceinline__ void cp_async16(uint32_t dst, const void* src, int src_bytes) {
    asm volatile("cp.async.ca.shared.global [%0], [%1], 16, %2;"
                 :: "r"(dst), "l"(src), "r"(src_bytes));
}
#define CP_COMMIT() asm volatile("cp.async.commit_group;" ::: "memory")
#define CP_WAIT1()  asm volatile("cp.async.wait_group 1;" ::: "memory")

// ------------------------------------------------------------------
// CSR build
// ------------------------------------------------------------------
__global__ void count_kernel(const int* __restrict__ dst, int E) {
    int i = blockIdx.x * blockDim.x + threadIdx.x;
    if (i < E) atomicAdd(&g_cnt[dst[i]], 1);
}

__global__ void scan1_kernel() {   // block sums + dinv (fused)
    __shared__ int s[SCAN_TB];
    int t = threadIdx.x;
    int i = blockIdx.x * SCAN_TB + t;
    int v = 0;
    if (i < N_NODES) {
        v = g_cnt[i];
        g_dinv[i] = rsqrtf((float)v + 1.0f);
    }
    s[t] = v;
    __syncthreads();
    for (int off = SCAN_TB / 2; off > 0; off >>= 1) {
        if (t < off) s[t] += s[t + off];
        __syncthreads();
    }
    if (t == 0) g_part[blockIdx.x] = s[0];
}

__global__ void scan2_kernel() {
    __shared__ int s[SCAN_TB];
    int t = threadIdx.x;
    int v = (t < SCAN_NBLK) ? g_part[t] : 0;
    s[t] = v;
    __syncthreads();
    for (int off = 1; off < SCAN_TB; off <<= 1) {
        int u = (t >= off) ? s[t - off] : 0;
        __syncthreads();
        s[t] += u;
        __syncthreads();
    }
    if (t < SCAN_NBLK) g_part[t] = s[t] - v;
    if (t == SCAN_TB - 1) g_rowptr[N_NODES] = s[SCAN_TB - 1];
}

__global__ void scan3_kernel() {
    __shared__ int s[SCAN_TB];
    int t = threadIdx.x;
    int i = blockIdx.x * SCAN_TB + t;
    int v = (i < N_NODES) ? g_cnt[i] : 0;
    s[t] = v;
    __syncthreads();
    for (int off = 1; off < SCAN_TB; off <<= 1) {
        int u = (t >= off) ? s[t - off] : 0;
        __syncthreads();
        s[t] += u;
        __syncthreads();
    }
    if (i < N_NODES) {
        int excl = g_part[blockIdx.x] + s[t] - v;
        g_rowptr[i] = excl;
        g_fill[i]   = excl;
    }
}

__global__ void fill_kernel(const int* __restrict__ src, const int* __restrict__ dst, int E) {
    int i = blockIdx.x * blockDim.x + threadIdx.x;
    if (i < E) {
        int d = dst[i];
        int pos = atomicAdd(&g_fill[d], 1);
        g_esrc[pos] = src[i];
    }
}

// ------------------------------------------------------------------
// GEMM1: tf32 mma.sync, CTA 128x128, BK=16, warp tile 32x64.
// 3-stage cp.async pipeline; cvt to tf32 at fragment read.
// Output packed bf16x2. (N=256, K=512)
// ------------------------------------------------------------------
#define ASTRIDE 20    // 16 + 4 pad (80B rows, 16B aligned)
#define BSTRIDE 132   // 128 + 4 pad (528B rows, 16B aligned)
#define A_ELEMS (128 * ASTRIDE)
#define B_ELEMS (16 * BSTRIDE)
#define G1_SMEM ((3 * A_ELEMS + 3 * B_ELEMS) * 4)   // 56064 bytes

__global__ void __launch_bounds__(256)
gemm_tf32_mma(const float* __restrict__ A, const float* __restrict__ B,
              uint32_t* __restrict__ Cb, int M, int N, int K) {
    extern __shared__ float sm[];
    float* Asb = sm;                     // [3][128][ASTRIDE]
    float* Bsb = sm + 3 * A_ELEMS;       // [3][16][BSTRIDE]

    const int tid  = threadIdx.x;
    const int lane = tid & 31;
    const int w    = tid >> 5;
    const int wm   = w >> 1;
    const int wn   = w & 1;
    const int g    = lane >> 2;
    const int t4   = lane & 3;

    const int row0 = blockIdx.y * 128;
    const int col0 = blockIdx.x * 128;

    const int ar = tid >> 1;
    const int ak = (tid & 1) * 8;
    const int bk = tid >> 4;
    const int bn = (tid & 15) * 8;

    const int gm = row0 + ar;
    const int asz = (gm < M) ? 16 : 0;
    const float* aptr = A + (size_t)(gm < M ? gm : 0) * K + ak;
    const float* bptr = B + (size_t)bk * N + col0 + bn;

    const uint32_t a_dst0 = smem_u32(Asb + ar * ASTRIDE + ak);
    const uint32_t b_dst0 = smem_u32(Bsb + bk * BSTRIDE + bn);

    float c[2][8][4];
#pragma unroll
    for (int mt = 0; mt < 2; mt++)
#pragma unroll
        for (int nt = 0; nt < 8; nt++)
#pragma unroll
            for (int q = 0; q < 4; q++) c[mt][nt][q] = 0.f;

    // prologue: stages 0 and 1
#pragma unroll
    for (int s = 0; s < 2; s++) {
        uint32_t ad = a_dst0 + s * A_ELEMS * 4;
        cp_async16(ad, aptr + s * 16, asz);
        cp_async16(ad + 16, aptr + s * 16 + 4, asz);
        uint32_t bd = b_dst0 + s * B_ELEMS * 4;
        cp_async16(bd, bptr + (size_t)(s * 16) * N, 16);
        cp_async16(bd + 16, bptr + (size_t)(s * 16) * N + 4, 16);
        CP_COMMIT();
    }
    CP_WAIT1();          // stage 0 ready
    __syncthreads();

    int buf = 0;
    for (int k0 = 0; k0 < K; k0 += 16) {
        // issue loads for k0+32 into stage (buf+2)%3
        if (k0 + 32 < K) {
            int s = buf + 2; if (s >= 3) s -= 3;
            uint32_t ad = a_dst0 + s * A_ELEMS * 4;
            cp_async16(ad, aptr + k0 + 32, asz);
            cp_async16(ad + 16, aptr + k0 + 32 + 4, asz);
            uint32_t bd = b_dst0 + s * B_ELEMS * 4;
            cp_async16(bd, bptr + (size_t)(k0 + 32) * N, 16);
            cp_async16(bd + 16, bptr + (size_t)(k0 + 32) * N + 4, 16);
        }
        CP_COMMIT();     // (possibly empty group keeps the ledger uniform)

        const float* Ab = Asb + buf * A_ELEMS;
        const float* Bb = Bsb + buf * B_ELEMS;

#pragma unroll
        for (int kk = 0; kk < 16; kk += 8) {
            uint32_t af[2][4];
#pragma unroll
            for (int mt = 0; mt < 2; mt++) {
                int rm = wm * 32 + mt * 16;
                af[mt][0] = f2tf32(Ab[(rm + g) * ASTRIDE + kk + t4]);
                af[mt][1] = f2tf32(Ab[(rm + 8 + g) * ASTRIDE + kk + t4]);
                af[mt][2] = f2tf32(Ab[(rm + g) * ASTRIDE + kk + 4 + t4]);
                af[mt][3] = f2tf32(Ab[(rm + 8 + g) * ASTRIDE + kk + 4 + t4]);
            }
#pragma unroll
            for (int nt = 0; nt < 8; nt++) {
                int nb = wn * 64 + nt * 8;
                uint32_t b0 = f2tf32(Bb[(kk + t4) * BSTRIDE + nb + g]);
                uint32_t b1 = f2tf32(Bb[(kk + 4 + t4) * BSTRIDE + nb + g]);
#pragma unroll
                for (int mt = 0; mt < 2; mt++) {
                    asm volatile(
                        "mma.sync.aligned.m16n8k8.row.col.f32.tf32.tf32.f32 "
                        "{%0,%1,%2,%3}, {%4,%5,%6,%7}, {%8,%9}, {%0,%1,%2,%3};"
                        : "+f"(c[mt][nt][0]), "+f"(c[mt][nt][1]),
                          "+f"(c[mt][nt][2]), "+f"(c[mt][nt][3])
                        : "r"(af[mt][0]), "r"(af[mt][1]), "r"(af[mt][2]), "r"(af[mt][3]),
                          "r"(b0), "r"(b1));
                }
            }
        }

        if (k0 + 16 < K) {
            CP_WAIT1();      // next stage's data landed
            __syncthreads(); // all threads done reading buf; next writes target it
        }
        buf = (buf == 2) ? 0 : buf + 1;
    }

    // epilogue: pack adjacent column pairs to bf16x2
#pragma unroll
    for (int mt = 0; mt < 2; mt++) {
#pragma unroll
        for (int nt = 0; nt < 8; nt++) {
            int rbase = row0 + wm * 32 + mt * 16 + g;
            int cpair = (col0 + wn * 64 + nt * 8 + 2 * t4) >> 1;
            if (rbase < M)
                Cb[(size_t)rbase * (N / 2) + cpair] = pack_bf162(c[mt][nt][0], c[mt][nt][1]);
            if (rbase + 8 < M)
                Cb[(size_t)(rbase + 8) * (N / 2) + cpair] = pack_bf162(c[mt][nt][2], c[mt][nt][3]);
        }
    }
}

// ------------------------------------------------------------------
// GEMM2: tf32 mma.sync, CTA 128x64, warp tile 32x32 (N=64,K=256)
// Output packed bf16x2.
// ------------------------------------------------------------------
#define B2STRIDE 68  // 64 + 4 pad

__global__ void __launch_bounds__(256, 2)
gemm2_tf32_mma(const float* __restrict__ A, const float* __restrict__ B,
               uint32_t* __restrict__ Cb, int M) {
    const int N = OUT_DIM, K = HID_DIM;
    __shared__ float As[128][ASTRIDE];
    __shared__ float Bs[16][B2STRIDE];

    const int tid  = threadIdx.x;
    const int lane = tid & 31;
    const int w    = tid >> 5;
    const int wm   = w >> 1;
    const int wn   = w & 1;
    const int g    = lane >> 2;
    const int t4   = lane & 3;

    const int row0 = blockIdx.x * 128;

    const int ar = tid >> 1;
    const int ak = (tid & 1) * 8;
    const int bk = tid >> 4;
    const int bn = (tid & 15) * 4;

    float c[2][4][4];
#pragma unroll
    for (int mt = 0; mt < 2; mt++)
#pragma unroll
        for (int nt = 0; nt < 4; nt++)
#pragma unroll
            for (int q = 0; q < 4; q++) c[mt][nt][q] = 0.f;

    for (int k0 = 0; k0 < K; k0 += 16) {
        {
            int gm = row0 + ar;
            float4 v0 = make_float4(0.f, 0.f, 0.f, 0.f);
            float4 v1 = make_float4(0.f, 0.f, 0.f, 0.f);
            if (gm < M) {
                const float* ap = A + (size_t)gm * K + k0 + ak;
                v0 = *(const float4*)(ap);
                v1 = *(const float4*)(ap + 4);
            }
            As[ar][ak + 0] = __uint_as_float(f2tf32(v0.x));
            As[ar][ak + 1] = __uint_as_float(f2tf32(v0.y));
            As[ar][ak + 2] = __uint_as_float(f2tf32(v0.z));
            As[ar][ak + 3] = __uint_as_float(f2tf32(v0.w));
            As[ar][ak + 4] = __uint_as_float(f2tf32(v1.x));
            As[ar][ak + 5] = __uint_as_float(f2tf32(v1.y));
            As[ar][ak + 6] = __uint_as_float(f2tf32(v1.z));
            As[ar][ak + 7] = __uint_as_float(f2tf32(v1.w));
        }
        {
            const float* bp = B + (size_t)(k0 + bk) * N + bn;
            float4 v0 = *(const float4*)(bp);
            Bs[bk][bn + 0] = __uint_as_float(f2tf32(v0.x));
            Bs[bk][bn + 1] = __uint_as_float(f2tf32(v0.y));
            Bs[bk][bn + 2] = __uint_as_float(f2tf32(v0.z));
            Bs[bk][bn + 3] = __uint_as_float(f2tf32(v0.w));
        }
        __syncthreads();

#pragma unroll
        for (int kk = 0; kk < 16; kk += 8) {
            uint32_t af[2][4];
#pragma unroll
            for (int mt = 0; mt < 2; mt++) {
                int rm = wm * 32 + mt * 16;
                af[mt][0] = __float_as_uint(As[rm + g][kk + t4]);
                af[mt][1] = __float_as_uint(As[rm + 8 + g][kk + t4]);
                af[mt][2] = __float_as_uint(As[rm + g][kk + 4 + t4]);
                af[mt][3] = __float_as_uint(As[rm + 8 + g][kk + 4 + t4]);
            }
#pragma unroll
            for (int nt = 0; nt < 4; nt++) {
                int nb = wn * 32 + nt * 8;
                uint32_t b0 = __float_as_uint(Bs[kk + t4][nb + g]);
                uint32_t b1 = __float_as_uint(Bs[kk + 4 + t4][nb + g]);
#pragma unroll
                for (int mt = 0; mt < 2; mt++) {
                    asm volatile(
                        "mma.sync.aligned.m16n8k8.row.col.f32.tf32.tf32.f32 "
                        "{%0,%1,%2,%3}, {%4,%5,%6,%7}, {%8,%9}, {%0,%1,%2,%3};"
                        : "+f"(c[mt][nt][0]), "+f"(c[mt][nt][1]),
                          "+f"(c[mt][nt][2]), "+f"(c[mt][nt][3])
                        : "r"(af[mt][0]), "r"(af[mt][1]), "r"(af[mt][2]), "r"(af[mt][3]),
                          "r"(b0), "r"(b1));
                }
            }
        }
        __syncthreads();
    }

#pragma unroll
    for (int mt = 0; mt < 2; mt++) {
#pragma unroll
        for (int nt = 0; nt < 4; nt++) {
            int rbase = row0 + wm * 32 + mt * 16 + g;
            int cpair = (wn * 32 + nt * 8 + 2 * t4) >> 1;
            if (rbase < M)
                Cb[(size_t)rbase * (N / 2) + cpair] = pack_bf162(c[mt][nt][0], c[mt][nt][1]);
            if (rbase + 8 < M)
                Cb[(size_t)(rbase + 8) * (N / 2) + cpair] = pack_bf162(c[mt][nt][2], c[mt][nt][3]);
        }
    }
}

// ------------------------------------------------------------------
// Layer-1 aggregation (bf16 gather, 4-edge unroll) + self+bias+relu
// Warp per node; lane handles 8 features (one uint4).
// ------------------------------------------------------------------
__global__ void spmm_relu_bf16(const uint32_t* __restrict__ h, float* __restrict__ out,
                               const float* __restrict__ b1) {
    const int node = (blockIdx.x * blockDim.x + threadIdx.x) >> 5;
    const int lane = threadIdx.x & 31;
    if (node >= N_NODES) return;
    const int beg = g_rowptr[node];
    const int end = g_rowptr[node + 1];

    float acc[8] = {};
    int e = beg;
    for (; e + 3 < end; e += 4) {
        int s0 = __ldg(&g_esrc[e]);
        int s1 = __ldg(&g_esrc[e + 1]);
        int s2 = __ldg(&g_esrc[e + 2]);
        int s3 = __ldg(&g_esrc[e + 3]);
        float w0 = __ldg(&g_dinv[s0]);
        float w1 = __ldg(&g_dinv[s1]);
        float w2 = __ldg(&g_dinv[s2]);
        float w3 = __ldg(&g_dinv[s3]);
        uint4 v0 = __ldg((const uint4*)(h + (size_t)s0 * (HID_DIM / 2)) + lane);
        uint4 v1 = __ldg((const uint4*)(h + (size_t)s1 * (HID_DIM / 2)) + lane);
        uint4 v2 = __ldg((const uint4*)(h + (size_t)s2 * (HID_DIM / 2)) + lane);
        uint4 v3 = __ldg((const uint4*)(h + (size_t)s3 * (HID_DIM / 2)) + lane);
        acc[0] += w0 * bf_lo(v0.x) + w1 * bf_lo(v1.x) + w2 * bf_lo(v2.x) + w3 * bf_lo(v3.x);
        acc[1] += w0 * bf_hi(v0.x) + w1 * bf_hi(v1.x) + w2 * bf_hi(v2.x) + w3 * bf_hi(v3.x);
        acc[2] += w0 * bf_lo(v0.y) + w1 * bf_lo(v1.y) + w2 * bf_lo(v2.y) + w3 * bf_lo(v3.y);
        acc[3] += w0 * bf_hi(v0.y) + w1 * bf_hi(v1.y) + w2 * bf_hi(v2.y) + w3 * bf_hi(v3.y);
        acc[4] += w0 * bf_lo(v0.z) + w1 * bf_lo(v1.z) + w2 * bf_lo(v2.z) + w3 * bf_lo(v3.z);
        acc[5] += w0 * bf_hi(v0.z) + w1 * bf_hi(v1.z) + w2 * bf_hi(v2.z) + w3 * bf_hi(v3.z);
        acc[6] += w0 * bf_lo(v0.w) + w1 * bf_lo(v1.w) + w2 * bf_lo(v2.w) + w3 * bf_lo(v3.w);
        acc[7] += w0 * bf_hi(v0.w) + w1 * bf_hi(v1.w) + w2 * bf_hi(v2.w) + w3 * bf_hi(v3.w);
    }
    for (; e < end; e++) {
        int s0 = __ldg(&g_esrc[e]);
        float w0 = __ldg(&g_dinv[s0]);
        uint4 v0 = __ldg((const uint4*)(h + (size_t)s0 * (HID_DIM / 2)) + lane);
        acc[0] += w0 * bf_lo(v0.x); acc[1] += w0 * bf_hi(v0.x);
        acc[2] += w0 * bf_lo(v0.y); acc[3] += w0 * bf_hi(v0.y);
        acc[4] += w0 * bf_lo(v0.z); acc[5] += w0 * bf_hi(v0.z);
        acc[6] += w0 * bf_lo(v0.w); acc[7] += w0 * bf_hi(v0.w);
    }

    float di = g_dinv[node];
    float sw = di * di;
    uint4 sv = __ldg((const uint4*)(h + (size_t)node * (HID_DIM / 2)) + lane);
    float4 bia0 = __ldg((const float4*)b1 + 2 * lane);
    float4 bia1 = __ldg((const float4*)b1 + 2 * lane + 1);

    float4 r0, r1;
    r0.x = fmaxf(di * acc[0] + sw * bf_lo(sv.x) + bia0.x, 0.f);
    r0.y = fmaxf(di * acc[1] + sw * bf_hi(sv.x) + bia0.y, 0.f);
    r0.z = fmaxf(di * acc[2] + sw * bf_lo(sv.y) + bia0.z, 0.f);
    r0.w = fmaxf(di * acc[3] + sw * bf_hi(sv.y) + bia0.w, 0.f);
    r1.x = fmaxf(di * acc[4] + sw * bf_lo(sv.z) + bia1.x, 0.f);
    r1.y = fmaxf(di * acc[5] + sw * bf_hi(sv.z) + bia1.y, 0.f);
    r1.z = fmaxf(di * acc[6] + sw * bf_lo(sv.w) + bia1.z, 0.f);
    r1.w = fmaxf(di * acc[7] + sw * bf_hi(sv.w) + bia1.w, 0.f);

    float4* op = (float4*)(out + (size_t)node * HID_DIM) + 2 * lane;
    op[0] = r0;
    op[1] = r1;
}

// ------------------------------------------------------------------
// Layer-2 aggregation (bf16 gather, 4-edge unroll) + bias + log_softmax
// ------------------------------------------------------------------
__global__ void spmm_softmax_bf16(const uint32_t* __restrict__ h, float* __restrict__ out,
                                  const float* __restrict__ b2) {
    const int node = (blockIdx.x * blockDim.x + threadIdx.x) >> 5;
    const int lane = threadIdx.x & 31;
    if (node >= N_NODES) return;

    const int beg = g_rowptr[node];
    const int end = g_rowptr[node + 1];

    float a0 = 0.f, a1 = 0.f;
    int e = beg;
    for (; e + 3 < end; e += 4) {
        int s0 = __ldg(&g_esrc[e]);
        int s1 = __ldg(&g_esrc[e + 1]);
        int s2 = __ldg(&g_esrc[e + 2]);
        int s3 = __ldg(&g_esrc[e + 3]);
        float w0 = __ldg(&g_dinv[s0]);
        float w1 = __ldg(&g_dinv[s1]);
        float w2 = __ldg(&g_dinv[s2]);
        float w3 = __ldg(&g_dinv[s3]);
        uint32_t v0 = __ldg(h + (size_t)s0 * (OUT_DIM / 2) + lane);
        uint32_t v1 = __ldg(h + (size_t)s1 * (OUT_DIM / 2) + lane);
        uint32_t v2 = __ldg(h + (size_t)s2 * (OUT_DIM / 2) + lane);
        uint32_t v3 = __ldg(h + (size_t)s3 * (OUT_DIM / 2) + lane);
        a0 += w0 * bf_lo(v0) + w1 * bf_lo(v1) + w2 * bf_lo(v2) + w3 * bf_lo(v3);
        a1 += w0 * bf_hi(v0) + w1 * bf_hi(v1) + w2 * bf_hi(v2) + w3 * bf_hi(v3);
    }
    for (; e < end; e++) {
        int s0 = __ldg(&g_esrc[e]);
        float w0 = __ldg(&g_dinv[s0]);
        uint32_t v0 = __ldg(h + (size_t)s0 * (OUT_DIM / 2) + lane);
        a0 += w0 * bf_lo(v0);
        a1 += w0 * bf_hi(v0);
    }

    float di = g_dinv[node];
    float sw = di * di;
    uint32_t sv = __ldg(h + (size_t)node * (OUT_DIM / 2) + lane);
    float2 bias = __ldg((const float2*)b2 + lane);
    float v0 = di * a0 + sw * bf_lo(sv) + bias.x;
    float v1 = di * a1 + sw * bf_hi(sv) + bias.y;

    float m = fmaxf(v0, v1);
#pragma unroll
    for (int o = 16; o; o >>= 1) m = fmaxf(m, __shfl_xor_sync(0xFFFFFFFFu, m, o));
    float s = expf(v0 - m) + expf(v1 - m);
#pragma unroll
    for (int o = 16; o; o >>= 1) s += __shfl_xor_sync(0xFFFFFFFFu, s, o);
    float ls = m + logf(s);

    ((float2*)(out + (size_t)node * OUT_DIM))[lane] = make_float2(v0 - ls, v1 - ls);
}

// ------------------------------------------------------------------
extern "C" void kernel_launch(void* const* d_in, const int* in_sizes, int n_in,
                              void* d_out, int out_size) {
    const float* x  = (const float*)d_in[0];
    const float* W1 = (const float*)d_in[1];
    const float* b1 = (const float*)d_in[2];
    const float* W2 = (const float*)d_in[3];
    const float* b2 = (const float*)d_in[4];
    const int* ei   = (const int*)d_in[5];
    const int E = in_sizes[5] / 2;
    const int* src = ei;
    const int* dst = ei + E;
    float* out = (float*)d_out;

    uint32_t *h1b, *h2b;
    float* a1;
    int* cntp;
    cudaGetSymbolAddress((void**)&h1b, g_h1b);
    cudaGetSymbolAddress((void**)&a1, g_a1);
    cudaGetSymbolAddress((void**)&h2b, g_h2b);
    cudaGetSymbolAddress((void**)&cntp, g_cnt);

    const int TB = 256;

    // ---- CSR build ----
    cudaMemsetAsync(cntp, 0, N_NODES * sizeof(int), 0);
    count_kernel<<<(E + TB - 1) / TB, TB>>>(dst, E);
    scan1_kernel<<<SCAN_NBLK, SCAN_TB>>>();       // also computes dinv
    scan2_kernel<<<1, SCAN_TB>>>();
    scan3_kernel<<<SCAN_NBLK, SCAN_TB>>>();
    fill_kernel<<<(E + TB - 1) / TB, TB>>>(src, dst, E);

    // ---- layer 1 ----
    cudaFuncSetAttribute(gemm_tf32_mma, cudaFuncAttributeMaxDynamicSharedMemorySize,
                         G1_SMEM);
    gemm_tf32_mma<<<dim3(HID_DIM / 128, (N_NODES + 127) / 128), 256, G1_SMEM>>>(
        x, W1, h1b, N_NODES, HID_DIM, IN_DIM);
    spmm_relu_bf16<<<(N_NODES * 32 + TB - 1) / TB, TB>>>(h1b, a1, b1);

    // ---- layer 2 ----
    gemm2_tf32_mma<<<(N_NODES + 127) / 128, 256>>>(a1, W2, h2b, N_NODES);
    spmm_softmax_bf16<<<(N_NODES * 32 + TB - 1) / TB, TB>>>(h2b, out, b2);
}

// round 11
// speedup vs baseline: 6.4319x; 1.2500x over previous
#include <cuda_runtime.h>
#include <cstdint>

#define N_NODES 50000
#define IN_DIM  512
#define HID_DIM 256
#define OUT_DIM 64
#define EDGE_CAP 1700000

#define SCAN_TB 256
#define SCAN_NBLK ((N_NODES + SCAN_TB - 1) / SCAN_TB)   // 196

// ---- scratch (no allocations allowed) ----
__device__ int      g_cnt[N_NODES];
__device__ int      g_rowptr[N_NODES + 1];
__device__ int      g_fill[N_NODES];
__device__ int      g_esrc[EDGE_CAP];
__device__ int      g_part[SCAN_NBLK];
__device__ float    g_dinv[N_NODES];
__device__ uint32_t g_h1b[(size_t)N_NODES * (HID_DIM / 2)];  // bf16x2 packed
__device__ uint32_t g_a1b[(size_t)N_NODES * (HID_DIM / 2)];  // bf16x2 packed
__device__ uint32_t g_h2b[(size_t)N_NODES * (OUT_DIM / 2)];  // bf16x2 packed

// ------------------------------------------------------------------
// helpers
// ------------------------------------------------------------------
static __device__ __forceinline__ uint32_t pack_bf162(float lo, float hi) {
    uint32_t u;
    asm("cvt.rn.bf16x2.f32 %0, %1, %2;" : "=r"(u) : "f"(hi), "f"(lo));
    return u;
}
static __device__ __forceinline__ float bf_lo(uint32_t u) {
    return __uint_as_float(u << 16);
}
static __device__ __forceinline__ float bf_hi(uint32_t u) {
    return __uint_as_float(u & 0xFFFF0000u);
}

// ------------------------------------------------------------------
// CSR build
// ------------------------------------------------------------------
__global__ void count_kernel(const int* __restrict__ dst, int E) {
    int i = blockIdx.x * blockDim.x + threadIdx.x;
    if (i < E) atomicAdd(&g_cnt[dst[i]], 1);
}

__global__ void scan1_kernel() {   // block sums + dinv (fused)
    __shared__ int s[SCAN_TB];
    int t = threadIdx.x;
    int i = blockIdx.x * SCAN_TB + t;
    int v = 0;
    if (i < N_NODES) {
        v = g_cnt[i];
        g_dinv[i] = rsqrtf((float)v + 1.0f);
    }
    s[t] = v;
    __syncthreads();
    for (int off = SCAN_TB / 2; off > 0; off >>= 1) {
        if (t < off) s[t] += s[t + off];
        __syncthreads();
    }
    if (t == 0) g_part[blockIdx.x] = s[0];
}

__global__ void scan2_kernel() {
    __shared__ int s[SCAN_TB];
    int t = threadIdx.x;
    int v = (t < SCAN_NBLK) ? g_part[t] : 0;
    s[t] = v;
    __syncthreads();
    for (int off = 1; off < SCAN_TB; off <<= 1) {
        int u = (t >= off) ? s[t - off] : 0;
        __syncthreads();
        s[t] += u;
        __syncthreads();
    }
    if (t < SCAN_NBLK) g_part[t] = s[t] - v;
    if (t == SCAN_TB - 1) g_rowptr[N_NODES] = s[SCAN_TB - 1];
}

__global__ void scan3_kernel() {
    __shared__ int s[SCAN_TB];
    int t = threadIdx.x;
    int i = blockIdx.x * SCAN_TB + t;
    int v = (i < N_NODES) ? g_cnt[i] : 0;
    s[t] = v;
    __syncthreads();
    for (int off = 1; off < SCAN_TB; off <<= 1) {
        int u = (t >= off) ? s[t - off] : 0;
        __syncthreads();
        s[t] += u;
        __syncthreads();
    }
    if (i < N_NODES) {
        int excl = g_part[blockIdx.x] + s[t] - v;
        g_rowptr[i] = excl;
        g_fill[i]   = excl;
    }
}

__global__ void fill_kernel(const int* __restrict__ src, const int* __restrict__ dst, int E) {
    int i = blockIdx.x * blockDim.x + threadIdx.x;
    if (i < E) {
        int d = dst[i];
        int pos = atomicAdd(&g_fill[d], 1);
        g_esrc[pos] = src[i];
    }
}

// ------------------------------------------------------------------
// GEMM1: bf16 mma.sync m16n8k16, CTA 128x128, BK=16, warp tile 32x64.
// Double-buffered packed-pair smem (stride 12 u32: conflict-free frags).
// A,B converted fp32->bf16 at smem store. Output packed bf16x2.
// (N=256, K=512)
// ------------------------------------------------------------------
#define PSTRIDE 12   // 8 k-pairs + 4 pad (u32)

__global__ void __launch_bounds__(256, 2)
gemm1_bf16_mma(const float* __restrict__ A, const float* __restrict__ B,
               uint32_t* __restrict__ Cb, int M, int N, int K) {
    __shared__ uint32_t Asp[2][128][PSTRIDE];   // [m][kpair]
    __shared__ uint32_t Bsp[2][128][PSTRIDE];   // [n][kpair]

    const int tid  = threadIdx.x;
    const int lane = tid & 31;
    const int w    = tid >> 5;
    const int wm   = w >> 1;              // 0..3
    const int wn   = w & 1;               // 0..1
    const int g    = lane >> 2;           // 0..7
    const int t4   = lane & 3;            // 0..3

    const int row0 = blockIdx.y * 128;
    const int col0 = blockIdx.x * 128;

    // A load mapping: 128 rows x 16 k; thread: row=tid>>1, k-half=(tid&1)*8
    const int ar  = tid >> 1;
    const int ap4 = (tid & 1) * 4;        // u32 pair offset 0 or 4
    // B load mapping: 128 n x 8 pairs; thread: n=tid&127, pair-half=(tid>>7)*4
    const int bn_ = tid & 127;
    const int bh4 = (tid >> 7) * 4;

    const int gm = row0 + ar;
    const bool arow_ok = (gm < M);
    const float* aptr = A + (size_t)(arow_ok ? gm : 0) * K + ap4 * 2;
    const float* bcol = B + col0 + bn_;

    float c[2][8][4];
#pragma unroll
    for (int mt = 0; mt < 2; mt++)
#pragma unroll
        for (int nt = 0; nt < 8; nt++)
#pragma unroll
            for (int q = 0; q < 4; q++) c[mt][nt][q] = 0.f;

    // ---- prime buffer 0 ----
    float4 pa0 = make_float4(0.f, 0.f, 0.f, 0.f), pa1 = pa0;
    float pb[8];
    if (arow_ok) { pa0 = *(const float4*)(aptr); pa1 = *(const float4*)(aptr + 4); }
#pragma unroll
    for (int j = 0; j < 4; j++) {
        int k = 2 * (bh4 + j);
        pb[2 * j]     = bcol[(size_t)k * N];
        pb[2 * j + 1] = bcol[(size_t)(k + 1) * N];
    }
    {
        uint32_t* as = &Asp[0][ar][ap4];
        as[0] = pack_bf162(pa0.x, pa0.y); as[1] = pack_bf162(pa0.z, pa0.w);
        as[2] = pack_bf162(pa1.x, pa1.y); as[3] = pack_bf162(pa1.z, pa1.w);
        uint32_t* bs = &Bsp[0][bn_][bh4];
#pragma unroll
        for (int j = 0; j < 4; j++) bs[j] = pack_bf162(pb[2 * j], pb[2 * j + 1]);
    }
    __syncthreads();

    int buf = 0;
    for (int k0 = 0; k0 < K; k0 += 16) {
        const bool has_next = (k0 + 16) < K;
        if (has_next) {
            if (arow_ok) {
                pa0 = *(const float4*)(aptr + k0 + 16);
                pa1 = *(const float4*)(aptr + k0 + 16 + 4);
            }
#pragma unroll
            for (int j = 0; j < 4; j++) {
                int k = k0 + 16 + 2 * (bh4 + j);
                pb[2 * j]     = bcol[(size_t)k * N];
                pb[2 * j + 1] = bcol[(size_t)(k + 1) * N];
            }
        }

        // ---- compute: one m16n8k16 per (mt, nt) ----
        uint32_t af[2][4];
#pragma unroll
        for (int mt = 0; mt < 2; mt++) {
            int rm = wm * 32 + mt * 16;
            af[mt][0] = Asp[buf][rm + g][t4];
            af[mt][1] = Asp[buf][rm + 8 + g][t4];
            af[mt][2] = Asp[buf][rm + g][4 + t4];
            af[mt][3] = Asp[buf][rm + 8 + g][4 + t4];
        }
#pragma unroll
        for (int nt = 0; nt < 8; nt++) {
            int nb = wn * 64 + nt * 8;
            uint32_t b0 = Bsp[buf][nb + g][t4];
            uint32_t b1 = Bsp[buf][nb + g][4 + t4];
#pragma unroll
            for (int mt = 0; mt < 2; mt++) {
                asm volatile(
                    "mma.sync.aligned.m16n8k16.row.col.f32.bf16.bf16.f32 "
                    "{%0,%1,%2,%3}, {%4,%5,%6,%7}, {%8,%9}, {%0,%1,%2,%3};"
                    : "+f"(c[mt][nt][0]), "+f"(c[mt][nt][1]),
                      "+f"(c[mt][nt][2]), "+f"(c[mt][nt][3])
                    : "r"(af[mt][0]), "r"(af[mt][1]), "r"(af[mt][2]), "r"(af[mt][3]),
                      "r"(b0), "r"(b1));
            }
        }

        if (has_next) {
            const int nb = buf ^ 1;
            uint32_t* as = &Asp[nb][ar][ap4];
            as[0] = pack_bf162(pa0.x, pa0.y); as[1] = pack_bf162(pa0.z, pa0.w);
            as[2] = pack_bf162(pa1.x, pa1.y); as[3] = pack_bf162(pa1.z, pa1.w);
            uint32_t* bs = &Bsp[nb][bn_][bh4];
#pragma unroll
            for (int j = 0; j < 4; j++) bs[j] = pack_bf162(pb[2 * j], pb[2 * j + 1]);
            __syncthreads();
            buf = nb;
        }
    }

    // epilogue: pack adjacent column pairs to bf16x2
#pragma unroll
    for (int mt = 0; mt < 2; mt++) {
#pragma unroll
        for (int nt = 0; nt < 8; nt++) {
            int rbase = row0 + wm * 32 + mt * 16 + g;
            int cpair = (col0 + wn * 64 + nt * 8 + 2 * t4) >> 1;
            if (rbase < M)
                Cb[(size_t)rbase * (N / 2) + cpair] = pack_bf162(c[mt][nt][0], c[mt][nt][1]);
            if (rbase + 8 < M)
                Cb[(size_t)(rbase + 8) * (N / 2) + cpair] = pack_bf162(c[mt][nt][2], c[mt][nt][3]);
        }
    }
}

// ------------------------------------------------------------------
// GEMM2: bf16 mma.sync m16n8k16, CTA 128x64, warp tile 32x32.
// A arrives ALREADY packed bf16x2 (a1b) — zero conversion for A.
// (N=64, K=256)
// ------------------------------------------------------------------
__global__ void __launch_bounds__(256, 2)
gemm2_bf16_mma(const uint32_t* __restrict__ Ab, const float* __restrict__ B,
               uint32_t* __restrict__ Cb, int M) {
    const int N = OUT_DIM, K = HID_DIM;
    __shared__ uint32_t Asp[128][PSTRIDE];   // [m][kpair]
    __shared__ uint32_t Bsp[64][PSTRIDE];    // [n][kpair]

    const int tid  = threadIdx.x;
    const int lane = tid & 31;
    const int w    = tid >> 5;
    const int wm   = w >> 1;
    const int wn   = w & 1;
    const int g    = lane >> 2;
    const int t4   = lane & 3;

    const int row0 = blockIdx.x * 128;

    const int ar  = tid >> 1;
    const int ap4 = (tid & 1) * 4;        // u32 pair offset
    const int bn_ = tid & 63;             // n
    const int bq  = tid >> 6;             // 0..3

    const int gm = row0 + ar;
    const bool arow_ok = (gm < M);
    const uint32_t* aptr = Ab + (size_t)(arow_ok ? gm : 0) * (K / 2) + ap4;
    const float* bcol = B + bn_;

    float c[2][4][4];
#pragma unroll
    for (int mt = 0; mt < 2; mt++)
#pragma unroll
        for (int nt = 0; nt < 4; nt++)
#pragma unroll
            for (int q = 0; q < 4; q++) c[mt][nt][q] = 0.f;

    for (int k0 = 0; k0 < K; k0 += 16) {
        // A: one uint4 (4 pairs) per thread, no conversion
        {
            uint4 av = make_uint4(0u, 0u, 0u, 0u);
            if (arow_ok) av = *(const uint4*)(aptr + k0 / 2);
            uint32_t* as = &Asp[ar][ap4];
            as[0] = av.x; as[1] = av.y; as[2] = av.z; as[3] = av.w;
        }
        // B: 2 pairs per thread (kp = bq and bq+4)
        {
#pragma unroll
            for (int j = 0; j < 2; j++) {
                int kp = bq + 4 * j;
                int k = k0 + 2 * kp;
                float f0 = bcol[(size_t)k * N];
                float f1 = bcol[(size_t)(k + 1) * N];
                Bsp[bn_][kp] = pack_bf162(f0, f1);
            }
        }
        __syncthreads();

        uint32_t af[2][4];
#pragma unroll
        for (int mt = 0; mt < 2; mt++) {
            int rm = wm * 32 + mt * 16;
            af[mt][0] = Asp[rm + g][t4];
            af[mt][1] = Asp[rm + 8 + g][t4];
            af[mt][2] = Asp[rm + g][4 + t4];
            af[mt][3] = Asp[rm + 8 + g][4 + t4];
        }
#pragma unroll
        for (int nt = 0; nt < 4; nt++) {
            int nb = wn * 32 + nt * 8;
            uint32_t b0 = Bsp[nb + g][t4];
            uint32_t b1 = Bsp[nb + g][4 + t4];
#pragma unroll
            for (int mt = 0; mt < 2; mt++) {
                asm volatile(
                    "mma.sync.aligned.m16n8k16.row.col.f32.bf16.bf16.f32 "
                    "{%0,%1,%2,%3}, {%4,%5,%6,%7}, {%8,%9}, {%0,%1,%2,%3};"
                    : "+f"(c[mt][nt][0]), "+f"(c[mt][nt][1]),
                      "+f"(c[mt][nt][2]), "+f"(c[mt][nt][3])
                    : "r"(af[mt][0]), "r"(af[mt][1]), "r"(af[mt][2]), "r"(af[mt][3]),
                      "r"(b0), "r"(b1));
            }
        }
        __syncthreads();
    }

#pragma unroll
    for (int mt = 0; mt < 2; mt++) {
#pragma unroll
        for (int nt = 0; nt < 4; nt++) {
            int rbase = row0 + wm * 32 + mt * 16 + g;
            int cpair = (wn * 32 + nt * 8 + 2 * t4) >> 1;
            if (rbase < M)
                Cb[(size_t)rbase * (N / 2) + cpair] = pack_bf162(c[mt][nt][0], c[mt][nt][1]);
            if (rbase + 8 < M)
                Cb[(size_t)(rbase + 8) * (N / 2) + cpair] = pack_bf162(c[mt][nt][2], c[mt][nt][3]);
        }
    }
}

// ------------------------------------------------------------------
// Layer-1 aggregation (bf16 gather, 4-edge unroll) + self+bias+relu
// Warp per node; lane handles 8 features. Output packed bf16x2.
// ------------------------------------------------------------------
__global__ void spmm_relu_bf16(const uint32_t* __restrict__ h, uint32_t* __restrict__ outb,
                               const float* __restrict__ b1) {
    const int node = (blockIdx.x * blockDim.x + threadIdx.x) >> 5;
    const int lane = threadIdx.x & 31;
    if (node >= N_NODES) return;
    const int beg = g_rowptr[node];
    const int end = g_rowptr[node + 1];

    float acc[8] = {};
    int e = beg;
    for (; e + 3 < end; e += 4) {
        int s0 = __ldg(&g_esrc[e]);
        int s1 = __ldg(&g_esrc[e + 1]);
        int s2 = __ldg(&g_esrc[e + 2]);
        int s3 = __ldg(&g_esrc[e + 3]);
        float w0 = __ldg(&g_dinv[s0]);
        float w1 = __ldg(&g_dinv[s1]);
        float w2 = __ldg(&g_dinv[s2]);
        float w3 = __ldg(&g_dinv[s3]);
        uint4 v0 = __ldg((const uint4*)(h + (size_t)s0 * (HID_DIM / 2)) + lane);
        uint4 v1 = __ldg((const uint4*)(h + (size_t)s1 * (HID_DIM / 2)) + lane);
        uint4 v2 = __ldg((const uint4*)(h + (size_t)s2 * (HID_DIM / 2)) + lane);
        uint4 v3 = __ldg((const uint4*)(h + (size_t)s3 * (HID_DIM / 2)) + lane);
        acc[0] += w0 * bf_lo(v0.x) + w1 * bf_lo(v1.x) + w2 * bf_lo(v2.x) + w3 * bf_lo(v3.x);
        acc[1] += w0 * bf_hi(v0.x) + w1 * bf_hi(v1.x) + w2 * bf_hi(v2.x) + w3 * bf_hi(v3.x);
        acc[2] += w0 * bf_lo(v0.y) + w1 * bf_lo(v1.y) + w2 * bf_lo(v2.y) + w3 * bf_lo(v3.y);
        acc[3] += w0 * bf_hi(v0.y) + w1 * bf_hi(v1.y) + w2 * bf_hi(v2.y) + w3 * bf_hi(v3.y);
        acc[4] += w0 * bf_lo(v0.z) + w1 * bf_lo(v1.z) + w2 * bf_lo(v2.z) + w3 * bf_lo(v3.z);
        acc[5] += w0 * bf_hi(v0.z) + w1 * bf_hi(v1.z) + w2 * bf_hi(v2.z) + w3 * bf_hi(v3.z);
        acc[6] += w0 * bf_lo(v0.w) + w1 * bf_lo(v1.w) + w2 * bf_lo(v2.w) + w3 * bf_lo(v3.w);
        acc[7] += w0 * bf_hi(v0.w) + w1 * bf_hi(v1.w) + w2 * bf_hi(v2.w) + w3 * bf_hi(v3.w);
    }
    for (; e < end; e++) {
        int s0 = __ldg(&g_esrc[e]);
        float w0 = __ldg(&g_dinv[s0]);
        uint4 v0 = __ldg((const uint4*)(h + (size_t)s0 * (HID_DIM / 2)) + lane);
        acc[0] += w0 * bf_lo(v0.x); acc[1] += w0 * bf_hi(v0.x);
        acc[2] += w0 * bf_lo(v0.y); acc[3] += w0 * bf_hi(v0.y);
        acc[4] += w0 * bf_lo(v0.z); acc[5] += w0 * bf_hi(v0.z);
        acc[6] += w0 * bf_lo(v0.w); acc[7] += w0 * bf_hi(v0.w);
    }

    float di = g_dinv[node];
    float sw = di * di;
    uint4 sv = __ldg((const uint4*)(h + (size_t)node * (HID_DIM / 2)) + lane);
    float4 bia0 = __ldg((const float4*)b1 + 2 * lane);
    float4 bia1 = __ldg((const float4*)b1 + 2 * lane + 1);

    float r0 = fmaxf(di * acc[0] + sw * bf_lo(sv.x) + bia0.x, 0.f);
    float r1 = fmaxf(di * acc[1] + sw * bf_hi(sv.x) + bia0.y, 0.f);
    float r2 = fmaxf(di * acc[2] + sw * bf_lo(sv.y) + bia0.z, 0.f);
    float r3 = fmaxf(di * acc[3] + sw * bf_hi(sv.y) + bia0.w, 0.f);
    float r4 = fmaxf(di * acc[4] + sw * bf_lo(sv.z) + bia1.x, 0.f);
    float r5 = fmaxf(di * acc[5] + sw * bf_hi(sv.z) + bia1.y, 0.f);
    float r6 = fmaxf(di * acc[6] + sw * bf_lo(sv.w) + bia1.z, 0.f);
    float r7 = fmaxf(di * acc[7] + sw * bf_hi(sv.w) + bia1.w, 0.f);

    uint4 rv;
    rv.x = pack_bf162(r0, r1);
    rv.y = pack_bf162(r2, r3);
    rv.z = pack_bf162(r4, r5);
    rv.w = pack_bf162(r6, r7);
    ((uint4*)(outb + (size_t)node * (HID_DIM / 2)))[lane] = rv;
}

// ------------------------------------------------------------------
// Layer-2 aggregation (bf16 gather, 4-edge unroll) + bias + log_softmax
// ------------------------------------------------------------------
__global__ void spmm_softmax_bf16(const uint32_t* __restrict__ h, float* __restrict__ out,
                                  const float* __restrict__ b2) {
    const int node = (blockIdx.x * blockDim.x + threadIdx.x) >> 5;
    const int lane = threadIdx.x & 31;
    if (node >= N_NODES) return;

    const int beg = g_rowptr[node];
    const int end = g_rowptr[node + 1];

    float a0 = 0.f, a1 = 0.f;
    int e = beg;
    for (; e + 3 < end; e += 4) {
        int s0 = __ldg(&g_esrc[e]);
        int s1 = __ldg(&g_esrc[e + 1]);
        int s2 = __ldg(&g_esrc[e + 2]);
        int s3 = __ldg(&g_esrc[e + 3]);
        float w0 = __ldg(&g_dinv[s0]);
        float w1 = __ldg(&g_dinv[s1]);
        float w2 = __ldg(&g_dinv[s2]);
        float w3 = __ldg(&g_dinv[s3]);
        uint32_t v0 = __ldg(h + (size_t)s0 * (OUT_DIM / 2) + lane);
        uint32_t v1 = __ldg(h + (size_t)s1 * (OUT_DIM / 2) + lane);
        uint32_t v2 = __ldg(h + (size_t)s2 * (OUT_DIM / 2) + lane);
        uint32_t v3 = __ldg(h + (size_t)s3 * (OUT_DIM / 2) + lane);
        a0 += w0 * bf_lo(v0) + w1 * bf_lo(v1) + w2 * bf_lo(v2) + w3 * bf_lo(v3);
        a1 += w0 * bf_hi(v0) + w1 * bf_hi(v1) + w2 * bf_hi(v2) + w3 * bf_hi(v3);
    }
    for (; e < end; e++) {
        int s0 = __ldg(&g_esrc[e]);
        float w0 = __ldg(&g_dinv[s0]);
        uint32_t v0 = __ldg(h + (size_t)s0 * (OUT_DIM / 2) + lane);
        a0 += w0 * bf_lo(v0);
        a1 += w0 * bf_hi(v0);
    }

    float di = g_dinv[node];
    float sw = di * di;
    uint32_t sv = __ldg(h + (size_t)node * (OUT_DIM / 2) + lane);
    float2 bias = __ldg((const float2*)b2 + lane);
    float v0 = di * a0 + sw * bf_lo(sv) + bias.x;
    float v1 = di * a1 + sw * bf_hi(sv) + bias.y;

    float m = fmaxf(v0, v1);
#pragma unroll
    for (int o = 16; o; o >>= 1) m = fmaxf(m, __shfl_xor_sync(0xFFFFFFFFu, m, o));
    float s = expf(v0 - m) + expf(v1 - m);
#pragma unroll
    for (int o = 16; o; o >>= 1) s += __shfl_xor_sync(0xFFFFFFFFu, s, o);
    float ls = m + logf(s);

    ((float2*)(out + (size_t)node * OUT_DIM))[lane] = make_float2(v0 - ls, v1 - ls);
}

// ------------------------------------------------------------------
extern "C" void kernel_launch(void* const* d_in, const int* in_sizes, int n_in,
                              void* d_out, int out_size) {
    const float* x  = (const float*)d_in[0];
    const float* W1 = (const float*)d_in[1];
    const float* b1 = (const float*)d_in[2];
    const float* W2 = (const float*)d_in[3];
    const float* b2 = (const float*)d_in[4];
    const int* ei   = (const int*)d_in[5];
    const int E = in_sizes[5] / 2;
    const int* src = ei;
    const int* dst = ei + E;
    float* out = (float*)d_out;

    uint32_t *h1b, *a1b, *h2b;
    int* cntp;
    cudaGetSymbolAddress((void**)&h1b, g_h1b);
    cudaGetSymbolAddress((void**)&a1b, g_a1b);
    cudaGetSymbolAddress((void**)&h2b, g_h2b);
    cudaGetSymbolAddress((void**)&cntp, g_cnt);

    const int TB = 256;

    // ---- CSR build ----
    cudaMemsetAsync(cntp, 0, N_NODES * sizeof(int), 0);
    count_kernel<<<(E + TB - 1) / TB, TB>>>(dst, E);
    scan1_kernel<<<SCAN_NBLK, SCAN_TB>>>();       // also computes dinv
    scan2_kernel<<<1, SCAN_TB>>>();
    scan3_kernel<<<SCAN_NBLK, SCAN_TB>>>();
    fill_kernel<<<(E + TB - 1) / TB, TB>>>(src, dst, E);

    // ---- layer 1 ----
    gemm1_bf16_mma<<<dim3(HID_DIM / 128, (N_NODES + 127) / 128), 256>>>(
        x, W1, h1b, N_NODES, HID_DIM, IN_DIM);
    spmm_relu_bf16<<<(N_NODES * 32 + TB - 1) / TB, TB>>>(h1b, a1b, b1);

    // ---- layer 2 ----
    gemm2_bf16_mma<<<(N_NODES + 127) / 128, 256>>>(a1b, W2, h2b, N_NODES);
    spmm_softmax_bf16<<<(N_NODES * 32 + TB - 1) / TB, TB>>>(h2b, out, b2);
}

// round 12
// speedup vs baseline: 7.0176x; 1.0910x over previous
#include <cuda_runtime.h>
#include <cstdint>

#define N_NODES 50000
#define IN_DIM  512
#define HID_DIM 256
#define OUT_DIM 64
#define EDGE_CAP 1700000

#define SCAN_TB 256
#define SCAN_NBLK ((N_NODES + SCAN_TB - 1) / SCAN_TB)   // 196

// ---- scratch (no allocations allowed) ----
__device__ int      g_cnt[N_NODES];
__device__ int      g_rowptr[N_NODES + 1];
__device__ int      g_fill[N_NODES];
__device__ int      g_esrc[EDGE_CAP];
__device__ int      g_part[SCAN_NBLK];
__device__ float    g_dinv[N_NODES];
__device__ uint32_t g_h1b[(size_t)N_NODES * (HID_DIM / 2)];  // bf16x2 packed
__device__ uint32_t g_a1b[(size_t)N_NODES * (HID_DIM / 2)];  // bf16x2 packed
__device__ uint32_t g_h2b[(size_t)N_NODES * (OUT_DIM / 2)];  // bf16x2 packed

// ------------------------------------------------------------------
// helpers
// ------------------------------------------------------------------
static __device__ __forceinline__ uint32_t pack_bf162(float lo, float hi) {
    uint32_t u;
    asm("cvt.rn.bf16x2.f32 %0, %1, %2;" : "=r"(u) : "f"(hi), "f"(lo));
    return u;
}
static __device__ __forceinline__ float bf_lo(uint32_t u) {
    return __uint_as_float(u << 16);
}
static __device__ __forceinline__ float bf_hi(uint32_t u) {
    return __uint_as_float(u & 0xFFFF0000u);
}

// ------------------------------------------------------------------
// CSR build
// ------------------------------------------------------------------
__global__ void count_kernel(const int* __restrict__ dst, int E) {
    int i = blockIdx.x * blockDim.x + threadIdx.x;
    if (i < E) atomicAdd(&g_cnt[dst[i]], 1);
}

__global__ void scan1_kernel() {   // block sums + dinv (fused)
    __shared__ int s[SCAN_TB];
    int t = threadIdx.x;
    int i = blockIdx.x * SCAN_TB + t;
    int v = 0;
    if (i < N_NODES) {
        v = g_cnt[i];
        g_dinv[i] = rsqrtf((float)v + 1.0f);
    }
    s[t] = v;
    __syncthreads();
    for (int off = SCAN_TB / 2; off > 0; off >>= 1) {
        if (t < off) s[t] += s[t + off];
        __syncthreads();
    }
    if (t == 0) g_part[blockIdx.x] = s[0];
}

__global__ void scan2_kernel() {
    __shared__ int s[SCAN_TB];
    int t = threadIdx.x;
    int v = (t < SCAN_NBLK) ? g_part[t] : 0;
    s[t] = v;
    __syncthreads();
    for (int off = 1; off < SCAN_TB; off <<= 1) {
        int u = (t >= off) ? s[t - off] : 0;
        __syncthreads();
        s[t] += u;
        __syncthreads();
    }
    if (t < SCAN_NBLK) g_part[t] = s[t] - v;
    if (t == SCAN_TB - 1) g_rowptr[N_NODES] = s[SCAN_TB - 1];
}

__global__ void scan3_kernel() {
    __shared__ int s[SCAN_TB];
    int t = threadIdx.x;
    int i = blockIdx.x * SCAN_TB + t;
    int v = (i < N_NODES) ? g_cnt[i] : 0;
    s[t] = v;
    __syncthreads();
    for (int off = 1; off < SCAN_TB; off <<= 1) {
        int u = (t >= off) ? s[t - off] : 0;
        __syncthreads();
        s[t] += u;
        __syncthreads();
    }
    if (i < N_NODES) {
        int excl = g_part[blockIdx.x] + s[t] - v;
        g_rowptr[i] = excl;
        g_fill[i]   = excl;
    }
}

__global__ void fill_kernel(const int* __restrict__ src, const int* __restrict__ dst, int E) {
    int i = blockIdx.x * blockDim.x + threadIdx.x;
    if (i < E) {
        int d = dst[i];
        int pos = atomicAdd(&g_fill[d], 1);
        g_esrc[pos] = src[i];
    }
}

// ------------------------------------------------------------------
// GEMM1: bf16 mma.sync m16n8k16, CTA 128x128, BK=16, warp tile 32x64.
// Double-buffered packed-pair smem (stride 12 u32: conflict-free frags).
// A,B converted fp32->bf16 at smem store. Output packed bf16x2.
// (N=256, K=512)
// ------------------------------------------------------------------
#define PSTRIDE 12   // 8 k-pairs + 4 pad (u32)

__global__ void __launch_bounds__(256, 2)
gemm1_bf16_mma(const float* __restrict__ A, const float* __restrict__ B,
               uint32_t* __restrict__ Cb, int M, int N, int K) {
    __shared__ uint32_t Asp[2][128][PSTRIDE];   // [m][kpair]
    __shared__ uint32_t Bsp[2][128][PSTRIDE];   // [n][kpair]

    const int tid  = threadIdx.x;
    const int lane = tid & 31;
    const int w    = tid >> 5;
    const int wm   = w >> 1;              // 0..3
    const int wn   = w & 1;               // 0..1
    const int g    = lane >> 2;           // 0..7
    const int t4   = lane & 3;            // 0..3

    const int row0 = blockIdx.y * 128;
    const int col0 = blockIdx.x * 128;

    const int ar  = tid >> 1;
    const int ap4 = (tid & 1) * 4;        // u32 pair offset 0 or 4
    const int bn_ = tid & 127;
    const int bh4 = (tid >> 7) * 4;

    const int gm = row0 + ar;
    const bool arow_ok = (gm < M);
    const float* aptr = A + (size_t)(arow_ok ? gm : 0) * K + ap4 * 2;
    const float* bcol = B + col0 + bn_;

    float c[2][8][4];
#pragma unroll
    for (int mt = 0; mt < 2; mt++)
#pragma unroll
        for (int nt = 0; nt < 8; nt++)
#pragma unroll
            for (int q = 0; q < 4; q++) c[mt][nt][q] = 0.f;

    // ---- prime buffer 0 ----
    float4 pa0 = make_float4(0.f, 0.f, 0.f, 0.f), pa1 = pa0;
    float pb[8];
    if (arow_ok) { pa0 = *(const float4*)(aptr); pa1 = *(const float4*)(aptr + 4); }
#pragma unroll
    for (int j = 0; j < 4; j++) {
        int k = 2 * (bh4 + j);
        pb[2 * j]     = bcol[(size_t)k * N];
        pb[2 * j + 1] = bcol[(size_t)(k + 1) * N];
    }
    {
        uint32_t* as = &Asp[0][ar][ap4];
        as[0] = pack_bf162(pa0.x, pa0.y); as[1] = pack_bf162(pa0.z, pa0.w);
        as[2] = pack_bf162(pa1.x, pa1.y); as[3] = pack_bf162(pa1.z, pa1.w);
        uint32_t* bs = &Bsp[0][bn_][bh4];
#pragma unroll
        for (int j = 0; j < 4; j++) bs[j] = pack_bf162(pb[2 * j], pb[2 * j + 1]);
    }
    __syncthreads();

    int buf = 0;
    for (int k0 = 0; k0 < K; k0 += 16) {
        const bool has_next = (k0 + 16) < K;
        if (has_next) {
            if (arow_ok) {
                pa0 = *(const float4*)(aptr + k0 + 16);
                pa1 = *(const float4*)(aptr + k0 + 16 + 4);
            }
#pragma unroll
            for (int j = 0; j < 4; j++) {
                int k = k0 + 16 + 2 * (bh4 + j);
                pb[2 * j]     = bcol[(size_t)k * N];
                pb[2 * j + 1] = bcol[(size_t)(k + 1) * N];
            }
        }

        uint32_t af[2][4];
#pragma unroll
        for (int mt = 0; mt < 2; mt++) {
            int rm = wm * 32 + mt * 16;
            af[mt][0] = Asp[buf][rm + g][t4];
            af[mt][1] = Asp[buf][rm + 8 + g][t4];
            af[mt][2] = Asp[buf][rm + g][4 + t4];
            af[mt][3] = Asp[buf][rm + 8 + g][4 + t4];
        }
#pragma unroll
        for (int nt = 0; nt < 8; nt++) {
            int nb = wn * 64 + nt * 8;
            uint32_t b0 = Bsp[buf][nb + g][t4];
            uint32_t b1 = Bsp[buf][nb + g][4 + t4];
#pragma unroll
            for (int mt = 0; mt < 2; mt++) {
                asm volatile(
                    "mma.sync.aligned.m16n8k16.row.col.f32.bf16.bf16.f32 "
                    "{%0,%1,%2,%3}, {%4,%5,%6,%7}, {%8,%9}, {%0,%1,%2,%3};"
                    : "+f"(c[mt][nt][0]), "+f"(c[mt][nt][1]),
                      "+f"(c[mt][nt][2]), "+f"(c[mt][nt][3])
                    : "r"(af[mt][0]), "r"(af[mt][1]), "r"(af[mt][2]), "r"(af[mt][3]),
                      "r"(b0), "r"(b1));
            }
        }

        if (has_next) {
            const int nb = buf ^ 1;
            uint32_t* as = &Asp[nb][ar][ap4];
            as[0] = pack_bf162(pa0.x, pa0.y); as[1] = pack_bf162(pa0.z, pa0.w);
            as[2] = pack_bf162(pa1.x, pa1.y); as[3] = pack_bf162(pa1.z, pa1.w);
            uint32_t* bs = &Bsp[nb][bn_][bh4];
#pragma unroll
            for (int j = 0; j < 4; j++) bs[j] = pack_bf162(pb[2 * j], pb[2 * j + 1]);
            __syncthreads();
            buf = nb;
        }
    }

#pragma unroll
    for (int mt = 0; mt < 2; mt++) {
#pragma unroll
        for (int nt = 0; nt < 8; nt++) {
            int rbase = row0 + wm * 32 + mt * 16 + g;
            int cpair = (col0 + wn * 64 + nt * 8 + 2 * t4) >> 1;
            if (rbase < M)
                Cb[(size_t)rbase * (N / 2) + cpair] = pack_bf162(c[mt][nt][0], c[mt][nt][1]);
            if (rbase + 8 < M)
                Cb[(size_t)(rbase + 8) * (N / 2) + cpair] = pack_bf162(c[mt][nt][2], c[mt][nt][3]);
        }
    }
}

// ------------------------------------------------------------------
// GEMM2: bf16 mma.sync m16n8k16, CTA 128x64, warp tile 32x32.
// A arrives ALREADY packed bf16x2 (a1b). (N=64, K=256)
// ------------------------------------------------------------------
__global__ void __launch_bounds__(256, 2)
gemm2_bf16_mma(const uint32_t* __restrict__ Ab, const float* __restrict__ B,
               uint32_t* __restrict__ Cb, int M) {
    const int N = OUT_DIM, K = HID_DIM;
    __shared__ uint32_t Asp[128][PSTRIDE];
    __shared__ uint32_t Bsp[64][PSTRIDE];

    const int tid  = threadIdx.x;
    const int lane = tid & 31;
    const int w    = tid >> 5;
    const int wm   = w >> 1;
    const int wn   = w & 1;
    const int g    = lane >> 2;
    const int t4   = lane & 3;

    const int row0 = blockIdx.x * 128;

    const int ar  = tid >> 1;
    const int ap4 = (tid & 1) * 4;
    const int bn_ = tid & 63;
    const int bq  = tid >> 6;

    const int gm = row0 + ar;
    const bool arow_ok = (gm < M);
    const uint32_t* aptr = Ab + (size_t)(arow_ok ? gm : 0) * (K / 2) + ap4;
    const float* bcol = B + bn_;

    float c[2][4][4];
#pragma unroll
    for (int mt = 0; mt < 2; mt++)
#pragma unroll
        for (int nt = 0; nt < 4; nt++)
#pragma unroll
            for (int q = 0; q < 4; q++) c[mt][nt][q] = 0.f;

    for (int k0 = 0; k0 < K; k0 += 16) {
        {
            uint4 av = make_uint4(0u, 0u, 0u, 0u);
            if (arow_ok) av = *(const uint4*)(aptr + k0 / 2);
            uint32_t* as = &Asp[ar][ap4];
            as[0] = av.x; as[1] = av.y; as[2] = av.z; as[3] = av.w;
        }
        {
#pragma unroll
            for (int j = 0; j < 2; j++) {
                int kp = bq + 4 * j;
                int k = k0 + 2 * kp;
                float f0 = bcol[(size_t)k * N];
                float f1 = bcol[(size_t)(k + 1) * N];
                Bsp[bn_][kp] = pack_bf162(f0, f1);
            }
        }
        __syncthreads();

        uint32_t af[2][4];
#pragma unroll
        for (int mt = 0; mt < 2; mt++) {
            int rm = wm * 32 + mt * 16;
            af[mt][0] = Asp[rm + g][t4];
            af[mt][1] = Asp[rm + 8 + g][t4];
            af[mt][2] = Asp[rm + g][4 + t4];
            af[mt][3] = Asp[rm + 8 + g][4 + t4];
        }
#pragma unroll
        for (int nt = 0; nt < 4; nt++) {
            int nb = wn * 32 + nt * 8;
            uint32_t b0 = Bsp[nb + g][t4];
            uint32_t b1 = Bsp[nb + g][4 + t4];
#pragma unroll
            for (int mt = 0; mt < 2; mt++) {
                asm volatile(
                    "mma.sync.aligned.m16n8k16.row.col.f32.bf16.bf16.f32 "
                    "{%0,%1,%2,%3}, {%4,%5,%6,%7}, {%8,%9}, {%0,%1,%2,%3};"
                    : "+f"(c[mt][nt][0]), "+f"(c[mt][nt][1]),
                      "+f"(c[mt][nt][2]), "+f"(c[mt][nt][3])
                    : "r"(af[mt][0]), "r"(af[mt][1]), "r"(af[mt][2]), "r"(af[mt][3]),
                      "r"(b0), "r"(b1));
            }
        }
        __syncthreads();
    }

#pragma unroll
    for (int mt = 0; mt < 2; mt++) {
#pragma unroll
        for (int nt = 0; nt < 4; nt++) {
            int rbase = row0 + wm * 32 + mt * 16 + g;
            int cpair = (wn * 32 + nt * 8 + 2 * t4) >> 1;
            if (rbase < M)
                Cb[(size_t)rbase * (N / 2) + cpair] = pack_bf162(c[mt][nt][0], c[mt][nt][1]);
            if (rbase + 8 < M)
                Cb[(size_t)(rbase + 8) * (N / 2) + cpair] = pack_bf162(c[mt][nt][2], c[mt][nt][3]);
        }
    }
}

// ------------------------------------------------------------------
// Layer-1 aggregation (bf16 gather, 4-edge unroll) + self+bias+relu
// ------------------------------------------------------------------
__global__ void spmm_relu_bf16(const uint32_t* __restrict__ h, uint32_t* __restrict__ outb,
                               const float* __restrict__ b1) {
    const int node = (blockIdx.x * blockDim.x + threadIdx.x) >> 5;
    const int lane = threadIdx.x & 31;
    if (node >= N_NODES) return;
    const int beg = g_rowptr[node];
    const int end = g_rowptr[node + 1];

    float acc[8] = {};
    int e = beg;
    for (; e + 3 < end; e += 4) {
        int s0 = __ldg(&g_esrc[e]);
        int s1 = __ldg(&g_esrc[e + 1]);
        int s2 = __ldg(&g_esrc[e + 2]);
        int s3 = __ldg(&g_esrc[e + 3]);
        float w0 = __ldg(&g_dinv[s0]);
        float w1 = __ldg(&g_dinv[s1]);
        float w2 = __ldg(&g_dinv[s2]);
        float w3 = __ldg(&g_dinv[s3]);
        uint4 v0 = __ldg((const uint4*)(h + (size_t)s0 * (HID_DIM / 2)) + lane);
        uint4 v1 = __ldg((const uint4*)(h + (size_t)s1 * (HID_DIM / 2)) + lane);
        uint4 v2 = __ldg((const uint4*)(h + (size_t)s2 * (HID_DIM / 2)) + lane);
        uint4 v3 = __ldg((const uint4*)(h + (size_t)s3 * (HID_DIM / 2)) + lane);
        acc[0] += w0 * bf_lo(v0.x) + w1 * bf_lo(v1.x) + w2 * bf_lo(v2.x) + w3 * bf_lo(v3.x);
        acc[1] += w0 * bf_hi(v0.x) + w1 * bf_hi(v1.x) + w2 * bf_hi(v2.x) + w3 * bf_hi(v3.x);
        acc[2] += w0 * bf_lo(v0.y) + w1 * bf_lo(v1.y) + w2 * bf_lo(v2.y) + w3 * bf_lo(v3.y);
        acc[3] += w0 * bf_hi(v0.y) + w1 * bf_hi(v1.y) + w2 * bf_hi(v2.y) + w3 * bf_hi(v3.y);
        acc[4] += w0 * bf_lo(v0.z) + w1 * bf_lo(v1.z) + w2 * bf_lo(v2.z) + w3 * bf_lo(v3.z);
        acc[5] += w0 * bf_hi(v0.z) + w1 * bf_hi(v1.z) + w2 * bf_hi(v2.z) + w3 * bf_hi(v3.z);
        acc[6] += w0 * bf_lo(v0.w) + w1 * bf_lo(v1.w) + w2 * bf_lo(v2.w) + w3 * bf_lo(v3.w);
        acc[7] += w0 * bf_hi(v0.w) + w1 * bf_hi(v1.w) + w2 * bf_hi(v2.w) + w3 * bf_hi(v3.w);
    }
    for (; e < end; e++) {
        int s0 = __ldg(&g_esrc[e]);
        float w0 = __ldg(&g_dinv[s0]);
        uint4 v0 = __ldg((const uint4*)(h + (size_t)s0 * (HID_DIM / 2)) + lane);
        acc[0] += w0 * bf_lo(v0.x); acc[1] += w0 * bf_hi(v0.x);
        acc[2] += w0 * bf_lo(v0.y); acc[3] += w0 * bf_hi(v0.y);
        acc[4] += w0 * bf_lo(v0.z); acc[5] += w0 * bf_hi(v0.z);
        acc[6] += w0 * bf_lo(v0.w); acc[7] += w0 * bf_hi(v0.w);
    }

    float di = g_dinv[node];
    float sw = di * di;
    uint4 sv = __ldg((const uint4*)(h + (size_t)node * (HID_DIM / 2)) + lane);
    float4 bia0 = __ldg((const float4*)b1 + 2 * lane);
    float4 bia1 = __ldg((const float4*)b1 + 2 * lane + 1);

    float r0 = fmaxf(di * acc[0] + sw * bf_lo(sv.x) + bia0.x, 0.f);
    float r1 = fmaxf(di * acc[1] + sw * bf_hi(sv.x) + bia0.y, 0.f);
    float r2 = fmaxf(di * acc[2] + sw * bf_lo(sv.y) + bia0.z, 0.f);
    float r3 = fmaxf(di * acc[3] + sw * bf_hi(sv.y) + bia0.w, 0.f);
    float r4 = fmaxf(di * acc[4] + sw * bf_lo(sv.z) + bia1.x, 0.f);
    float r5 = fmaxf(di * acc[5] + sw * bf_hi(sv.z) + bia1.y, 0.f);
    float r6 = fmaxf(di * acc[6] + sw * bf_lo(sv.w) + bia1.z, 0.f);
    float r7 = fmaxf(di * acc[7] + sw * bf_hi(sv.w) + bia1.w, 0.f);

    uint4 rv;
    rv.x = pack_bf162(r0, r1);
    rv.y = pack_bf162(r2, r3);
    rv.z = pack_bf162(r4, r5);
    rv.w = pack_bf162(r6, r7);
    ((uint4*)(outb + (size_t)node * (HID_DIM / 2)))[lane] = rv;
}

// ------------------------------------------------------------------
// Layer-2 aggregation (bf16 gather, 4-edge unroll) + bias + log_softmax
// ------------------------------------------------------------------
__global__ void spmm_softmax_bf16(const uint32_t* __restrict__ h, float* __restrict__ out,
                                  const float* __restrict__ b2) {
    const int node = (blockIdx.x * blockDim.x + threadIdx.x) >> 5;
    const int lane = threadIdx.x & 31;
    if (node >= N_NODES) return;

    const int beg = g_rowptr[node];
    const int end = g_rowptr[node + 1];

    float a0 = 0.f, a1 = 0.f;
    int e = beg;
    for (; e + 3 < end; e += 4) {
        int s0 = __ldg(&g_esrc[e]);
        int s1 = __ldg(&g_esrc[e + 1]);
        int s2 = __ldg(&g_esrc[e + 2]);
        int s3 = __ldg(&g_esrc[e + 3]);
        float w0 = __ldg(&g_dinv[s0]);
        float w1 = __ldg(&g_dinv[s1]);
        float w2 = __ldg(&g_dinv[s2]);
        float w3 = __ldg(&g_dinv[s3]);
        uint32_t v0 = __ldg(h + (size_t)s0 * (OUT_DIM / 2) + lane);
        uint32_t v1 = __ldg(h + (size_t)s1 * (OUT_DIM / 2) + lane);
        uint32_t v2 = __ldg(h + (size_t)s2 * (OUT_DIM / 2) + lane);
        uint32_t v3 = __ldg(h + (size_t)s3 * (OUT_DIM / 2) + lane);
        a0 += w0 * bf_lo(v0) + w1 * bf_lo(v1) + w2 * bf_lo(v2) + w3 * bf_lo(v3);
        a1 += w0 * bf_hi(v0) + w1 * bf_hi(v1) + w2 * bf_hi(v2) + w3 * bf_hi(v3);
    }
    for (; e < end; e++) {
        int s0 = __ldg(&g_esrc[e]);
        float w0 = __ldg(&g_dinv[s0]);
        uint32_t v0 = __ldg(h + (size_t)s0 * (OUT_DIM / 2) + lane);
        a0 += w0 * bf_lo(v0);
        a1 += w0 * bf_hi(v0);
    }

    float di = g_dinv[node];
    float sw = di * di;
    uint32_t sv = __ldg(h + (size_t)node * (OUT_DIM / 2) + lane);
    float2 bias = __ldg((const float2*)b2 + lane);
    float v0 = di * a0 + sw * bf_lo(sv) + bias.x;
    float v1 = di * a1 + sw * bf_hi(sv) + bias.y;

    float m = fmaxf(v0, v1);
#pragma unroll
    for (int o = 16; o; o >>= 1) m = fmaxf(m, __shfl_xor_sync(0xFFFFFFFFu, m, o));
    float s = expf(v0 - m) + expf(v1 - m);
#pragma unroll
    for (int o = 16; o; o >>= 1) s += __shfl_xor_sync(0xFFFFFFFFu, s, o);
    float ls = m + logf(s);

    ((float2*)(out + (size_t)node * OUT_DIM))[lane] = make_float2(v0 - ls, v1 - ls);
}

// ------------------------------------------------------------------
extern "C" void kernel_launch(void* const* d_in, const int* in_sizes, int n_in,
                              void* d_out, int out_size) {
    const float* x  = (const float*)d_in[0];
    const float* W1 = (const float*)d_in[1];
    const float* b1 = (const float*)d_in[2];
    const float* W2 = (const float*)d_in[3];
    const float* b2 = (const float*)d_in[4];
    const int* ei   = (const int*)d_in[5];
    const int E = in_sizes[5] / 2;
    const int* src = ei;
    const int* dst = ei + E;
    float* out = (float*)d_out;

    uint32_t *h1b, *a1b, *h2b;
    int* cntp;
    cudaGetSymbolAddress((void**)&h1b, g_h1b);
    cudaGetSymbolAddress((void**)&a1b, g_a1b);
    cudaGetSymbolAddress((void**)&h2b, g_h2b);
    cudaGetSymbolAddress((void**)&cntp, g_cnt);

    // Host-side stream/events, created once on the (non-captured) correctness
    // call. Capture-legal fork/join pattern thereafter.
    static cudaStream_t s_side = nullptr;
    static cudaEvent_t s_evFork = nullptr, s_evJoin = nullptr;
    if (s_side == nullptr) {
        cudaStreamCreateWithFlags(&s_side, cudaStreamNonBlocking);
        cudaEventCreateWithFlags(&s_evFork, cudaEventDisableTiming);
        cudaEventCreateWithFlags(&s_evJoin, cudaEventDisableTiming);
    }

    const int TB = 256;

    // ---- fork: CSR build on side stream, GEMM1 on main stream ----
    cudaEventRecord(s_evFork, 0);
    cudaStreamWaitEvent(s_side, s_evFork, 0);

    cudaMemsetAsync(cntp, 0, N_NODES * sizeof(int), s_side);
    count_kernel<<<(E + TB - 1) / TB, TB, 0, s_side>>>(dst, E);
    scan1_kernel<<<SCAN_NBLK, SCAN_TB, 0, s_side>>>();       // also computes dinv
    scan2_kernel<<<1, SCAN_TB, 0, s_side>>>();
    scan3_kernel<<<SCAN_NBLK, SCAN_TB, 0, s_side>>>();
    fill_kernel<<<(E + TB - 1) / TB, TB, 0, s_side>>>(src, dst, E);
    cudaEventRecord(s_evJoin, s_side);

    // main stream: h1 = bf16(x @ W1), independent of CSR
    gemm1_bf16_mma<<<dim3(HID_DIM / 128, (N_NODES + 127) / 128), 256>>>(
        x, W1, h1b, N_NODES, HID_DIM, IN_DIM);

    // ---- join, then the dependent chain ----
    cudaStreamWaitEvent(0, s_evJoin, 0);
    spmm_relu_bf16<<<(N_NODES * 32 + TB - 1) / TB, TB>>>(h1b, a1b, b1);
    gemm2_bf16_mma<<<(N_NODES + 127) / 128, 256>>>(a1b, W2, h2b, N_NODES);
    spmm_softmax_bf16<<<(N_NODES * 32 + TB - 1) / TB, TB>>>(h2b, out, b2);
}